// round 9
// baseline (speedup 1.0000x reference)
#include <cuda_runtime.h>
#include <cuda_bf16.h>
#include <math.h>
#include <stdint.h>

#define B_   128
#define T_   512
#define H_   512
#define G_   2048
#define DIN_ 8
#define HOR_ 64
#define MQ_  5
#define DFF_ 7
#define NBLK 128

typedef unsigned long long u64;

// ---------------- scratch (device globals; no allocations) ----------------
__device__ float g_gates0[2][T_][B_][G_];    // precomputed layer-0 input gates
__device__ float g_gates1[2][T_][B_][G_];    // precomputed layer-1 input gates
__device__ float g_c[2][2][B_][H_];          // final cell states [layer][dir]
__device__ float g_h0fin[2][B_][H_];         // layer-0 final h per dir (fp32)
__device__ float g_h1fin[2][B_][H_];         // layer-1 final h per dir (fp32)
__device__ float g_dec_h0[2][B_][H_];
__device__ float g_dec_c0[B_][H_];
__device__ float g_dec_h1[2][B_][H_];
__device__ float g_dec_c1[B_][H_];
__device__ float g_decx[B_][DIN_];           // decoder input vector [y_fb, fut]

// bf16 hi/lo split activations (enc-L0 h sequence; also gates1_mma's A input)
__device__ __nv_bfloat16 g_Ah[T_ * B_][1024];
__device__ __nv_bfloat16 g_Al[T_ * B_][1024];
// layer-1 h ping-pong, bf16 hi/lo
__device__ __nv_bfloat16 g_h1h[2][2][B_][H_];
__device__ __nv_bfloat16 g_h1l[2][2][B_][H_];
// gates1 weights, bf16 hi/lo
__device__ __nv_bfloat16 g_Bh[2][G_][1024];
__device__ __nv_bfloat16 g_Bl[2][G_][1024];

// ---------------- lightweight acq/rel grid barriers ----------------
// idx 0/1: encoder per-dir (64 blocks); idx 2: decoder (128 blocks).
__device__ unsigned g_bcnt[4];
__device__ unsigned g_bgen[4];

__device__ __forceinline__ unsigned bar_read_gen(int idx)
{
    unsigned g;
    asm volatile("ld.acquire.gpu.u32 %0, [%1];"
                 : "=r"(g) : "l"(&g_bgen[idx]) : "memory");
    return g;
}

__device__ __forceinline__ void bar_lite(int idx, unsigned nb, unsigned& mygen)
{
    __syncthreads();
    if (threadIdx.x == 0) {
        unsigned old;
        asm volatile("atom.release.gpu.add.u32 %0, [%1], 1;"
                     : "=r"(old) : "l"(&g_bcnt[idx]) : "memory");
        if (old == nb - 1u) {
            asm volatile("st.relaxed.gpu.u32 [%0], 0;"
                         :: "l"(&g_bcnt[idx]) : "memory");
            asm volatile("st.release.gpu.u32 [%0], %1;"
                         :: "l"(&g_bgen[idx]), "r"(mygen + 1u) : "memory");
        } else {
            unsigned g;
            do {
                asm volatile("ld.acquire.gpu.u32 %0, [%1];"
                             : "=r"(g) : "l"(&g_bgen[idx]) : "memory");
            } while (g == mygen);
        }
        ++mygen;
    }
    __syncthreads();
}

// ---------------- packed fp32x2 helpers (decoder SIMT path) ----------------
__device__ __forceinline__ void ffma2(u64& d, u64 a, u64 b) {
    asm("fma.rn.f32x2 %0, %1, %2, %0;" : "+l"(d) : "l"(a), "l"(b));
}
__device__ __forceinline__ u64 bcast2(float v) {
    u64 r;
    asm("mov.b64 %0, {%1, %1};" : "=l"(r) : "f"(v));
    return r;
}
__device__ __forceinline__ void unpack2(u64 v, float& lo, float& hi) {
    asm("mov.b64 {%0, %1}, %2;" : "=f"(lo), "=f"(hi) : "l"(v));
}

// ---------------- fast transcendentals ----------------
__device__ __forceinline__ float sigm_(float x) {
    return __fdividef(1.f, 1.f + __expf(-x));
}
__device__ __forceinline__ float tanh_(float x) {
    return __fdividef(2.f, 1.f + __expf(-2.f * x)) - 1.f;
}

// ---------------- mma.sync / ldmatrix helpers ----------------
__device__ __forceinline__ uint32_t smem_u32(const void* p) {
    uint32_t a;
    asm("{ .reg .u64 t; cvta.to.shared.u64 t, %1; cvt.u32.u64 %0, t; }"
        : "=r"(a) : "l"(p));
    return a;
}
__device__ __forceinline__ void ldsm4(uint32_t a, uint32_t& r0, uint32_t& r1,
                                      uint32_t& r2, uint32_t& r3) {
    asm volatile("ldmatrix.sync.aligned.m8n8.x4.shared.b16 {%0,%1,%2,%3}, [%4];"
                 : "=r"(r0), "=r"(r1), "=r"(r2), "=r"(r3) : "r"(a));
}
__device__ __forceinline__ void ldsm2(uint32_t a, uint32_t& r0, uint32_t& r1) {
    asm volatile("ldmatrix.sync.aligned.m8n8.x2.shared.b16 {%0,%1}, [%2];"
                 : "=r"(r0), "=r"(r1) : "r"(a));
}
__device__ __forceinline__ void mma_bf16(float* c, const uint32_t* a, const uint32_t* b) {
    asm volatile(
        "mma.sync.aligned.m16n8k16.row.col.f32.bf16.bf16.f32 "
        "{%0,%1,%2,%3}, {%4,%5,%6,%7}, {%8,%9}, {%0,%1,%2,%3};"
        : "+f"(c[0]), "+f"(c[1]), "+f"(c[2]), "+f"(c[3])
        : "r"(a[0]), "r"(a[1]), "r"(a[2]), "r"(a[3]), "r"(b[0]), "r"(b[1]));
}

// ---------------- layer-0 input gates: one-shot tiny-K GEMM ----------------
__global__ __launch_bounds__(256) void gates0_gemm(
    const float* __restrict__ X, const float* __restrict__ w_ih)
{
    __shared__ float xs_[B_][DIN_];
    const int t = blockIdx.x, dir = blockIdx.y;
    const int tid = threadIdx.x;
    for (int e = tid; e < B_ * DIN_; e += 256) {
        int b = e >> 3, k = e & 7;
        xs_[b][k] = __ldg(X + ((long)b * T_ + t) * DIN_ + k);
    }
    __syncthreads();
    const float* w = w_ih + (long)dir * G_ * DIN_;
    for (int g = tid; g < G_; g += 256) {
        float4 w0 = *reinterpret_cast<const float4*>(w + g * DIN_);
        float4 w1 = *reinterpret_cast<const float4*>(w + g * DIN_ + 4);
        float* op = &g_gates0[dir][t][0][0];
        for (int b = 0; b < B_; ++b) {
            const float* xb = xs_[b];
            float acc = xb[0] * w0.x + xb[1] * w0.y + xb[2] * w0.z + xb[3] * w0.w
                      + xb[4] * w1.x + xb[5] * w1.y + xb[6] * w1.z + xb[7] * w1.w;
            op[(long)b * G_ + g] = acc;
        }
    }
}

// -------- fp32 -> bf16 hi/lo conversion for gates1 weights ----------------
__global__ __launch_bounds__(256) void convB_kernel(const float* __restrict__ w_ih1)
{
    const long npairs = (long)2 * G_ * 512;
    __nv_bfloat16* bh = &g_Bh[0][0][0];
    __nv_bfloat16* bl = &g_Bl[0][0][0];
    for (long p = (long)blockIdx.x * 256 + threadIdx.x; p < npairs;
         p += (long)gridDim.x * 256) {
        float2 v = *reinterpret_cast<const float2*>(w_ih1 + p * 2);
        __nv_bfloat16 h0 = __float2bfloat16(v.x);
        __nv_bfloat16 l0 = __float2bfloat16(v.x - __bfloat162float(h0));
        __nv_bfloat16 h1 = __float2bfloat16(v.y);
        __nv_bfloat16 l1 = __float2bfloat16(v.y - __bfloat162float(h1));
        *reinterpret_cast<__nv_bfloat162*>(bh + p * 2) = __nv_bfloat162(h0, h1);
        *reinterpret_cast<__nv_bfloat162*>(bl + p * 2) = __nv_bfloat162(l0, l1);
    }
}

// =========== persistent mma-based encoder layer (layer = 0 or 1) ==========
// Block = 64 batch x 64 gate-cols (16 j x 4 gate types), K=512/step.
// W_hh hi/lo resident in SMEM all 512 steps; A (=h) streamed per step in
// 4 double-buffered k-chunks of 128. 8 warps = 4M x 2N (warp: 16 x 32).
#define ESM_W_H 0
#define ESM_W_L 66560
#define ESM_A   133120
#define ESM_AB  17408
#define ESM_C   202752
#define ENC_SMEM 220160

template<int LAYER>
__global__ __launch_bounds__(256, 1) void enc_mma_persist(
    const float* __restrict__ w_hh, const float* __restrict__ bias)
{
    extern __shared__ __align__(16) char esm[];
    __nv_bfloat16* Wh = reinterpret_cast<__nv_bfloat16*>(esm + ESM_W_H);
    __nv_bfloat16* Wl = reinterpret_cast<__nv_bfloat16*>(esm + ESM_W_L);
    float* Cb = reinterpret_cast<float*>(esm + ESM_C);

    const int tid = threadIdx.x, lane = tid & 31, wid = tid >> 5;
    const int warp_m = wid & 3, warp_n = wid >> 2;
    const int bid = blockIdx.x;
    const int dir = bid >> 6, rr = bid & 63;
    const int b0 = (rr >> 5) * 64, j0 = (rr & 31) * 16;

    unsigned mygen = 0;
    if (tid == 0) mygen = bar_read_gen(dir);

    // ---- one-time W_hh load + hi/lo split into resident smem ----
    const float* wsrc = w_hh + (long)dir * G_ * H_;
    for (int idx = tid; idx < 64 * 512; idx += 256) {
        int n = idx >> 9, k = idx & 511;
        int gc = (n >> 4) * 512 + j0 + (n & 15);
        float v = __ldg(wsrc + (long)gc * H_ + k);
        __nv_bfloat16 h = __float2bfloat16(v);
        Wh[n * 520 + k] = h;
        Wl[n * 520 + k] = __float2bfloat16(v - __bfloat162float(h));
    }

    // ---- per-thread pointwise cell mapping: (pb batch-local, jq j-quad) ----
    const int pb = tid >> 2, jq = tid & 3;
    const float* bp = bias + dir * G_ + j0 + jq * 4;
    float4 bI = __ldg((const float4*)(bp));
    float4 bF = __ldg((const float4*)(bp + 512));
    float4 bG = __ldg((const float4*)(bp + 1024));
    float4 bO = __ldg((const float4*)(bp + 1536));
    float cst[4] = {0.f, 0.f, 0.f, 0.f};

    // ---- ldmatrix lane offsets ----
    uint32_t WhB = smem_u32(Wh), WlB = smem_u32(Wl);
    const uint32_t aRow = (uint32_t)((warp_m * 16 + (lane & 15)) * 272
                                     + (lane >> 4) * 16);
    uint32_t bRow[4];
    #pragma unroll
    for (int ni = 0; ni < 4; ++ni)
        bRow[ni] = (uint32_t)((warp_n * 32 + ni * 8 + (lane & 7)) * 1040
                              + ((lane >> 3) & 1) * 16);

    const float* gatesrc = (LAYER == 0 ? &g_gates0[0][0][0][0]
                                       : &g_gates1[0][0][0][0])
                         + (long)dir * T_ * B_ * G_;
    __syncthreads();

    for (int s = 0; s < T_; ++s) {
        const int t = dir ? (T_ - 1 - s) : s;
        // prefetch gate-init (hidden behind the MMA work)
        const float* gp = gatesrc + ((long)t * B_ + b0 + pb) * G_ + j0 + jq * 4;
        float4 gI = __ldg((const float4*)(gp));
        float4 gF = __ldg((const float4*)(gp + 512));
        float4 gG = __ldg((const float4*)(gp + 1024));
        float4 gO = __ldg((const float4*)(gp + 1536));

        float acc[4][4] = {};
        if (s > 0) {
            const __nv_bfloat16 *pAh, *pAl;
            long apitch;
            if (LAYER == 0) {
                const int tp = dir ? t + 1 : t - 1;
                pAh = &g_Ah[tp * 128 + b0][dir * 512];
                pAl = &g_Al[tp * 128 + b0][dir * 512];
                apitch = 1024;
            } else {
                pAh = &g_h1h[s & 1][dir][b0][0];
                pAl = &g_h1l[s & 1][dir][b0][0];
                apitch = 512;
            }
            uint4 stg[8];
            auto stage = [&](int kc) {
                #pragma unroll
                for (int i = 0; i < 8; ++i) {
                    int idx = tid + i * 256;            // 0..2047
                    int term = idx >> 10, rem = idx & 1023;
                    int row = rem >> 4, c8 = rem & 15;
                    const __nv_bfloat16* src =
                        (term ? pAl : pAh) + (long)row * apitch + kc * 128 + c8 * 8;
                    stg[i] = __ldcg(reinterpret_cast<const uint4*>(src));
                }
            };
            auto commitA = [&](int buf) {
                #pragma unroll
                for (int i = 0; i < 8; ++i) {
                    int idx = tid + i * 256;
                    int term = idx >> 10, rem = idx & 1023;
                    int row = rem >> 4, c8 = rem & 15;
                    *reinterpret_cast<uint4*>(
                        esm + ESM_A + (buf * 2 + term) * ESM_AB + row * 272 + c8 * 16)
                        = stg[i];
                }
            };
            stage(0);
            commitA(0);
            __syncthreads();
            #pragma unroll 1
            for (int kc = 0; kc < 4; ++kc) {
                const int buf = kc & 1;
                if (kc < 3) stage(kc + 1);
                const uint32_t AhB = smem_u32(esm + ESM_A + (buf * 2) * ESM_AB);
                const uint32_t AlB = AhB + ESM_AB;
                #pragma unroll
                for (int ks = 0; ks < 8; ++ks) {
                    uint32_t ah[4], al[4], bh[4][2], bl[4][2];
                    ldsm4(AhB + aRow + ks * 32, ah[0], ah[1], ah[2], ah[3]);
                    ldsm4(AlB + aRow + ks * 32, al[0], al[1], al[2], al[3]);
                    #pragma unroll
                    for (int ni = 0; ni < 4; ++ni) {
                        ldsm2(WhB + bRow[ni] + kc * 256 + ks * 32, bh[ni][0], bh[ni][1]);
                        ldsm2(WlB + bRow[ni] + kc * 256 + ks * 32, bl[ni][0], bl[ni][1]);
                    }
                    #pragma unroll
                    for (int ni = 0; ni < 4; ++ni) {
                        mma_bf16(acc[ni], ah, bh[ni]);
                        mma_bf16(acc[ni], ah, bl[ni]);
                        mma_bf16(acc[ni], al, bh[ni]);
                    }
                }
                if (kc < 3) commitA(buf ^ 1);
                __syncthreads();
            }
        }
        // ---- epilogue: dump acc frags to Cbuf (64 x 64, pitch 68) ----
        {
            const int row = warp_m * 16 + (lane >> 2);
            #pragma unroll
            for (int ni = 0; ni < 4; ++ni) {
                const int col = warp_n * 32 + ni * 8 + (lane & 3) * 2;
                *reinterpret_cast<float2*>(&Cb[row * 68 + col]) =
                    make_float2(acc[ni][0], acc[ni][1]);
                *reinterpret_cast<float2*>(&Cb[(row + 8) * 68 + col]) =
                    make_float2(acc[ni][2], acc[ni][3]);
            }
        }
        __syncthreads();
        // ---- pointwise LSTM cell + h split/write ----
        {
            __align__(8) __nv_bfloat16 hh[4], hl[4];
            float hv[4];
            const float* gIv = (const float*)&gI;
            const float* gFv = (const float*)&gF;
            const float* gGv = (const float*)&gG;
            const float* gOv = (const float*)&gO;
            const float* bIv = (const float*)&bI;
            const float* bFv = (const float*)&bF;
            const float* bGv = (const float*)&bG;
            const float* bOv = (const float*)&bO;
            #pragma unroll
            for (int q = 0; q < 4; ++q) {
                const int jl = jq * 4 + q;
                float iv = Cb[pb * 68 + jl]      + gIv[q] + bIv[q];
                float fv = Cb[pb * 68 + 16 + jl] + gFv[q] + bFv[q];
                float gv = Cb[pb * 68 + 32 + jl] + gGv[q] + bGv[q];
                float ov = Cb[pb * 68 + 48 + jl] + gOv[q] + bOv[q];
                float i_ = sigm_(iv), f_ = sigm_(fv), g_ = tanh_(gv), o_ = sigm_(ov);
                float c = f_ * cst[q] + i_ * g_;
                cst[q] = c;
                float h = o_ * tanh_(c);
                hv[q] = h;
                hh[q] = __float2bfloat16(h);
                hl[q] = __float2bfloat16(h - __bfloat162float(hh[q]));
            }
            if (LAYER == 0) {
                *reinterpret_cast<uint2*>(&g_Ah[t * 128 + b0 + pb][dir * 512 + j0 + jq * 4])
                    = *reinterpret_cast<uint2*>(hh);
                *reinterpret_cast<uint2*>(&g_Al[t * 128 + b0 + pb][dir * 512 + j0 + jq * 4])
                    = *reinterpret_cast<uint2*>(hl);
                if (s == T_ - 1)
                    *reinterpret_cast<float4*>(&g_h0fin[dir][b0 + pb][j0 + jq * 4]) =
                        make_float4(hv[0], hv[1], hv[2], hv[3]);
            } else {
                *reinterpret_cast<uint2*>(&g_h1h[(s + 1) & 1][dir][b0 + pb][j0 + jq * 4])
                    = *reinterpret_cast<uint2*>(hh);
                *reinterpret_cast<uint2*>(&g_h1l[(s + 1) & 1][dir][b0 + pb][j0 + jq * 4])
                    = *reinterpret_cast<uint2*>(hl);
                if (s == T_ - 1)
                    *reinterpret_cast<float4*>(&g_h1fin[dir][b0 + pb][j0 + jq * 4]) =
                        make_float4(hv[0], hv[1], hv[2], hv[3]);
            }
        }
        bar_lite(dir, 64, mygen);
    }
    #pragma unroll
    for (int q = 0; q < 4; ++q)
        g_c[LAYER][dir][b0 + pb][j0 + jq * 4 + q] = cst[q];
}

// ======== gates1 via mma.sync bf16: D[64,128] = A[64,1024] @ W^T ==========
// M=64 tile, 2 CTAs/SM for tensor-pipe occupancy.
#define PITCH 40

__global__ __launch_bounds__(256, 2) void gates1_mma()
{
    __shared__ __align__(16) __nv_bfloat16 smA[2][64 * PITCH];
    __shared__ __align__(16) __nv_bfloat16 smB[2][128 * PITCH];
    const int tid = threadIdx.x;
    const int wid = tid >> 5, lane = tid & 31;
    const int n0 = blockIdx.x * 128, r0 = blockIdx.y * 64, dir = blockIdx.z;
    const int warp_m = wid & 1, warp_n = wid >> 1;

    const __nv_bfloat16* srcA[2] = { &g_Ah[r0][0], &g_Al[r0][0] };
    const __nv_bfloat16* srcB[2] = { &g_Bh[dir][n0][0], &g_Bl[dir][n0][0] };
    uint32_t sA[2] = { smem_u32(smA[0]), smem_u32(smA[1]) };
    uint32_t sB[2] = { smem_u32(smB[0]), smem_u32(smB[1]) };

    uint32_t aOff[2], bOff[4];
    #pragma unroll
    for (int mi = 0; mi < 2; ++mi)
        aOff[mi] = (uint32_t)((warp_m * 32 + mi * 16 + (lane & 15)) * (PITCH * 2)
                              + (lane >> 4) * 16);
    #pragma unroll
    for (int ni = 0; ni < 4; ++ni)
        bOff[ni] = (uint32_t)((warp_n * 32 + ni * 8 + (lane & 7)) * (PITCH * 2)
                              + ((lane >> 3) & 1) * 16);

    uint2 stg[12];
    auto stage = [&](int kbase) {
        #pragma unroll
        for (int i = 0; i < 12; ++i) {
            int idx = i * 256 + tid;
            if (idx < 1024) {
                int term = idx >> 9, rem = idx & 511, row = rem >> 3, c = rem & 7;
                stg[i] = *reinterpret_cast<const uint2*>(
                    srcA[term] + (long)row * 1024 + kbase + c * 4);
            } else {
                int j = idx - 1024;
                int term = j >> 10, rem = j & 1023, row = rem >> 3, c = rem & 7;
                stg[i] = *reinterpret_cast<const uint2*>(
                    srcB[term] + (long)row * 1024 + kbase + c * 4);
            }
        }
    };
    auto commit = [&]() {
        #pragma unroll
        for (int i = 0; i < 12; ++i) {
            int idx = i * 256 + tid;
            if (idx < 1024) {
                int term = idx >> 9, rem = idx & 511, row = rem >> 3, c = rem & 7;
                *reinterpret_cast<uint2*>(&smA[term][row * PITCH + c * 4]) = stg[i];
            } else {
                int j = idx - 1024;
                int term = j >> 10, rem = j & 1023, row = rem >> 3, c = rem & 7;
                *reinterpret_cast<uint2*>(&smB[term][row * PITCH + c * 4]) = stg[i];
            }
        }
    };

    float acc[2][4][4];
    #pragma unroll
    for (int mi = 0; mi < 2; ++mi)
        #pragma unroll
        for (int ni = 0; ni < 4; ++ni)
            #pragma unroll
            for (int q = 0; q < 4; ++q) acc[mi][ni][q] = 0.f;

    stage(0);
    commit();
    __syncthreads();
    #pragma unroll 1
    for (int kc = 0; kc < 32; ++kc) {
        if (kc < 31) stage((kc + 1) * 32);
        #pragma unroll
        for (int ks = 0; ks < 2; ++ks) {
            const uint32_t kb = ks * 32;
            uint32_t ah[2][4], al[2][4], bh[4][2], bl[4][2];
            #pragma unroll
            for (int mi = 0; mi < 2; ++mi) {
                ldsm4(sA[0] + aOff[mi] + kb, ah[mi][0], ah[mi][1], ah[mi][2], ah[mi][3]);
                ldsm4(sA[1] + aOff[mi] + kb, al[mi][0], al[mi][1], al[mi][2], al[mi][3]);
            }
            #pragma unroll
            for (int ni = 0; ni < 4; ++ni) {
                ldsm2(sB[0] + bOff[ni] + kb, bh[ni][0], bh[ni][1]);
                ldsm2(sB[1] + bOff[ni] + kb, bl[ni][0], bl[ni][1]);
            }
            #pragma unroll
            for (int mi = 0; mi < 2; ++mi)
                #pragma unroll
                for (int ni = 0; ni < 4; ++ni) {
                    mma_bf16(acc[mi][ni], ah[mi], bh[ni]);
                    mma_bf16(acc[mi][ni], ah[mi], bl[ni]);
                    mma_bf16(acc[mi][ni], al[mi], bh[ni]);
                }
        }
        __syncthreads();
        if (kc < 31) { commit(); __syncthreads(); }
    }

    float* ob = &g_gates1[dir][0][0][0];
    const int group = lane >> 2, tig = lane & 3;
    #pragma unroll
    for (int mi = 0; mi < 2; ++mi) {
        const long row = r0 + warp_m * 32 + mi * 16 + group;
        #pragma unroll
        for (int ni = 0; ni < 4; ++ni) {
            const int col = n0 + warp_n * 32 + ni * 8 + tig * 2;
            *reinterpret_cast<float2*>(ob + row * G_ + col) =
                make_float2(acc[mi][ni][0], acc[mi][ni][1]);
            *reinterpret_cast<float2*>(ob + (row + 8) * G_ + col) =
                make_float2(acc[mi][ni][2], acc[mi][ni][3]);
        }
    }
}

// -------- SIMT segment accumulate (decoder only, BT=16) -------------------
template<int BT>
__device__ __forceinline__ void seg_accum(
    float (*a_s)[BT + 4], float (*w_s)[33],
    const float* __restrict__ xp, int xs, int use_ldcg,
    const float* __restrict__ wp, int ws, int K,
    int b0, int j0, u64 acc2[BT / 16][4])
{
    const int tid = threadIdx.x, tx = tid & 31, ty = tid >> 5;
    constexpr int P = BT / 16;
    for (int k0 = 0; k0 < K; k0 += 32) {
        __syncthreads();
        #pragma unroll
        for (int i = 0; i < (BT * 32) / 256; ++i) {
            int e = tid + i * 256;
            int r = e >> 5, kk = e & 31, kg = k0 + kk;
            float v = 0.f;
            if (kg < K) {
                const float* p = xp + (long)(b0 + r) * xs + kg;
                v = use_ldcg ? __ldcg(p) : __ldg(p);
            }
            a_s[kk][r] = v;
        }
        #pragma unroll
        for (int i = 0; i < 16; ++i) {
            int e = tid + i * 256;
            int c = e >> 5, kk = e & 31, kg = k0 + kk;
            float v = 0.f;
            if (kg < K) {
                int gc = j0 + (c >> 5) * 512 + (c & 31);
                v = __ldg(wp + (long)gc * ws + kg);
            }
            w_s[c][kk] = v;
        }
        __syncthreads();
        #pragma unroll
        for (int kk = 0; kk < 32; ++kk) {
            u64 av[P];
            #pragma unroll
            for (int p = 0; p < P; ++p)
                av[p] = *reinterpret_cast<const u64*>(&a_s[kk][ty * (2 * P) + 2 * p]);
            #pragma unroll
            for (int gi = 0; gi < 4; ++gi) {
                u64 wv2 = bcast2(w_s[gi * 32 + tx][kk]);
                #pragma unroll
                for (int p = 0; p < P; ++p)
                    ffma2(acc2[p][gi], av[p], wv2);
            }
        }
    }
}

// ---------------- bridge: elu(h/c_flat @ Wbᵀ + bb) -> decoder init ---------
__global__ __launch_bounds__(256) void bridge_kernel(
    const float* __restrict__ wb, const float* __restrict__ bb)
{
    __shared__ float in_s[32][33], w_s2[32][33];
    const int tid = threadIdx.x, tx = tid & 31, ty = tid >> 5;
    const int b0 = blockIdx.x * 32, m0 = blockIdx.y * 32, z = blockIdx.z;
    const float* srcs[4];
    if (z == 0) {
        srcs[0] = &g_h0fin[0][0][0]; srcs[1] = &g_h0fin[1][0][0];
        srcs[2] = &g_h1fin[0][0][0]; srcs[3] = &g_h1fin[1][0][0];
    } else {
        srcs[0] = &g_c[0][0][0][0]; srcs[1] = &g_c[0][1][0][0];
        srcs[2] = &g_c[1][0][0][0]; srcs[3] = &g_c[1][1][0][0];
    }
    float acc[4] = {0.f, 0.f, 0.f, 0.f};
    for (int k0 = 0; k0 < 2048; k0 += 32) {
        __syncthreads();
        const float* src = srcs[k0 >> 9];
        const int kl = k0 & 511;
        #pragma unroll
        for (int i = 0; i < 4; ++i) {
            int e = tid + i * 256;
            int r = e >> 5, kk = e & 31;
            in_s[r][kk] = src[(long)(b0 + r) * H_ + kl + kk];
            w_s2[r][kk] = wb[(long)(m0 + r) * 2048 + k0 + kk];
        }
        __syncthreads();
        #pragma unroll
        for (int kk = 0; kk < 32; ++kk) {
            float wv = w_s2[tx][kk];
            #pragma unroll
            for (int bi = 0; bi < 4; ++bi)
                acc[bi] = fmaf(in_s[ty * 4 + bi][kk], wv, acc[bi]);
        }
    }
    const int m = m0 + tx;
    #pragma unroll
    for (int bi = 0; bi < 4; ++bi) {
        int b = b0 + ty * 4 + bi;
        float v = acc[bi] + bb[m];
        v = (v > 0.f) ? v : expm1f(v);
        if (z == 0) {
            if (m < 512) g_dec_h0[0][b][m] = v; else g_dec_h1[0][b][m - 512] = v;
        } else {
            if (m < 512) g_dec_c0[b][m] = v;    else g_dec_c1[b][m - 512] = v;
        }
    }
}

// ---------------- decoder: persistent, 64 steps ----------------------------
__global__ __launch_bounds__(256, 1) void dec_persist(
    const float* __restrict__ X, const float* __restrict__ fut,
    const float* __restrict__ dwih0, const float* __restrict__ dwhh0,
    const float* __restrict__ db0,
    const float* __restrict__ dwih1, const float* __restrict__ dwhh1,
    const float* __restrict__ db1,
    const float* __restrict__ wo, const float* __restrict__ bo,
    float* __restrict__ out)
{
    __shared__ __align__(16) float a_s[32][20];
    __shared__ __align__(16) float w_s[128][33];
    __shared__ float red[8][MQ_];
    const int bid = blockIdx.x, tid = threadIdx.x;
    const int tx = tid & 31, ty = tid >> 5;
    const int b0 = (bid >> 4) * 16, j0 = (bid & 15) * 32;
    const int j = j0 + tx;

    unsigned mygen = 0;
    if (tid == 0) mygen = bar_read_gen(2);

    if (tid < DIN_)
        g_decx[bid][tid] = (tid == 0)
            ? __ldg(X + (long)bid * T_ * DIN_ + (T_ - 1) * DIN_)
            : __ldg(fut + (long)bid * HOR_ * DFF_ + (tid - 1));

    const float b0I = __ldg(db0 + j),        b0F = __ldg(db0 + 512 + j),
                b0G = __ldg(db0 + 1024 + j), b0O = __ldg(db0 + 1536 + j);
    const float b1I = __ldg(db1 + j),        b1F = __ldg(db1 + 512 + j),
                b1G = __ldg(db1 + 1024 + j), b1O = __ldg(db1 + 1536 + j);
    float c0[2], c1[2];
    #pragma unroll
    for (int bi = 0; bi < 2; ++bi) {
        c0[bi] = g_dec_c0[b0 + ty * 2 + bi][j];
        c1[bi] = g_dec_c1[b0 + ty * 2 + bi][j];
    }
    bar_lite(2, NBLK, mygen);

    for (int s = 0; s < HOR_; ++s) {
        {
            u64 acc2[1][4] = {};
            seg_accum<16>(a_s, w_s, &g_decx[0][0], DIN_, 1, dwih0, DIN_, DIN_, b0, j0, acc2);
            seg_accum<16>(a_s, w_s, &g_dec_h0[s & 1][0][0], H_, 1, dwhh0, H_, H_, b0, j0, acc2);
            float acc[2][4];
            #pragma unroll
            for (int gi = 0; gi < 4; ++gi)
                unpack2(acc2[0][gi], acc[0][gi], acc[1][gi]);
            #pragma unroll
            for (int bi = 0; bi < 2; ++bi) {
                float i_ = sigm_(acc[bi][0] + b0I);
                float f_ = sigm_(acc[bi][1] + b0F);
                float g_ = tanh_(acc[bi][2] + b0G);
                float o_ = sigm_(acc[bi][3] + b0O);
                float c  = f_ * c0[bi] + i_ * g_;
                c0[bi] = c;
                g_dec_h0[(s + 1) & 1][b0 + ty * 2 + bi][j] = o_ * tanh_(c);
            }
        }
        bar_lite(2, NBLK, mygen);
        {
            u64 acc2[1][4] = {};
            seg_accum<16>(a_s, w_s, &g_dec_h0[(s + 1) & 1][0][0], H_, 1, dwih1, H_, H_, b0, j0, acc2);
            seg_accum<16>(a_s, w_s, &g_dec_h1[s & 1][0][0],       H_, 1, dwhh1, H_, H_, b0, j0, acc2);
            float acc[2][4];
            #pragma unroll
            for (int gi = 0; gi < 4; ++gi)
                unpack2(acc2[0][gi], acc[0][gi], acc[1][gi]);
            #pragma unroll
            for (int bi = 0; bi < 2; ++bi) {
                float i_ = sigm_(acc[bi][0] + b1I);
                float f_ = sigm_(acc[bi][1] + b1F);
                float g_ = tanh_(acc[bi][2] + b1G);
                float o_ = sigm_(acc[bi][3] + b1O);
                float c  = f_ * c1[bi] + i_ * g_;
                c1[bi] = c;
                g_dec_h1[(s + 1) & 1][b0 + ty * 2 + bi][j] = o_ * tanh_(c);
            }
        }
        bar_lite(2, NBLK, mygen);
        {
            const float* h1 = &g_dec_h1[(s + 1) & 1][bid][0];
            float part[MQ_] = {0.f, 0.f, 0.f, 0.f, 0.f};
            for (int k = tid; k < H_; k += 256) {
                float hv = __ldcg(h1 + k);
                #pragma unroll
                for (int q = 0; q < MQ_; ++q)
                    part[q] = fmaf(hv, __ldg(wo + q * H_ + k), part[q]);
            }
            #pragma unroll
            for (int o = 16; o; o >>= 1)
                #pragma unroll
                for (int q = 0; q < MQ_; ++q)
                    part[q] += __shfl_down_sync(0xffffffffu, part[q], o);
            if ((tid & 31) == 0)
                #pragma unroll
                for (int q = 0; q < MQ_; ++q) red[tid >> 5][q] = part[q];
            __syncthreads();
            if (tid < MQ_) {
                float v = __ldg(bo + tid);
                #pragma unroll
                for (int w2 = 0; w2 < 8; ++w2) v += red[w2][tid];
                out[(long)bid * HOR_ * MQ_ + s * MQ_ + tid] = v;
                if (tid == 0) g_decx[bid][0] = v;
            }
            if (s + 1 < HOR_ && tid >= 32 && tid < 32 + DFF_)
                g_decx[bid][tid - 31] =
                    __ldg(fut + (long)bid * HOR_ * DFF_ + (s + 1) * DFF_ + (tid - 32));
        }
        bar_lite(2, NBLK, mygen);
    }
}

// ---------------- launcher (7 graph nodes) ----------------
extern "C" void kernel_launch(void* const* d_in, const int* in_sizes, int n_in,
                              void* d_out, int out_size)
{
    int off = (n_in >= 4 && in_sizes[3] == 1) ? 0 : -1;
    const float* X     = (const float*)d_in[0];
    const float* fut   = (const float*)d_in[1];
    const float* ewih0 = (const float*)d_in[4 + off];
    const float* ewhh0 = (const float*)d_in[5 + off];
    const float* eb0   = (const float*)d_in[6 + off];
    const float* ewih1 = (const float*)d_in[7 + off];
    const float* ewhh1 = (const float*)d_in[8 + off];
    const float* eb1   = (const float*)d_in[9 + off];
    const float* dwih0 = (const float*)d_in[10 + off];
    const float* dwhh0 = (const float*)d_in[11 + off];
    const float* db0   = (const float*)d_in[12 + off];
    const float* dwih1 = (const float*)d_in[13 + off];
    const float* dwhh1 = (const float*)d_in[14 + off];
    const float* db1   = (const float*)d_in[15 + off];
    const float* wb    = (const float*)d_in[16 + off];
    const float* bb    = (const float*)d_in[17 + off];
    const float* wo    = (const float*)d_in[18 + off];
    const float* bo    = (const float*)d_in[19 + off];
    float* out = (float*)d_out;

    cudaFuncSetAttribute(enc_mma_persist<0>,
                         cudaFuncAttributeMaxDynamicSharedMemorySize, ENC_SMEM);
    cudaFuncSetAttribute(enc_mma_persist<1>,
                         cudaFuncAttributeMaxDynamicSharedMemorySize, ENC_SMEM);

    gates0_gemm<<<dim3(T_, 2), 256>>>(X, ewih0);
    convB_kernel<<<2048, 256>>>(ewih1);
    enc_mma_persist<0><<<NBLK, 256, ENC_SMEM>>>(ewhh0, eb0);
    gates1_mma<<<dim3(16, 1024, 2), 256>>>();
    enc_mma_persist<1><<<NBLK, 256, ENC_SMEM>>>(ewhh1, eb1);
    bridge_kernel<<<dim3(4, 32, 2), 256>>>(wb, bb);
    dec_persist<<<NBLK, 256>>>(X, fut, dwih0, dwhh0, db0,
                               dwih1, dwhh1, db1, wo, bo, out);
}

// round 10
// speedup vs baseline: 1.4786x; 1.4786x over previous
#include <cuda_runtime.h>
#include <cuda_bf16.h>
#include <math.h>
#include <stdint.h>

#define B_   128
#define T_   512
#define H_   512
#define G_   2048
#define DIN_ 8
#define HOR_ 64
#define MQ_  5
#define DFF_ 7
#define NBLK 128

typedef unsigned long long u64;

// ---------------- scratch (device globals; no allocations) ----------------
__device__ float g_gates1[2][T_][B_][G_];    // precomputed layer-1 input gates
__device__ float g_c[2][2][B_][H_];          // final cell states [layer][dir]
__device__ float g_h0fin[2][B_][H_];         // layer-0 final h per dir (fp32)
__device__ float g_h1fin[2][B_][H_];         // layer-1 final h per dir (fp32)
__device__ float g_dec_h0[2][B_][H_];
__device__ float g_dec_c0[B_][H_];
__device__ float g_dec_h1[2][B_][H_];
__device__ float g_dec_c1[B_][H_];
__device__ float g_decx[B_][DIN_];           // decoder input vector [y_fb, fut]

// bf16 hi/lo split activations (enc-L0 h sequence; also gates1_mma's A input)
__device__ __nv_bfloat16 g_Ah[T_ * B_][1024];
__device__ __nv_bfloat16 g_Al[T_ * B_][1024];
// layer-1 h ping-pong, bf16 hi/lo
__device__ __nv_bfloat16 g_h1h[2][2][B_][H_];
__device__ __nv_bfloat16 g_h1l[2][2][B_][H_];
// gates1 weights, bf16 hi/lo
__device__ __nv_bfloat16 g_Bh[2][G_][1024];
__device__ __nv_bfloat16 g_Bl[2][G_][1024];

// ---------------- grid barrier (R8 mechanism: weak volatile poll) ----------
// idx 0/1: encoder per-dir (64 blocks each); idx 2: decoder (128 blocks).
// Counters padded 128B apart so the two dirs don't share a cache line.
__device__ unsigned g_bcnt[3 * 32];
__device__ unsigned g_bgen[3 * 32];

__device__ __forceinline__ void grid_barrier(int idx, unsigned nb)
{
    __syncthreads();
    if (threadIdx.x == 0) {
        volatile unsigned* genp = &g_bgen[idx * 32];
        unsigned gen = *genp;
        __threadfence();                       // release prior writes
        if (atomicAdd(&g_bcnt[idx * 32], 1u) == nb - 1u) {
            g_bcnt[idx * 32] = 0u;
            __threadfence();
            *genp = gen + 1u;
        } else {
            while (*genp == gen) { }           // WEAK poll (volatile LDG)
        }
        __threadfence();                       // acquire
    }
    __syncthreads();
}

// ---------------- packed fp32x2 helpers (decoder SIMT path) ----------------
__device__ __forceinline__ void ffma2(u64& d, u64 a, u64 b) {
    asm("fma.rn.f32x2 %0, %1, %2, %0;" : "+l"(d) : "l"(a), "l"(b));
}
__device__ __forceinline__ u64 bcast2(float v) {
    u64 r;
    asm("mov.b64 %0, {%1, %1};" : "=l"(r) : "f"(v));
    return r;
}
__device__ __forceinline__ void unpack2(u64 v, float& lo, float& hi) {
    asm("mov.b64 {%0, %1}, %2;" : "=f"(lo), "=f"(hi) : "l"(v));
}

// ---------------- fast transcendentals ----------------
__device__ __forceinline__ float sigm_(float x) {
    return __fdividef(1.f, 1.f + __expf(-x));
}
__device__ __forceinline__ float tanh_(float x) {
    return __fdividef(2.f, 1.f + __expf(-2.f * x)) - 1.f;
}

// ---------------- mma.sync / ldmatrix helpers ----------------
__device__ __forceinline__ uint32_t smem_u32(const void* p) {
    uint32_t a;
    asm("{ .reg .u64 t; cvta.to.shared.u64 t, %1; cvt.u32.u64 %0, t; }"
        : "=r"(a) : "l"(p));
    return a;
}
__device__ __forceinline__ void ldsm4(uint32_t a, uint32_t& r0, uint32_t& r1,
                                      uint32_t& r2, uint32_t& r3) {
    asm volatile("ldmatrix.sync.aligned.m8n8.x4.shared.b16 {%0,%1,%2,%3}, [%4];"
                 : "=r"(r0), "=r"(r1), "=r"(r2), "=r"(r3) : "r"(a));
}
__device__ __forceinline__ void ldsm2(uint32_t a, uint32_t& r0, uint32_t& r1) {
    asm volatile("ldmatrix.sync.aligned.m8n8.x2.shared.b16 {%0,%1}, [%2];"
                 : "=r"(r0), "=r"(r1) : "r"(a));
}
__device__ __forceinline__ void mma_bf16(float* c, const uint32_t* a, const uint32_t* b) {
    asm volatile(
        "mma.sync.aligned.m16n8k16.row.col.f32.bf16.bf16.f32 "
        "{%0,%1,%2,%3}, {%4,%5,%6,%7}, {%8,%9}, {%0,%1,%2,%3};"
        : "+f"(c[0]), "+f"(c[1]), "+f"(c[2]), "+f"(c[3])
        : "r"(a[0]), "r"(a[1]), "r"(a[2]), "r"(a[3]), "r"(b[0]), "r"(b[1]));
}

// -------- fp32 -> bf16 hi/lo conversion for gates1 weights ----------------
__global__ __launch_bounds__(256) void convB_kernel(const float* __restrict__ w_ih1)
{
    const long npairs = (long)2 * G_ * 512;
    __nv_bfloat16* bh = &g_Bh[0][0][0];
    __nv_bfloat16* bl = &g_Bl[0][0][0];
    for (long p = (long)blockIdx.x * 256 + threadIdx.x; p < npairs;
         p += (long)gridDim.x * 256) {
        float2 v = *reinterpret_cast<const float2*>(w_ih1 + p * 2);
        __nv_bfloat16 h0 = __float2bfloat16(v.x);
        __nv_bfloat16 l0 = __float2bfloat16(v.x - __bfloat162float(h0));
        __nv_bfloat16 h1 = __float2bfloat16(v.y);
        __nv_bfloat16 l1 = __float2bfloat16(v.y - __bfloat162float(h1));
        *reinterpret_cast<__nv_bfloat162*>(bh + p * 2) = __nv_bfloat162(h0, h1);
        *reinterpret_cast<__nv_bfloat162*>(bl + p * 2) = __nv_bfloat162(l0, l1);
    }
}

// =========== persistent mma-based encoder layer (layer = 0 or 1) ==========
// Block = 64 batch x 64 gate-cols (16 j x 4 gate types), K=512/step.
// W_hh hi/lo resident in SMEM all 512 steps; A (=h) streamed per step in
// 8 double-buffered k-chunks of 64. 8 warps = 4M x 2N (warp: 16 x 32).
// LAYER 0 computes its K=8 input projection in-step from X (no gates0 pass).
#define ESM_W_H 0
#define ESM_W_L 66560
#define ESM_A   133120
#define ESM_AB  9216
#define ESM_C   169984
#define ESM_WIH 187392
#define ESM_X   189440
#define ENC_SMEM 191488

template<int LAYER>
__global__ __launch_bounds__(256, 1) void enc_mma_persist(
    const float* __restrict__ w_hh, const float* __restrict__ w_ih,
    const float* __restrict__ X, const float* __restrict__ bias)
{
    extern __shared__ __align__(16) char esm[];
    __nv_bfloat16* Wh = reinterpret_cast<__nv_bfloat16*>(esm + ESM_W_H);
    __nv_bfloat16* Wl = reinterpret_cast<__nv_bfloat16*>(esm + ESM_W_L);
    float* Cb  = reinterpret_cast<float*>(esm + ESM_C);
    float* Wih = reinterpret_cast<float*>(esm + ESM_WIH);
    float* xsm = reinterpret_cast<float*>(esm + ESM_X);

    const int tid = threadIdx.x, lane = tid & 31, wid = tid >> 5;
    const int warp_m = wid & 3, warp_n = wid >> 2;
    const int bid = blockIdx.x;
    const int dir = bid >> 6, rr = bid & 63;
    const int b0 = (rr >> 5) * 64, j0 = (rr & 31) * 16;

    // ---- one-time W_hh load + hi/lo split into resident smem ----
    const float* wsrc = w_hh + (long)dir * G_ * H_;
    for (int idx = tid; idx < 64 * 512; idx += 256) {
        int n = idx >> 9, k = idx & 511;
        int gc = (n >> 4) * 512 + j0 + (n & 15);
        float v = __ldg(wsrc + (long)gc * H_ + k);
        __nv_bfloat16 h = __float2bfloat16(v);
        Wh[n * 520 + k] = h;
        Wl[n * 520 + k] = __float2bfloat16(v - __bfloat162float(h));
    }
    // ---- LAYER 0: one-time W_ih tile (64 gate-cols x 8) ----
    if (LAYER == 0) {
        const float* wi = w_ih + (long)dir * G_ * DIN_;
        for (int idx = tid; idx < 64 * DIN_; idx += 256) {
            int n = idx >> 3, k = idx & 7;
            int gc = (n >> 4) * 512 + j0 + (n & 15);
            Wih[n * 8 + k] = __ldg(wi + (long)gc * DIN_ + k);
        }
    }

    // ---- per-thread pointwise cell mapping: (pb batch-local, jq j-quad) ----
    const int pb = tid >> 2, jq = tid & 3;
    const float* bp = bias + dir * G_ + j0 + jq * 4;
    float bIv[4], bFv[4], bGv[4], bOv[4];
    {
        float4 t0 = __ldg((const float4*)(bp));
        float4 t1 = __ldg((const float4*)(bp + 512));
        float4 t2 = __ldg((const float4*)(bp + 1024));
        float4 t3 = __ldg((const float4*)(bp + 1536));
        bIv[0]=t0.x; bIv[1]=t0.y; bIv[2]=t0.z; bIv[3]=t0.w;
        bFv[0]=t1.x; bFv[1]=t1.y; bFv[2]=t1.z; bFv[3]=t1.w;
        bGv[0]=t2.x; bGv[1]=t2.y; bGv[2]=t2.z; bGv[3]=t2.w;
        bOv[0]=t3.x; bOv[1]=t3.y; bOv[2]=t3.z; bOv[3]=t3.w;
    }
    float cst[4] = {0.f, 0.f, 0.f, 0.f};

    // ---- ldmatrix lane offsets ----
    uint32_t WhB = smem_u32(Wh), WlB = smem_u32(Wl);
    const uint32_t aRow = (uint32_t)((warp_m * 16 + (lane & 15)) * 144
                                     + (lane >> 4) * 16);
    uint32_t bRow[4];
    #pragma unroll
    for (int ni = 0; ni < 4; ++ni)
        bRow[ni] = (uint32_t)((warp_n * 32 + ni * 8 + (lane & 7)) * 1040
                              + ((lane >> 3) & 1) * 16);

    __syncthreads();

    for (int s = 0; s < T_; ++s) {
        const int t = dir ? (T_ - 1 - s) : s;

        float gIv[4], gFv[4], gGv[4], gOv[4];
        if (LAYER == 0) {
            // store x[t] tile (64 batches x 8) then compute K=8 input gates
            #pragma unroll
            for (int i = 0; i < 2; ++i) {
                int e = tid + i * 256;
                int row = e >> 3, k = e & 7;
                xsm[row * 8 + k] = __ldg(X + ((long)(b0 + row) * T_ + t) * DIN_ + k);
            }
            __syncthreads();
            float4 x0 = *reinterpret_cast<const float4*>(&xsm[pb * 8]);
            float4 x1 = *reinterpret_cast<const float4*>(&xsm[pb * 8 + 4]);
            float gg[16];
            #pragma unroll
            for (int gate = 0; gate < 4; ++gate)
                #pragma unroll
                for (int q = 0; q < 4; ++q) {
                    const float* wr = &Wih[((gate << 4) + (jq << 2) + q) * 8];
                    float4 w0 = *reinterpret_cast<const float4*>(wr);
                    float4 w1 = *reinterpret_cast<const float4*>(wr + 4);
                    gg[gate * 4 + q] =
                        x0.x * w0.x + x0.y * w0.y + x0.z * w0.z + x0.w * w0.w +
                        x1.x * w1.x + x1.y * w1.y + x1.z * w1.z + x1.w * w1.w;
                }
            #pragma unroll
            for (int q = 0; q < 4; ++q) {
                gIv[q] = gg[q]; gFv[q] = gg[4 + q];
                gGv[q] = gg[8 + q]; gOv[q] = gg[12 + q];
            }
        } else {
            const float* gp = &g_gates1[0][0][0][0]
                + (long)dir * T_ * B_ * G_
                + ((long)t * B_ + b0 + pb) * G_ + j0 + jq * 4;
            float4 t0 = __ldg((const float4*)(gp));
            float4 t1 = __ldg((const float4*)(gp + 512));
            float4 t2 = __ldg((const float4*)(gp + 1024));
            float4 t3 = __ldg((const float4*)(gp + 1536));
            gIv[0]=t0.x; gIv[1]=t0.y; gIv[2]=t0.z; gIv[3]=t0.w;
            gFv[0]=t1.x; gFv[1]=t1.y; gFv[2]=t1.z; gFv[3]=t1.w;
            gGv[0]=t2.x; gGv[1]=t2.y; gGv[2]=t2.z; gGv[3]=t2.w;
            gOv[0]=t3.x; gOv[1]=t3.y; gOv[2]=t3.z; gOv[3]=t3.w;
        }

        float acc[4][4] = {};
        if (s > 0) {
            const __nv_bfloat16 *pAh, *pAl;
            long apitch;
            if (LAYER == 0) {
                const int tp = dir ? t + 1 : t - 1;
                pAh = &g_Ah[tp * 128 + b0][dir * 512];
                pAl = &g_Al[tp * 128 + b0][dir * 512];
                apitch = 1024;
            } else {
                pAh = &g_h1h[s & 1][dir][b0][0];
                pAl = &g_h1l[s & 1][dir][b0][0];
                apitch = 512;
            }
            uint4 stg[4];
            auto stage = [&](int kc) {
                #pragma unroll
                for (int i = 0; i < 4; ++i) {
                    int idx = tid + i * 256;
                    int term = idx >> 9, rem = idx & 511;
                    int row = rem >> 3, c8 = rem & 7;
                    const __nv_bfloat16* src =
                        (term ? pAl : pAh) + (long)row * apitch + kc * 64 + c8 * 8;
                    stg[i] = __ldcg(reinterpret_cast<const uint4*>(src));
                }
            };
            auto commitA = [&](int buf) {
                #pragma unroll
                for (int i = 0; i < 4; ++i) {
                    int idx = tid + i * 256;
                    int term = idx >> 9, rem = idx & 511;
                    int row = rem >> 3, c8 = rem & 7;
                    *reinterpret_cast<uint4*>(
                        esm + ESM_A + (buf * 2 + term) * ESM_AB + row * 144 + c8 * 16)
                        = stg[i];
                }
            };
            stage(0);
            commitA(0);
            __syncthreads();
            #pragma unroll 1
            for (int kc = 0; kc < 8; ++kc) {
                const int buf = kc & 1;
                if (kc < 7) stage(kc + 1);
                const uint32_t AhB = smem_u32(esm + ESM_A + (buf * 2) * ESM_AB);
                const uint32_t AlB = AhB + ESM_AB;
                #pragma unroll
                for (int ks = 0; ks < 4; ++ks) {
                    uint32_t ah[4], al[4], bh[4][2], bl[4][2];
                    ldsm4(AhB + aRow + ks * 32, ah[0], ah[1], ah[2], ah[3]);
                    ldsm4(AlB + aRow + ks * 32, al[0], al[1], al[2], al[3]);
                    #pragma unroll
                    for (int ni = 0; ni < 4; ++ni) {
                        ldsm2(WhB + bRow[ni] + kc * 128 + ks * 32, bh[ni][0], bh[ni][1]);
                        ldsm2(WlB + bRow[ni] + kc * 128 + ks * 32, bl[ni][0], bl[ni][1]);
                    }
                    #pragma unroll
                    for (int ni = 0; ni < 4; ++ni) {
                        mma_bf16(acc[ni], ah, bh[ni]);
                        mma_bf16(acc[ni], ah, bl[ni]);
                        mma_bf16(acc[ni], al, bh[ni]);
                    }
                }
                if (kc < 7) commitA(buf ^ 1);
                __syncthreads();
            }
        } else if (LAYER == 0) {
            __syncthreads();   // cover xsm reuse ordering on the no-MMA step
        }
        // ---- epilogue: dump acc frags to Cbuf (64 x 64, pitch 68) ----
        {
            const int row = warp_m * 16 + (lane >> 2);
            #pragma unroll
            for (int ni = 0; ni < 4; ++ni) {
                const int col = warp_n * 32 + ni * 8 + (lane & 3) * 2;
                *reinterpret_cast<float2*>(&Cb[row * 68 + col]) =
                    make_float2(acc[ni][0], acc[ni][1]);
                *reinterpret_cast<float2*>(&Cb[(row + 8) * 68 + col]) =
                    make_float2(acc[ni][2], acc[ni][3]);
            }
        }
        __syncthreads();
        // ---- pointwise LSTM cell + h split/write ----
        {
            __align__(8) __nv_bfloat16 hh[4], hl[4];
            float hv[4];
            #pragma unroll
            for (int q = 0; q < 4; ++q) {
                const int jl = jq * 4 + q;
                float iv = Cb[pb * 68 + jl]      + gIv[q] + bIv[q];
                float fv = Cb[pb * 68 + 16 + jl] + gFv[q] + bFv[q];
                float gv = Cb[pb * 68 + 32 + jl] + gGv[q] + bGv[q];
                float ov = Cb[pb * 68 + 48 + jl] + gOv[q] + bOv[q];
                float i_ = sigm_(iv), f_ = sigm_(fv), g_ = tanh_(gv), o_ = sigm_(ov);
                float c = f_ * cst[q] + i_ * g_;
                cst[q] = c;
                float h = o_ * tanh_(c);
                hv[q] = h;
                hh[q] = __float2bfloat16(h);
                hl[q] = __float2bfloat16(h - __bfloat162float(hh[q]));
            }
            if (LAYER == 0) {
                *reinterpret_cast<uint2*>(&g_Ah[t * 128 + b0 + pb][dir * 512 + j0 + jq * 4])
                    = *reinterpret_cast<uint2*>(hh);
                *reinterpret_cast<uint2*>(&g_Al[t * 128 + b0 + pb][dir * 512 + j0 + jq * 4])
                    = *reinterpret_cast<uint2*>(hl);
                if (s == T_ - 1)
                    *reinterpret_cast<float4*>(&g_h0fin[dir][b0 + pb][j0 + jq * 4]) =
                        make_float4(hv[0], hv[1], hv[2], hv[3]);
            } else {
                *reinterpret_cast<uint2*>(&g_h1h[(s + 1) & 1][dir][b0 + pb][j0 + jq * 4])
                    = *reinterpret_cast<uint2*>(hh);
                *reinterpret_cast<uint2*>(&g_h1l[(s + 1) & 1][dir][b0 + pb][j0 + jq * 4])
                    = *reinterpret_cast<uint2*>(hl);
                if (s == T_ - 1)
                    *reinterpret_cast<float4*>(&g_h1fin[dir][b0 + pb][j0 + jq * 4]) =
                        make_float4(hv[0], hv[1], hv[2], hv[3]);
            }
        }
        grid_barrier(dir, 64);
    }
    #pragma unroll
    for (int q = 0; q < 4; ++q)
        g_c[LAYER][dir][b0 + pb][j0 + jq * 4 + q] = cst[q];
}

// ======== gates1 via mma.sync bf16: D[128,128] = A[128,1024] @ W^T =========
#define PITCH 40

__global__ __launch_bounds__(256) void gates1_mma()
{
    __shared__ __align__(16) __nv_bfloat16 smem4[4][128 * PITCH];
    const int tid = threadIdx.x;
    const int wid = tid >> 5, lane = tid & 31;
    const int n0 = blockIdx.x * 128, r0 = blockIdx.y * 128, dir = blockIdx.z;
    const int warp_m = wid & 1, warp_n = wid >> 1;

    const __nv_bfloat16* srcs[4] = {
        &g_Ah[r0][0], &g_Al[r0][0], &g_Bh[dir][n0][0], &g_Bl[dir][n0][0] };
    uint32_t sb[4] = { smem_u32(smem4[0]), smem_u32(smem4[1]),
                       smem_u32(smem4[2]), smem_u32(smem4[3]) };

    uint32_t aOff[4], bOff[4];
    #pragma unroll
    for (int mi = 0; mi < 4; ++mi)
        aOff[mi] = (uint32_t)((warp_m * 64 + mi * 16 + (lane & 15)) * (PITCH * 2)
                              + (lane >> 4) * 16);
    #pragma unroll
    for (int ni = 0; ni < 4; ++ni)
        bOff[ni] = (uint32_t)((warp_n * 32 + ni * 8 + (lane & 7)) * (PITCH * 2)
                              + ((lane >> 3) & 1) * 16);

    uint2 stg[16];
    auto stage = [&](int kbase) {
        #pragma unroll
        for (int i = 0; i < 16; ++i) {
            int idx = i * 256 + tid;
            int tI = idx >> 10, row = (idx >> 3) & 127, c = idx & 7;
            stg[i] = *reinterpret_cast<const uint2*>(
                srcs[tI] + (long)row * 1024 + kbase + c * 4);
        }
    };
    auto commit = [&]() {
        #pragma unroll
        for (int i = 0; i < 16; ++i) {
            int idx = i * 256 + tid;
            int tI = idx >> 10, row = (idx >> 3) & 127, c = idx & 7;
            *reinterpret_cast<uint2*>(&smem4[tI][row * PITCH + c * 4]) = stg[i];
        }
    };

    float acc[4][4][4];
    #pragma unroll
    for (int mi = 0; mi < 4; ++mi)
        #pragma unroll
        for (int ni = 0; ni < 4; ++ni)
            #pragma unroll
            for (int q = 0; q < 4; ++q) acc[mi][ni][q] = 0.f;

    stage(0);
    commit();
    __syncthreads();
    #pragma unroll 1
    for (int kc = 0; kc < 32; ++kc) {
        if (kc < 31) stage((kc + 1) * 32);
        #pragma unroll
        for (int ks = 0; ks < 2; ++ks) {
            const uint32_t kb = ks * 32;
            uint32_t ah[4][4], al[4][4], bh[4][2], bl[4][2];
            #pragma unroll
            for (int mi = 0; mi < 4; ++mi) {
                ldsm4(sb[0] + aOff[mi] + kb, ah[mi][0], ah[mi][1], ah[mi][2], ah[mi][3]);
                ldsm4(sb[1] + aOff[mi] + kb, al[mi][0], al[mi][1], al[mi][2], al[mi][3]);
            }
            #pragma unroll
            for (int ni = 0; ni < 4; ++ni) {
                ldsm2(sb[2] + bOff[ni] + kb, bh[ni][0], bh[ni][1]);
                ldsm2(sb[3] + bOff[ni] + kb, bl[ni][0], bl[ni][1]);
            }
            #pragma unroll
            for (int mi = 0; mi < 4; ++mi)
                #pragma unroll
                for (int ni = 0; ni < 4; ++ni) {
                    mma_bf16(acc[mi][ni], ah[mi], bh[ni]);
                    mma_bf16(acc[mi][ni], ah[mi], bl[ni]);
                    mma_bf16(acc[mi][ni], al[mi], bh[ni]);
                }
        }
        __syncthreads();
        if (kc < 31) { commit(); __syncthreads(); }
    }

    float* ob = &g_gates1[dir][0][0][0];
    const int group = lane >> 2, tig = lane & 3;
    #pragma unroll
    for (int mi = 0; mi < 4; ++mi) {
        const long row = r0 + warp_m * 64 + mi * 16 + group;
        #pragma unroll
        for (int ni = 0; ni < 4; ++ni) {
            const int col = n0 + warp_n * 32 + ni * 8 + tig * 2;
            *reinterpret_cast<float2*>(ob + row * G_ + col) =
                make_float2(acc[mi][ni][0], acc[mi][ni][1]);
            *reinterpret_cast<float2*>(ob + (row + 8) * G_ + col) =
                make_float2(acc[mi][ni][2], acc[mi][ni][3]);
        }
    }
}

// -------- SIMT segment accumulate (decoder only, BT=16) -------------------
template<int BT>
__device__ __forceinline__ void seg_accum(
    float (*a_s)[BT + 4], float (*w_s)[33],
    const float* __restrict__ xp, int xs, int use_ldcg,
    const float* __restrict__ wp, int ws, int K,
    int b0, int j0, u64 acc2[BT / 16][4])
{
    const int tid = threadIdx.x, tx = tid & 31, ty = tid >> 5;
    constexpr int P = BT / 16;
    for (int k0 = 0; k0 < K; k0 += 32) {
        __syncthreads();
        #pragma unroll
        for (int i = 0; i < (BT * 32) / 256; ++i) {
            int e = tid + i * 256;
            int r = e >> 5, kk = e & 31, kg = k0 + kk;
            float v = 0.f;
            if (kg < K) {
                const float* p = xp + (long)(b0 + r) * xs + kg;
                v = use_ldcg ? __ldcg(p) : __ldg(p);
            }
            a_s[kk][r] = v;
        }
        #pragma unroll
        for (int i = 0; i < 16; ++i) {
            int e = tid + i * 256;
            int c = e >> 5, kk = e & 31, kg = k0 + kk;
            float v = 0.f;
            if (kg < K) {
                int gc = j0 + (c >> 5) * 512 + (c & 31);
                v = __ldg(wp + (long)gc * ws + kg);
            }
            w_s[c][kk] = v;
        }
        __syncthreads();
        #pragma unroll
        for (int kk = 0; kk < 32; ++kk) {
            u64 av[P];
            #pragma unroll
            for (int p = 0; p < P; ++p)
                av[p] = *reinterpret_cast<const u64*>(&a_s[kk][ty * (2 * P) + 2 * p]);
            #pragma unroll
            for (int gi = 0; gi < 4; ++gi) {
                u64 wv2 = bcast2(w_s[gi * 32 + tx][kk]);
                #pragma unroll
                for (int p = 0; p < P; ++p)
                    ffma2(acc2[p][gi], av[p], wv2);
            }
        }
    }
}

// ---------------- bridge: elu(h/c_flat @ Wbᵀ + bb) -> decoder init ---------
__global__ __launch_bounds__(256) void bridge_kernel(
    const float* __restrict__ wb, const float* __restrict__ bb)
{
    __shared__ float in_s[32][33], w_s2[32][33];
    const int tid = threadIdx.x, tx = tid & 31, ty = tid >> 5;
    const int b0 = blockIdx.x * 32, m0 = blockIdx.y * 32, z = blockIdx.z;
    const float* srcs[4];
    if (z == 0) {
        srcs[0] = &g_h0fin[0][0][0]; srcs[1] = &g_h0fin[1][0][0];
        srcs[2] = &g_h1fin[0][0][0]; srcs[3] = &g_h1fin[1][0][0];
    } else {
        srcs[0] = &g_c[0][0][0][0]; srcs[1] = &g_c[0][1][0][0];
        srcs[2] = &g_c[1][0][0][0]; srcs[3] = &g_c[1][1][0][0];
    }
    float acc[4] = {0.f, 0.f, 0.f, 0.f};
    for (int k0 = 0; k0 < 2048; k0 += 32) {
        __syncthreads();
        const float* src = srcs[k0 >> 9];
        const int kl = k0 & 511;
        #pragma unroll
        for (int i = 0; i < 4; ++i) {
            int e = tid + i * 256;
            int r = e >> 5, kk = e & 31;
            in_s[r][kk] = src[(long)(b0 + r) * H_ + kl + kk];
            w_s2[r][kk] = wb[(long)(m0 + r) * 2048 + k0 + kk];
        }
        __syncthreads();
        #pragma unroll
        for (int kk = 0; kk < 32; ++kk) {
            float wv = w_s2[tx][kk];
            #pragma unroll
            for (int bi = 0; bi < 4; ++bi)
                acc[bi] = fmaf(in_s[ty * 4 + bi][kk], wv, acc[bi]);
        }
    }
    const int m = m0 + tx;
    #pragma unroll
    for (int bi = 0; bi < 4; ++bi) {
        int b = b0 + ty * 4 + bi;
        float v = acc[bi] + bb[m];
        v = (v > 0.f) ? v : expm1f(v);
        if (z == 0) {
            if (m < 512) g_dec_h0[0][b][m] = v; else g_dec_h1[0][b][m - 512] = v;
        } else {
            if (m < 512) g_dec_c0[b][m] = v;    else g_dec_c1[b][m - 512] = v;
        }
    }
}

// ---------------- decoder: persistent, 64 steps ----------------------------
__global__ __launch_bounds__(256, 1) void dec_persist(
    const float* __restrict__ X, const float* __restrict__ fut,
    const float* __restrict__ dwih0, const float* __restrict__ dwhh0,
    const float* __restrict__ db0,
    const float* __restrict__ dwih1, const float* __restrict__ dwhh1,
    const float* __restrict__ db1,
    const float* __restrict__ wo, const float* __restrict__ bo,
    float* __restrict__ out)
{
    __shared__ __align__(16) float a_s[32][20];
    __shared__ __align__(16) float w_s[128][33];
    __shared__ float red[8][MQ_];
    const int bid = blockIdx.x, tid = threadIdx.x;
    const int tx = tid & 31, ty = tid >> 5;
    const int b0 = (bid >> 4) * 16, j0 = (bid & 15) * 32;
    const int j = j0 + tx;

    if (tid < DIN_)
        g_decx[bid][tid] = (tid == 0)
            ? __ldg(X + (long)bid * T_ * DIN_ + (T_ - 1) * DIN_)
            : __ldg(fut + (long)bid * HOR_ * DFF_ + (tid - 1));

    const float b0I = __ldg(db0 + j),        b0F = __ldg(db0 + 512 + j),
                b0G = __ldg(db0 + 1024 + j), b0O = __ldg(db0 + 1536 + j);
    const float b1I = __ldg(db1 + j),        b1F = __ldg(db1 + 512 + j),
                b1G = __ldg(db1 + 1024 + j), b1O = __ldg(db1 + 1536 + j);
    float c0[2], c1[2];
    #pragma unroll
    for (int bi = 0; bi < 2; ++bi) {
        c0[bi] = g_dec_c0[b0 + ty * 2 + bi][j];
        c1[bi] = g_dec_c1[b0 + ty * 2 + bi][j];
    }
    grid_barrier(2, NBLK);

    for (int s = 0; s < HOR_; ++s) {
        {
            u64 acc2[1][4] = {};
            seg_accum<16>(a_s, w_s, &g_decx[0][0], DIN_, 1, dwih0, DIN_, DIN_, b0, j0, acc2);
            seg_accum<16>(a_s, w_s, &g_dec_h0[s & 1][0][0], H_, 1, dwhh0, H_, H_, b0, j0, acc2);
            float acc[2][4];
            #pragma unroll
            for (int gi = 0; gi < 4; ++gi)
                unpack2(acc2[0][gi], acc[0][gi], acc[1][gi]);
            #pragma unroll
            for (int bi = 0; bi < 2; ++bi) {
                float i_ = sigm_(acc[bi][0] + b0I);
                float f_ = sigm_(acc[bi][1] + b0F);
                float g_ = tanh_(acc[bi][2] + b0G);
                float o_ = sigm_(acc[bi][3] + b0O);
                float c  = f_ * c0[bi] + i_ * g_;
                c0[bi] = c;
                g_dec_h0[(s + 1) & 1][b0 + ty * 2 + bi][j] = o_ * tanh_(c);
            }
        }
        grid_barrier(2, NBLK);
        {
            u64 acc2[1][4] = {};
            seg_accum<16>(a_s, w_s, &g_dec_h0[(s + 1) & 1][0][0], H_, 1, dwih1, H_, H_, b0, j0, acc2);
            seg_accum<16>(a_s, w_s, &g_dec_h1[s & 1][0][0],       H_, 1, dwhh1, H_, H_, b0, j0, acc2);
            float acc[2][4];
            #pragma unroll
            for (int gi = 0; gi < 4; ++gi)
                unpack2(acc2[0][gi], acc[0][gi], acc[1][gi]);
            #pragma unroll
            for (int bi = 0; bi < 2; ++bi) {
                float i_ = sigm_(acc[bi][0] + b1I);
                float f_ = sigm_(acc[bi][1] + b1F);
                float g_ = tanh_(acc[bi][2] + b1G);
                float o_ = sigm_(acc[bi][3] + b1O);
                float c  = f_ * c1[bi] + i_ * g_;
                c1[bi] = c;
                g_dec_h1[(s + 1) & 1][b0 + ty * 2 + bi][j] = o_ * tanh_(c);
            }
        }
        grid_barrier(2, NBLK);
        {
            const float* h1 = &g_dec_h1[(s + 1) & 1][bid][0];
            float part[MQ_] = {0.f, 0.f, 0.f, 0.f, 0.f};
            for (int k = tid; k < H_; k += 256) {
                float hv = __ldcg(h1 + k);
                #pragma unroll
                for (int q = 0; q < MQ_; ++q)
                    part[q] = fmaf(hv, __ldg(wo + q * H_ + k), part[q]);
            }
            #pragma unroll
            for (int o = 16; o; o >>= 1)
                #pragma unroll
                for (int q = 0; q < MQ_; ++q)
                    part[q] += __shfl_down_sync(0xffffffffu, part[q], o);
            if ((tid & 31) == 0)
                #pragma unroll
                for (int q = 0; q < MQ_; ++q) red[tid >> 5][q] = part[q];
            __syncthreads();
            if (tid < MQ_) {
                float v = __ldg(bo + tid);
                #pragma unroll
                for (int w2 = 0; w2 < 8; ++w2) v += red[w2][tid];
                out[(long)bid * HOR_ * MQ_ + s * MQ_ + tid] = v;
                if (tid == 0) g_decx[bid][0] = v;
            }
            if (s + 1 < HOR_ && tid >= 32 && tid < 32 + DFF_)
                g_decx[bid][tid - 31] =
                    __ldg(fut + (long)bid * HOR_ * DFF_ + (s + 1) * DFF_ + (tid - 32));
        }
        grid_barrier(2, NBLK);
    }
}

// ---------------- launcher (6 graph nodes) ----------------
extern "C" void kernel_launch(void* const* d_in, const int* in_sizes, int n_in,
                              void* d_out, int out_size)
{
    int off = (n_in >= 4 && in_sizes[3] == 1) ? 0 : -1;
    const float* X     = (const float*)d_in[0];
    const float* fut   = (const float*)d_in[1];
    const float* ewih0 = (const float*)d_in[4 + off];
    const float* ewhh0 = (const float*)d_in[5 + off];
    const float* eb0   = (const float*)d_in[6 + off];
    const float* ewih1 = (const float*)d_in[7 + off];
    const float* ewhh1 = (const float*)d_in[8 + off];
    const float* eb1   = (const float*)d_in[9 + off];
    const float* dwih0 = (const float*)d_in[10 + off];
    const float* dwhh0 = (const float*)d_in[11 + off];
    const float* db0   = (const float*)d_in[12 + off];
    const float* dwih1 = (const float*)d_in[13 + off];
    const float* dwhh1 = (const float*)d_in[14 + off];
    const float* db1   = (const float*)d_in[15 + off];
    const float* wb    = (const float*)d_in[16 + off];
    const float* bb    = (const float*)d_in[17 + off];
    const float* wo    = (const float*)d_in[18 + off];
    const float* bo    = (const float*)d_in[19 + off];
    float* out = (float*)d_out;

    cudaFuncSetAttribute(enc_mma_persist<0>,
                         cudaFuncAttributeMaxDynamicSharedMemorySize, ENC_SMEM);
    cudaFuncSetAttribute(enc_mma_persist<1>,
                         cudaFuncAttributeMaxDynamicSharedMemorySize, ENC_SMEM);

    convB_kernel<<<2048, 256>>>(ewih1);
    enc_mma_persist<0><<<NBLK, 256, ENC_SMEM>>>(ewhh0, ewih0, X, eb0);
    gates1_mma<<<dim3(16, 512, 2), 256>>>();
    enc_mma_persist<1><<<NBLK, 256, ENC_SMEM>>>(ewhh1, nullptr, nullptr, eb1);
    bridge_kernel<<<dim3(4, 32, 2), 256>>>(wb, bb);
    dec_persist<<<NBLK, 256>>>(X, fut, dwih0, dwhh0, db0,
                               dwih1, dwhh1, db1, wo, bo, out);
}

// round 11
// speedup vs baseline: 1.4923x; 1.0092x over previous
#include <cuda_runtime.h>
#include <cuda_bf16.h>
#include <math.h>
#include <stdint.h>

#define B_   128
#define T_   512
#define H_   512
#define G_   2048
#define DIN_ 8
#define HOR_ 64
#define MQ_  5
#define DFF_ 7
#define NBLK 128

typedef unsigned long long u64;

// ---------------- scratch (device globals; no allocations) ----------------
__device__ float g_gates0[2][T_][B_][G_];    // precomputed layer-0 input gates
__device__ float g_gates1[2][T_][B_][G_];    // precomputed layer-1 input gates
__device__ float g_c[2][2][B_][H_];          // final cell states [layer][dir]
__device__ float g_h0fin[2][B_][H_];         // layer-0 final h per dir (fp32)
__device__ float g_h1fin[2][B_][H_];         // layer-1 final h per dir (fp32)
__device__ float g_dec_h0[2][B_][H_];
__device__ float g_dec_c0[B_][H_];
__device__ float g_dec_h1[2][B_][H_];
__device__ float g_dec_c1[B_][H_];
__device__ float g_decx[B_][DIN_];           // decoder input vector [y_fb, fut]

// bf16 hi/lo split activations (enc-L0 h sequence; also gates1_mma's A input)
__device__ __nv_bfloat16 g_Ah[T_ * B_][1024];
__device__ __nv_bfloat16 g_Al[T_ * B_][1024];
// layer-1 h ping-pong, bf16 hi/lo
__device__ __nv_bfloat16 g_h1h[2][2][B_][H_];
__device__ __nv_bfloat16 g_h1l[2][2][B_][H_];
// gates1 weights, bf16 hi/lo
__device__ __nv_bfloat16 g_Bh[2][G_][1024];
__device__ __nv_bfloat16 g_Bl[2][G_][1024];

// ---------------- distributed-slot grid barrier ----------------
// Arrival: ONE release store per CTA to its own 32B-padded slot (no atomic
// serialization). Leader CTA (block 0) polls all slots with WEAK volatile
// loads, then publishes a generation word; followers weak-poll that word.
// Counters are monotonic across graph replays (base re-read at kernel entry).
#define SLOT_STRIDE 8
__device__ unsigned g_arr[2][NBLK * SLOT_STRIDE];   // [0]=encoder, [1]=decoder
__device__ unsigned g_gen2[2][32];

__device__ __forceinline__ void slot_barrier(int idx, unsigned tgt)
{
    __syncthreads();
    const int tid = threadIdx.x;
    if (tid == 0) {
        __threadfence();                      // release prior writes
        *(volatile unsigned*)&g_arr[idx][blockIdx.x * SLOT_STRIDE] = tgt;
    }
    if (blockIdx.x == 0) {
        if (tid < NBLK) {
            while (*(volatile unsigned*)&g_arr[idx][tid * SLOT_STRIDE] < tgt) {}
        }
        __syncthreads();
        if (tid == 0) {
            __threadfence();                  // order observations before publish
            *(volatile unsigned*)&g_gen2[idx][0] = tgt;
            __threadfence();
        }
    } else {
        if (tid == 0) {
            while (*(volatile unsigned*)&g_gen2[idx][0] < tgt) {}   // WEAK poll
            __threadfence();                  // acquire
        }
    }
    __syncthreads();
}

// ---------------- packed fp32x2 helpers (decoder SIMT path) ----------------
__device__ __forceinline__ void ffma2(u64& d, u64 a, u64 b) {
    asm("fma.rn.f32x2 %0, %1, %2, %0;" : "+l"(d) : "l"(a), "l"(b));
}
__device__ __forceinline__ u64 bcast2(float v) {
    u64 r;
    asm("mov.b64 %0, {%1, %1};" : "=l"(r) : "f"(v));
    return r;
}
__device__ __forceinline__ void unpack2(u64 v, float& lo, float& hi) {
    asm("mov.b64 {%0, %1}, %2;" : "=f"(lo), "=f"(hi) : "l"(v));
}

// ---------------- fast transcendentals ----------------
__device__ __forceinline__ float sigm_(float x) {
    return __fdividef(1.f, 1.f + __expf(-x));
}
__device__ __forceinline__ float tanh_(float x) {
    return __fdividef(2.f, 1.f + __expf(-2.f * x)) - 1.f;
}

// ---------------- mma.sync / ldmatrix helpers ----------------
__device__ __forceinline__ uint32_t smem_u32(const void* p) {
    uint32_t a;
    asm("{ .reg .u64 t; cvta.to.shared.u64 t, %1; cvt.u32.u64 %0, t; }"
        : "=r"(a) : "l"(p));
    return a;
}
__device__ __forceinline__ void ldsm4(uint32_t a, uint32_t& r0, uint32_t& r1,
                                      uint32_t& r2, uint32_t& r3) {
    asm volatile("ldmatrix.sync.aligned.m8n8.x4.shared.b16 {%0,%1,%2,%3}, [%4];"
                 : "=r"(r0), "=r"(r1), "=r"(r2), "=r"(r3) : "r"(a));
}
__device__ __forceinline__ void ldsm2(uint32_t a, uint32_t& r0, uint32_t& r1) {
    asm volatile("ldmatrix.sync.aligned.m8n8.x2.shared.b16 {%0,%1}, [%2];"
                 : "=r"(r0), "=r"(r1) : "r"(a));
}
__device__ __forceinline__ void mma_bf16(float* c, const uint32_t* a, const uint32_t* b) {
    asm volatile(
        "mma.sync.aligned.m16n8k16.row.col.f32.bf16.bf16.f32 "
        "{%0,%1,%2,%3}, {%4,%5,%6,%7}, {%8,%9}, {%0,%1,%2,%3};"
        : "+f"(c[0]), "+f"(c[1]), "+f"(c[2]), "+f"(c[3])
        : "r"(a[0]), "r"(a[1]), "r"(a[2]), "r"(a[3]), "r"(b[0]), "r"(b[1]));
}

// ---------------- layer-0 input gates: one-shot tiny-K GEMM ----------------
__global__ __launch_bounds__(256) void gates0_gemm(
    const float* __restrict__ X, const float* __restrict__ w_ih)
{
    __shared__ float xs_[B_][DIN_];
    const int t = blockIdx.x, dir = blockIdx.y;
    const int tid = threadIdx.x;
    for (int e = tid; e < B_ * DIN_; e += 256) {
        int b = e >> 3, k = e & 7;
        xs_[b][k] = __ldg(X + ((long)b * T_ + t) * DIN_ + k);
    }
    __syncthreads();
    const float* w = w_ih + (long)dir * G_ * DIN_;
    for (int g = tid; g < G_; g += 256) {
        float4 w0 = *reinterpret_cast<const float4*>(w + g * DIN_);
        float4 w1 = *reinterpret_cast<const float4*>(w + g * DIN_ + 4);
        float* op = &g_gates0[dir][t][0][0];
        for (int b = 0; b < B_; ++b) {
            const float* xb = xs_[b];
            float acc = xb[0] * w0.x + xb[1] * w0.y + xb[2] * w0.z + xb[3] * w0.w
                      + xb[4] * w1.x + xb[5] * w1.y + xb[6] * w1.z + xb[7] * w1.w;
            op[(long)b * G_ + g] = acc;
        }
    }
}

// -------- fp32 -> bf16 hi/lo conversion for gates1 weights ----------------
__global__ __launch_bounds__(256) void convB_kernel(const float* __restrict__ w_ih1)
{
    const long npairs = (long)2 * G_ * 512;
    __nv_bfloat16* bh = &g_Bh[0][0][0];
    __nv_bfloat16* bl = &g_Bl[0][0][0];
    for (long p = (long)blockIdx.x * 256 + threadIdx.x; p < npairs;
         p += (long)gridDim.x * 256) {
        float2 v = *reinterpret_cast<const float2*>(w_ih1 + p * 2);
        __nv_bfloat16 h0 = __float2bfloat16(v.x);
        __nv_bfloat16 l0 = __float2bfloat16(v.x - __bfloat162float(h0));
        __nv_bfloat16 h1 = __float2bfloat16(v.y);
        __nv_bfloat16 l1 = __float2bfloat16(v.y - __bfloat162float(h1));
        *reinterpret_cast<__nv_bfloat162*>(bh + p * 2) = __nv_bfloat162(h0, h1);
        *reinterpret_cast<__nv_bfloat162*>(bl + p * 2) = __nv_bfloat162(l0, l1);
    }
}

// =========== persistent mma-based encoder layer (layer = 0 or 1) ==========
// Block = 64 batch x 64 gate-cols (16 j x 4 gate types), K=512/step.
// W_hh hi/lo resident in SMEM all 512 steps; A (=h) streamed per step in
// 8 double-buffered k-chunks of 64. 8 warps = 4M x 2N (warp: 16 x 32).
#define ESM_W_H 0
#define ESM_W_L 66560
#define ESM_A   133120
#define ESM_AB  9216
#define ESM_C   169984
#define ENC_SMEM 187392

template<int LAYER>
__global__ __launch_bounds__(256, 1) void enc_mma_persist(
    const float* __restrict__ w_hh, const float* __restrict__ bias)
{
    extern __shared__ __align__(16) char esm[];
    __nv_bfloat16* Wh = reinterpret_cast<__nv_bfloat16*>(esm + ESM_W_H);
    __nv_bfloat16* Wl = reinterpret_cast<__nv_bfloat16*>(esm + ESM_W_L);
    float* Cb = reinterpret_cast<float*>(esm + ESM_C);

    const int tid = threadIdx.x, lane = tid & 31, wid = tid >> 5;
    const int warp_m = wid & 3, warp_n = wid >> 2;
    const int bid = blockIdx.x;
    const int dir = bid >> 6, rr = bid & 63;
    const int b0 = (rr >> 5) * 64, j0 = (rr & 31) * 16;

    // barrier base (monotonic across launches/replays; quiescent at entry)
    const unsigned bar_base = *(volatile unsigned*)&g_arr[0][blockIdx.x * SLOT_STRIDE];
    unsigned bstep = 0;

    // ---- one-time W_hh load + hi/lo split into resident smem ----
    const float* wsrc = w_hh + (long)dir * G_ * H_;
    for (int idx = tid; idx < 64 * 512; idx += 256) {
        int n = idx >> 9, k = idx & 511;
        int gc = (n >> 4) * 512 + j0 + (n & 15);
        float v = __ldg(wsrc + (long)gc * H_ + k);
        __nv_bfloat16 h = __float2bfloat16(v);
        Wh[n * 520 + k] = h;
        Wl[n * 520 + k] = __float2bfloat16(v - __bfloat162float(h));
    }

    // ---- per-thread pointwise cell mapping: (pb batch-local, jq j-quad) ----
    const int pb = tid >> 2, jq = tid & 3;
    const float* bp = bias + dir * G_ + j0 + jq * 4;
    float4 bI = __ldg((const float4*)(bp));
    float4 bF = __ldg((const float4*)(bp + 512));
    float4 bG = __ldg((const float4*)(bp + 1024));
    float4 bO = __ldg((const float4*)(bp + 1536));
    float cst[4] = {0.f, 0.f, 0.f, 0.f};

    // ---- ldmatrix lane offsets ----
    uint32_t WhB = smem_u32(Wh), WlB = smem_u32(Wl);
    const uint32_t aRow = (uint32_t)((warp_m * 16 + (lane & 15)) * 144
                                     + (lane >> 4) * 16);
    uint32_t bRow[4];
    #pragma unroll
    for (int ni = 0; ni < 4; ++ni)
        bRow[ni] = (uint32_t)((warp_n * 32 + ni * 8 + (lane & 7)) * 1040
                              + ((lane >> 3) & 1) * 16);

    const float* gatesrc = (LAYER == 0 ? &g_gates0[0][0][0][0]
                                       : &g_gates1[0][0][0][0])
                         + (long)dir * T_ * B_ * G_;
    __syncthreads();

    for (int s = 0; s < T_; ++s) {
        const int t = dir ? (T_ - 1 - s) : s;
        // prefetch gate-init (hidden behind the MMA work)
        const float* gp = gatesrc + ((long)t * B_ + b0 + pb) * G_ + j0 + jq * 4;
        float4 gI = __ldg((const float4*)(gp));
        float4 gF = __ldg((const float4*)(gp + 512));
        float4 gG = __ldg((const float4*)(gp + 1024));
        float4 gO = __ldg((const float4*)(gp + 1536));

        float acc[4][4] = {};
        if (s > 0) {
            const __nv_bfloat16 *pAh, *pAl;
            long apitch;
            if (LAYER == 0) {
                const int tp = dir ? t + 1 : t - 1;
                pAh = &g_Ah[tp * 128 + b0][dir * 512];
                pAl = &g_Al[tp * 128 + b0][dir * 512];
                apitch = 1024;
            } else {
                pAh = &g_h1h[s & 1][dir][b0][0];
                pAl = &g_h1l[s & 1][dir][b0][0];
                apitch = 512;
            }
            uint4 stg[4];
            auto stage = [&](int kc) {
                #pragma unroll
                for (int i = 0; i < 4; ++i) {
                    int idx = tid + i * 256;
                    int term = idx >> 9, rem = idx & 511;
                    int row = rem >> 3, c8 = rem & 7;
                    const __nv_bfloat16* src =
                        (term ? pAl : pAh) + (long)row * apitch + kc * 64 + c8 * 8;
                    stg[i] = __ldcg(reinterpret_cast<const uint4*>(src));
                }
            };
            auto commitA = [&](int buf) {
                #pragma unroll
                for (int i = 0; i < 4; ++i) {
                    int idx = tid + i * 256;
                    int term = idx >> 9, rem = idx & 511;
                    int row = rem >> 3, c8 = rem & 7;
                    *reinterpret_cast<uint4*>(
                        esm + ESM_A + (buf * 2 + term) * ESM_AB + row * 144 + c8 * 16)
                        = stg[i];
                }
            };
            stage(0);
            commitA(0);
            __syncthreads();
            #pragma unroll 1
            for (int kc = 0; kc < 8; ++kc) {
                const int buf = kc & 1;
                if (kc < 7) stage(kc + 1);
                const uint32_t AhB = smem_u32(esm + ESM_A + (buf * 2) * ESM_AB);
                const uint32_t AlB = AhB + ESM_AB;
                #pragma unroll
                for (int ks = 0; ks < 4; ++ks) {
                    uint32_t ah[4], al[4], bh[4][2], bl[4][2];
                    ldsm4(AhB + aRow + ks * 32, ah[0], ah[1], ah[2], ah[3]);
                    ldsm4(AlB + aRow + ks * 32, al[0], al[1], al[2], al[3]);
                    #pragma unroll
                    for (int ni = 0; ni < 4; ++ni) {
                        ldsm2(WhB + bRow[ni] + kc * 128 + ks * 32, bh[ni][0], bh[ni][1]);
                        ldsm2(WlB + bRow[ni] + kc * 128 + ks * 32, bl[ni][0], bl[ni][1]);
                    }
                    #pragma unroll
                    for (int ni = 0; ni < 4; ++ni) {
                        mma_bf16(acc[ni], ah, bh[ni]);
                        mma_bf16(acc[ni], ah, bl[ni]);
                        mma_bf16(acc[ni], al, bh[ni]);
                    }
                }
                if (kc < 7) commitA(buf ^ 1);
                __syncthreads();
            }
        }
        // ---- epilogue: dump acc frags to Cbuf (64 x 64, pitch 68) ----
        {
            const int row = warp_m * 16 + (lane >> 2);
            #pragma unroll
            for (int ni = 0; ni < 4; ++ni) {
                const int col = warp_n * 32 + ni * 8 + (lane & 3) * 2;
                *reinterpret_cast<float2*>(&Cb[row * 68 + col]) =
                    make_float2(acc[ni][0], acc[ni][1]);
                *reinterpret_cast<float2*>(&Cb[(row + 8) * 68 + col]) =
                    make_float2(acc[ni][2], acc[ni][3]);
            }
        }
        __syncthreads();
        // ---- pointwise LSTM cell + h split/write ----
        {
            __align__(8) __nv_bfloat16 hh[4], hl[4];
            float hv[4];
            const float* gIv = (const float*)&gI;
            const float* gFv = (const float*)&gF;
            const float* gGv = (const float*)&gG;
            const float* gOv = (const float*)&gO;
            const float* bIv = (const float*)&bI;
            const float* bFv = (const float*)&bF;
            const float* bGv = (const float*)&bG;
            const float* bOv = (const float*)&bO;
            #pragma unroll
            for (int q = 0; q < 4; ++q) {
                const int jl = jq * 4 + q;
                float iv = Cb[pb * 68 + jl]      + gIv[q] + bIv[q];
                float fv = Cb[pb * 68 + 16 + jl] + gFv[q] + bFv[q];
                float gv = Cb[pb * 68 + 32 + jl] + gGv[q] + bGv[q];
                float ov = Cb[pb * 68 + 48 + jl] + gOv[q] + bOv[q];
                float i_ = sigm_(iv), f_ = sigm_(fv), g_ = tanh_(gv), o_ = sigm_(ov);
                float c = f_ * cst[q] + i_ * g_;
                cst[q] = c;
                float h = o_ * tanh_(c);
                hv[q] = h;
                hh[q] = __float2bfloat16(h);
                hl[q] = __float2bfloat16(h - __bfloat162float(hh[q]));
            }
            if (LAYER == 0) {
                *reinterpret_cast<uint2*>(&g_Ah[t * 128 + b0 + pb][dir * 512 + j0 + jq * 4])
                    = *reinterpret_cast<uint2*>(hh);
                *reinterpret_cast<uint2*>(&g_Al[t * 128 + b0 + pb][dir * 512 + j0 + jq * 4])
                    = *reinterpret_cast<uint2*>(hl);
                if (s == T_ - 1)
                    *reinterpret_cast<float4*>(&g_h0fin[dir][b0 + pb][j0 + jq * 4]) =
                        make_float4(hv[0], hv[1], hv[2], hv[3]);
            } else {
                *reinterpret_cast<uint2*>(&g_h1h[(s + 1) & 1][dir][b0 + pb][j0 + jq * 4])
                    = *reinterpret_cast<uint2*>(hh);
                *reinterpret_cast<uint2*>(&g_h1l[(s + 1) & 1][dir][b0 + pb][j0 + jq * 4])
                    = *reinterpret_cast<uint2*>(hl);
                if (s == T_ - 1)
                    *reinterpret_cast<float4*>(&g_h1fin[dir][b0 + pb][j0 + jq * 4]) =
                        make_float4(hv[0], hv[1], hv[2], hv[3]);
            }
        }
        slot_barrier(0, bar_base + (++bstep));
    }
    #pragma unroll
    for (int q = 0; q < 4; ++q)
        g_c[LAYER][dir][b0 + pb][j0 + jq * 4 + q] = cst[q];
}

// ======== gates1 via mma.sync bf16: D[128,128] = A[128,1024] @ W^T =========
#define PITCH 40

__global__ __launch_bounds__(256) void gates1_mma()
{
    __shared__ __align__(16) __nv_bfloat16 smem4[4][128 * PITCH];
    const int tid = threadIdx.x;
    const int wid = tid >> 5, lane = tid & 31;
    const int n0 = blockIdx.x * 128, r0 = blockIdx.y * 128, dir = blockIdx.z;
    const int warp_m = wid & 1, warp_n = wid >> 1;

    const __nv_bfloat16* srcs[4] = {
        &g_Ah[r0][0], &g_Al[r0][0], &g_Bh[dir][n0][0], &g_Bl[dir][n0][0] };
    uint32_t sb[4] = { smem_u32(smem4[0]), smem_u32(smem4[1]),
                       smem_u32(smem4[2]), smem_u32(smem4[3]) };

    uint32_t aOff[4], bOff[4];
    #pragma unroll
    for (int mi = 0; mi < 4; ++mi)
        aOff[mi] = (uint32_t)((warp_m * 64 + mi * 16 + (lane & 15)) * (PITCH * 2)
                              + (lane >> 4) * 16);
    #pragma unroll
    for (int ni = 0; ni < 4; ++ni)
        bOff[ni] = (uint32_t)((warp_n * 32 + ni * 8 + (lane & 7)) * (PITCH * 2)
                              + ((lane >> 3) & 1) * 16);

    uint2 stg[16];
    auto stage = [&](int kbase) {
        #pragma unroll
        for (int i = 0; i < 16; ++i) {
            int idx = i * 256 + tid;
            int tI = idx >> 10, row = (idx >> 3) & 127, c = idx & 7;
            stg[i] = *reinterpret_cast<const uint2*>(
                srcs[tI] + (long)row * 1024 + kbase + c * 4);
        }
    };
    auto commit = [&]() {
        #pragma unroll
        for (int i = 0; i < 16; ++i) {
            int idx = i * 256 + tid;
            int tI = idx >> 10, row = (idx >> 3) & 127, c = idx & 7;
            *reinterpret_cast<uint2*>(&smem4[tI][row * PITCH + c * 4]) = stg[i];
        }
    };

    float acc[4][4][4];
    #pragma unroll
    for (int mi = 0; mi < 4; ++mi)
        #pragma unroll
        for (int ni = 0; ni < 4; ++ni)
            #pragma unroll
            for (int q = 0; q < 4; ++q) acc[mi][ni][q] = 0.f;

    stage(0);
    commit();
    __syncthreads();
    #pragma unroll 1
    for (int kc = 0; kc < 32; ++kc) {
        if (kc < 31) stage((kc + 1) * 32);
        #pragma unroll
        for (int ks = 0; ks < 2; ++ks) {
            const uint32_t kb = ks * 32;
            uint32_t ah[4][4], al[4][4], bh[4][2], bl[4][2];
            #pragma unroll
            for (int mi = 0; mi < 4; ++mi) {
                ldsm4(sb[0] + aOff[mi] + kb, ah[mi][0], ah[mi][1], ah[mi][2], ah[mi][3]);
                ldsm4(sb[1] + aOff[mi] + kb, al[mi][0], al[mi][1], al[mi][2], al[mi][3]);
            }
            #pragma unroll
            for (int ni = 0; ni < 4; ++ni) {
                ldsm2(sb[2] + bOff[ni] + kb, bh[ni][0], bh[ni][1]);
                ldsm2(sb[3] + bOff[ni] + kb, bl[ni][0], bl[ni][1]);
            }
            #pragma unroll
            for (int mi = 0; mi < 4; ++mi)
                #pragma unroll
                for (int ni = 0; ni < 4; ++ni) {
                    mma_bf16(acc[mi][ni], ah[mi], bh[ni]);
                    mma_bf16(acc[mi][ni], ah[mi], bl[ni]);
                    mma_bf16(acc[mi][ni], al[mi], bh[ni]);
                }
        }
        __syncthreads();
        if (kc < 31) { commit(); __syncthreads(); }
    }

    float* ob = &g_gates1[dir][0][0][0];
    const int group = lane >> 2, tig = lane & 3;
    #pragma unroll
    for (int mi = 0; mi < 4; ++mi) {
        const long row = r0 + warp_m * 64 + mi * 16 + group;
        #pragma unroll
        for (int ni = 0; ni < 4; ++ni) {
            const int col = n0 + warp_n * 32 + ni * 8 + tig * 2;
            *reinterpret_cast<float2*>(ob + row * G_ + col) =
                make_float2(acc[mi][ni][0], acc[mi][ni][1]);
            *reinterpret_cast<float2*>(ob + (row + 8) * G_ + col) =
                make_float2(acc[mi][ni][2], acc[mi][ni][3]);
        }
    }
}

// -------- SIMT segment accumulate (decoder only, BT=16) -------------------
template<int BT>
__device__ __forceinline__ void seg_accum(
    float (*a_s)[BT + 4], float (*w_s)[33],
    const float* __restrict__ xp, int xs, int use_ldcg,
    const float* __restrict__ wp, int ws, int K,
    int b0, int j0, u64 acc2[BT / 16][4])
{
    const int tid = threadIdx.x, tx = tid & 31, ty = tid >> 5;
    constexpr int P = BT / 16;
    for (int k0 = 0; k0 < K; k0 += 32) {
        __syncthreads();
        #pragma unroll
        for (int i = 0; i < (BT * 32) / 256; ++i) {
            int e = tid + i * 256;
            int r = e >> 5, kk = e & 31, kg = k0 + kk;
            float v = 0.f;
            if (kg < K) {
                const float* p = xp + (long)(b0 + r) * xs + kg;
                v = use_ldcg ? __ldcg(p) : __ldg(p);
            }
            a_s[kk][r] = v;
        }
        #pragma unroll
        for (int i = 0; i < 16; ++i) {
            int e = tid + i * 256;
            int c = e >> 5, kk = e & 31, kg = k0 + kk;
            float v = 0.f;
            if (kg < K) {
                int gc = j0 + (c >> 5) * 512 + (c & 31);
                v = __ldg(wp + (long)gc * ws + kg);
            }
            w_s[c][kk] = v;
        }
        __syncthreads();
        #pragma unroll
        for (int kk = 0; kk < 32; ++kk) {
            u64 av[P];
            #pragma unroll
            for (int p = 0; p < P; ++p)
                av[p] = *reinterpret_cast<const u64*>(&a_s[kk][ty * (2 * P) + 2 * p]);
            #pragma unroll
            for (int gi = 0; gi < 4; ++gi) {
                u64 wv2 = bcast2(w_s[gi * 32 + tx][kk]);
                #pragma unroll
                for (int p = 0; p < P; ++p)
                    ffma2(acc2[p][gi], av[p], wv2);
            }
        }
    }
}

// ---------------- bridge: elu(h/c_flat @ Wbᵀ + bb) -> decoder init ---------
__global__ __launch_bounds__(256) void bridge_kernel(
    const float* __restrict__ wb, const float* __restrict__ bb)
{
    __shared__ float in_s[32][33], w_s2[32][33];
    const int tid = threadIdx.x, tx = tid & 31, ty = tid >> 5;
    const int b0 = blockIdx.x * 32, m0 = blockIdx.y * 32, z = blockIdx.z;
    const float* srcs[4];
    if (z == 0) {
        srcs[0] = &g_h0fin[0][0][0]; srcs[1] = &g_h0fin[1][0][0];
        srcs[2] = &g_h1fin[0][0][0]; srcs[3] = &g_h1fin[1][0][0];
    } else {
        srcs[0] = &g_c[0][0][0][0]; srcs[1] = &g_c[0][1][0][0];
        srcs[2] = &g_c[1][0][0][0]; srcs[3] = &g_c[1][1][0][0];
    }
    float acc[4] = {0.f, 0.f, 0.f, 0.f};
    for (int k0 = 0; k0 < 2048; k0 += 32) {
        __syncthreads();
        const float* src = srcs[k0 >> 9];
        const int kl = k0 & 511;
        #pragma unroll
        for (int i = 0; i < 4; ++i) {
            int e = tid + i * 256;
            int r = e >> 5, kk = e & 31;
            in_s[r][kk] = src[(long)(b0 + r) * H_ + kl + kk];
            w_s2[r][kk] = wb[(long)(m0 + r) * 2048 + k0 + kk];
        }
        __syncthreads();
        #pragma unroll
        for (int kk = 0; kk < 32; ++kk) {
            float wv = w_s2[tx][kk];
            #pragma unroll
            for (int bi = 0; bi < 4; ++bi)
                acc[bi] = fmaf(in_s[ty * 4 + bi][kk], wv, acc[bi]);
        }
    }
    const int m = m0 + tx;
    #pragma unroll
    for (int bi = 0; bi < 4; ++bi) {
        int b = b0 + ty * 4 + bi;
        float v = acc[bi] + bb[m];
        v = (v > 0.f) ? v : expm1f(v);
        if (z == 0) {
            if (m < 512) g_dec_h0[0][b][m] = v; else g_dec_h1[0][b][m - 512] = v;
        } else {
            if (m < 512) g_dec_c0[b][m] = v;    else g_dec_c1[b][m - 512] = v;
        }
    }
}

// ---------------- decoder: persistent, 64 steps ----------------------------
__global__ __launch_bounds__(256, 1) void dec_persist(
    const float* __restrict__ X, const float* __restrict__ fut,
    const float* __restrict__ dwih0, const float* __restrict__ dwhh0,
    const float* __restrict__ db0,
    const float* __restrict__ dwih1, const float* __restrict__ dwhh1,
    const float* __restrict__ db1,
    const float* __restrict__ wo, const float* __restrict__ bo,
    float* __restrict__ out)
{
    __shared__ __align__(16) float a_s[32][20];
    __shared__ __align__(16) float w_s[128][33];
    __shared__ float red[8][MQ_];
    const int bid = blockIdx.x, tid = threadIdx.x;
    const int tx = tid & 31, ty = tid >> 5;
    const int b0 = (bid >> 4) * 16, j0 = (bid & 15) * 32;
    const int j = j0 + tx;

    const unsigned bar_base = *(volatile unsigned*)&g_arr[1][blockIdx.x * SLOT_STRIDE];
    unsigned bstep = 0;

    if (tid < DIN_)
        g_decx[bid][tid] = (tid == 0)
            ? __ldg(X + (long)bid * T_ * DIN_ + (T_ - 1) * DIN_)
            : __ldg(fut + (long)bid * HOR_ * DFF_ + (tid - 1));

    const float b0I = __ldg(db0 + j),        b0F = __ldg(db0 + 512 + j),
                b0G = __ldg(db0 + 1024 + j), b0O = __ldg(db0 + 1536 + j);
    const float b1I = __ldg(db1 + j),        b1F = __ldg(db1 + 512 + j),
                b1G = __ldg(db1 + 1024 + j), b1O = __ldg(db1 + 1536 + j);
    float c0[2], c1[2];
    #pragma unroll
    for (int bi = 0; bi < 2; ++bi) {
        c0[bi] = g_dec_c0[b0 + ty * 2 + bi][j];
        c1[bi] = g_dec_c1[b0 + ty * 2 + bi][j];
    }
    slot_barrier(1, bar_base + (++bstep));

    for (int s = 0; s < HOR_; ++s) {
        {
            u64 acc2[1][4] = {};
            seg_accum<16>(a_s, w_s, &g_decx[0][0], DIN_, 1, dwih0, DIN_, DIN_, b0, j0, acc2);
            seg_accum<16>(a_s, w_s, &g_dec_h0[s & 1][0][0], H_, 1, dwhh0, H_, H_, b0, j0, acc2);
            float acc[2][4];
            #pragma unroll
            for (int gi = 0; gi < 4; ++gi)
                unpack2(acc2[0][gi], acc[0][gi], acc[1][gi]);
            #pragma unroll
            for (int bi = 0; bi < 2; ++bi) {
                float i_ = sigm_(acc[bi][0] + b0I);
                float f_ = sigm_(acc[bi][1] + b0F);
                float g_ = tanh_(acc[bi][2] + b0G);
                float o_ = sigm_(acc[bi][3] + b0O);
                float c  = f_ * c0[bi] + i_ * g_;
                c0[bi] = c;
                g_dec_h0[(s + 1) & 1][b0 + ty * 2 + bi][j] = o_ * tanh_(c);
            }
        }
        slot_barrier(1, bar_base + (++bstep));
        {
            u64 acc2[1][4] = {};
            seg_accum<16>(a_s, w_s, &g_dec_h0[(s + 1) & 1][0][0], H_, 1, dwih1, H_, H_, b0, j0, acc2);
            seg_accum<16>(a_s, w_s, &g_dec_h1[s & 1][0][0],       H_, 1, dwhh1, H_, H_, b0, j0, acc2);
            float acc[2][4];
            #pragma unroll
            for (int gi = 0; gi < 4; ++gi)
                unpack2(acc2[0][gi], acc[0][gi], acc[1][gi]);
            #pragma unroll
            for (int bi = 0; bi < 2; ++bi) {
                float i_ = sigm_(acc[bi][0] + b1I);
                float f_ = sigm_(acc[bi][1] + b1F);
                float g_ = tanh_(acc[bi][2] + b1G);
                float o_ = sigm_(acc[bi][3] + b1O);
                float c  = f_ * c1[bi] + i_ * g_;
                c1[bi] = c;
                g_dec_h1[(s + 1) & 1][b0 + ty * 2 + bi][j] = o_ * tanh_(c);
            }
        }
        slot_barrier(1, bar_base + (++bstep));
        {
            const float* h1 = &g_dec_h1[(s + 1) & 1][bid][0];
            float part[MQ_] = {0.f, 0.f, 0.f, 0.f, 0.f};
            for (int k = tid; k < H_; k += 256) {
                float hv = __ldcg(h1 + k);
                #pragma unroll
                for (int q = 0; q < MQ_; ++q)
                    part[q] = fmaf(hv, __ldg(wo + q * H_ + k), part[q]);
            }
            #pragma unroll
            for (int o = 16; o; o >>= 1)
                #pragma unroll
                for (int q = 0; q < MQ_; ++q)
                    part[q] += __shfl_down_sync(0xffffffffu, part[q], o);
            if ((tid & 31) == 0)
                #pragma unroll
                for (int q = 0; q < MQ_; ++q) red[tid >> 5][q] = part[q];
            __syncthreads();
            if (tid < MQ_) {
                float v = __ldg(bo + tid);
                #pragma unroll
                for (int w2 = 0; w2 < 8; ++w2) v += red[w2][tid];
                out[(long)bid * HOR_ * MQ_ + s * MQ_ + tid] = v;
                if (tid == 0) g_decx[bid][0] = v;
            }
            if (s + 1 < HOR_ && tid >= 32 && tid < 32 + DFF_)
                g_decx[bid][tid - 31] =
                    __ldg(fut + (long)bid * HOR_ * DFF_ + (s + 1) * DFF_ + (tid - 32));
        }
        slot_barrier(1, bar_base + (++bstep));
    }
}

// ---------------- launcher (7 graph nodes) ----------------
extern "C" void kernel_launch(void* const* d_in, const int* in_sizes, int n_in,
                              void* d_out, int out_size)
{
    int off = (n_in >= 4 && in_sizes[3] == 1) ? 0 : -1;
    const float* X     = (const float*)d_in[0];
    const float* fut   = (const float*)d_in[1];
    const float* ewih0 = (const float*)d_in[4 + off];
    const float* ewhh0 = (const float*)d_in[5 + off];
    const float* eb0   = (const float*)d_in[6 + off];
    const float* ewih1 = (const float*)d_in[7 + off];
    const float* ewhh1 = (const float*)d_in[8 + off];
    const float* eb1   = (const float*)d_in[9 + off];
    const float* dwih0 = (const float*)d_in[10 + off];
    const float* dwhh0 = (const float*)d_in[11 + off];
    const float* db0   = (const float*)d_in[12 + off];
    const float* dwih1 = (const float*)d_in[13 + off];
    const float* dwhh1 = (const float*)d_in[14 + off];
    const float* db1   = (const float*)d_in[15 + off];
    const float* wb    = (const float*)d_in[16 + off];
    const float* bb    = (const float*)d_in[17 + off];
    const float* wo    = (const float*)d_in[18 + off];
    const float* bo    = (const float*)d_in[19 + off];
    float* out = (float*)d_out;

    cudaFuncSetAttribute(enc_mma_persist<0>,
                         cudaFuncAttributeMaxDynamicSharedMemorySize, ENC_SMEM);
    cudaFuncSetAttribute(enc_mma_persist<1>,
                         cudaFuncAttributeMaxDynamicSharedMemorySize, ENC_SMEM);

    gates0_gemm<<<dim3(T_, 2), 256>>>(X, ewih0);
    convB_kernel<<<2048, 256>>>(ewih1);
    enc_mma_persist<0><<<NBLK, 256, ENC_SMEM>>>(ewhh0, eb0);
    gates1_mma<<<dim3(16, 512, 2), 256>>>();
    enc_mma_persist<1><<<NBLK, 256, ENC_SMEM>>>(ewhh1, eb1);
    bridge_kernel<<<dim3(4, 32, 2), 256>>>(wb, bb);
    dec_persist<<<NBLK, 256>>>(X, fut, dwih0, dwhh0, db0,
                               dwih1, dwhh1, db1, wo, bo, out);
}

// round 12
// speedup vs baseline: 1.4976x; 1.0035x over previous
#include <cuda_runtime.h>
#include <cuda_bf16.h>
#include <math.h>
#include <stdint.h>

#define B_   128
#define T_   512
#define H_   512
#define G_   2048
#define DIN_ 8
#define HOR_ 64
#define MQ_  5
#define DFF_ 7
#define NBLK 128

typedef unsigned long long u64;

// ---------------- scratch (device globals; no allocations) ----------------
__device__ float g_gates0[2][T_][B_][G_];    // precomputed layer-0 input gates
__device__ float g_gates1[2][T_][B_][G_];    // precomputed layer-1 input gates
__device__ float g_c[2][2][B_][H_];          // final cell states [layer][dir]
__device__ float g_h0fin[2][B_][H_];         // layer-0 final h per dir (fp32)
__device__ float g_h1fin[2][B_][H_];         // layer-1 final h per dir (fp32)
__device__ float g_dec_h0[2][B_][H_];
__device__ float g_dec_c0[B_][H_];
__device__ float g_dec_h1[2][B_][H_];
__device__ float g_dec_c1[B_][H_];
__device__ float g_decx[B_][DIN_];           // decoder input vector [y_fb, fut]
__device__ unsigned g_bar_cnt;
__device__ unsigned g_bar_gen;

// bf16 hi/lo split activations (enc-L0 h sequence; also gates1_mma's A input)
__device__ __nv_bfloat16 g_Ah[T_ * B_][1024];
__device__ __nv_bfloat16 g_Al[T_ * B_][1024];
// layer-1 h ping-pong, bf16 hi/lo
__device__ __nv_bfloat16 g_h1h[2][2][B_][H_];
__device__ __nv_bfloat16 g_h1l[2][2][B_][H_];
// gates1 weights, bf16 hi/lo
__device__ __nv_bfloat16 g_Bh[2][G_][1024];
__device__ __nv_bfloat16 g_Bl[2][G_][1024];

// ---------------- software grid barrier (R8 mechanism, verbatim) ----------
__device__ __forceinline__ void grid_barrier()
{
    __syncthreads();
    if (threadIdx.x == 0) {
        volatile unsigned* genp = &g_bar_gen;
        unsigned gen = *genp;
        __threadfence();
        if (atomicAdd(&g_bar_cnt, 1u) == NBLK - 1u) {
            g_bar_cnt = 0u;
            __threadfence();
            *genp = gen + 1u;
        } else {
            while (*genp == gen) { }
        }
        __threadfence();
    }
    __syncthreads();
}

// ---------------- packed fp32x2 helpers (decoder SIMT path) ----------------
__device__ __forceinline__ void ffma2(u64& d, u64 a, u64 b) {
    asm("fma.rn.f32x2 %0, %1, %2, %0;" : "+l"(d) : "l"(a), "l"(b));
}
__device__ __forceinline__ u64 bcast2(float v) {
    u64 r;
    asm("mov.b64 %0, {%1, %1};" : "=l"(r) : "f"(v));
    return r;
}
__device__ __forceinline__ void unpack2(u64 v, float& lo, float& hi) {
    asm("mov.b64 {%0, %1}, %2;" : "=f"(lo), "=f"(hi) : "l"(v));
}

// ---------------- fast transcendentals ----------------
__device__ __forceinline__ float sigm_(float x) {
    return __fdividef(1.f, 1.f + __expf(-x));
}
__device__ __forceinline__ float tanh_(float x) {
    return __fdividef(2.f, 1.f + __expf(-2.f * x)) - 1.f;
}

// ---------------- mma.sync / ldmatrix helpers ----------------
__device__ __forceinline__ uint32_t smem_u32(const void* p) {
    uint32_t a;
    asm("{ .reg .u64 t; cvta.to.shared.u64 t, %1; cvt.u32.u64 %0, t; }"
        : "=r"(a) : "l"(p));
    return a;
}
__device__ __forceinline__ void ldsm4(uint32_t a, uint32_t& r0, uint32_t& r1,
                                      uint32_t& r2, uint32_t& r3) {
    asm volatile("ldmatrix.sync.aligned.m8n8.x4.shared.b16 {%0,%1,%2,%3}, [%4];"
                 : "=r"(r0), "=r"(r1), "=r"(r2), "=r"(r3) : "r"(a));
}
__device__ __forceinline__ void ldsm2(uint32_t a, uint32_t& r0, uint32_t& r1) {
    asm volatile("ldmatrix.sync.aligned.m8n8.x2.shared.b16 {%0,%1}, [%2];"
                 : "=r"(r0), "=r"(r1) : "r"(a));
}
__device__ __forceinline__ void mma_bf16(float* c, const uint32_t* a, const uint32_t* b) {
    asm volatile(
        "mma.sync.aligned.m16n8k16.row.col.f32.bf16.bf16.f32 "
        "{%0,%1,%2,%3}, {%4,%5,%6,%7}, {%8,%9}, {%0,%1,%2,%3};"
        : "+f"(c[0]), "+f"(c[1]), "+f"(c[2]), "+f"(c[3])
        : "r"(a[0]), "r"(a[1]), "r"(a[2]), "r"(a[3]), "r"(b[0]), "r"(b[1]));
}

// ---------------- layer-0 input gates: one-shot tiny-K GEMM ----------------
__global__ __launch_bounds__(256) void gates0_gemm(
    const float* __restrict__ X, const float* __restrict__ w_ih)
{
    __shared__ float xs_[B_][DIN_];
    const int t = blockIdx.x, dir = blockIdx.y;
    const int tid = threadIdx.x;
    for (int e = tid; e < B_ * DIN_; e += 256) {
        int b = e >> 3, k = e & 7;
        xs_[b][k] = __ldg(X + ((long)b * T_ + t) * DIN_ + k);
    }
    __syncthreads();
    const float* w = w_ih + (long)dir * G_ * DIN_;
    for (int g = tid; g < G_; g += 256) {
        float4 w0 = *reinterpret_cast<const float4*>(w + g * DIN_);
        float4 w1 = *reinterpret_cast<const float4*>(w + g * DIN_ + 4);
        float* op = &g_gates0[dir][t][0][0];
        for (int b = 0; b < B_; ++b) {
            const float* xb = xs_[b];
            float acc = xb[0] * w0.x + xb[1] * w0.y + xb[2] * w0.z + xb[3] * w0.w
                      + xb[4] * w1.x + xb[5] * w1.y + xb[6] * w1.z + xb[7] * w1.w;
            op[(long)b * G_ + g] = acc;
        }
    }
}

// -------- fp32 -> bf16 hi/lo conversion for gates1 weights ----------------
__global__ __launch_bounds__(256) void convB_kernel(const float* __restrict__ w_ih1)
{
    const long npairs = (long)2 * G_ * 512;
    __nv_bfloat16* bh = &g_Bh[0][0][0];
    __nv_bfloat16* bl = &g_Bl[0][0][0];
    for (long p = (long)blockIdx.x * 256 + threadIdx.x; p < npairs;
         p += (long)gridDim.x * 256) {
        float2 v = *reinterpret_cast<const float2*>(w_ih1 + p * 2);
        __nv_bfloat16 h0 = __float2bfloat16(v.x);
        __nv_bfloat16 l0 = __float2bfloat16(v.x - __bfloat162float(h0));
        __nv_bfloat16 h1 = __float2bfloat16(v.y);
        __nv_bfloat16 l1 = __float2bfloat16(v.y - __bfloat162float(h1));
        *reinterpret_cast<__nv_bfloat162*>(bh + p * 2) = __nv_bfloat162(h0, h1);
        *reinterpret_cast<__nv_bfloat162*>(bl + p * 2) = __nv_bfloat162(l0, l1);
    }
}

// =========== persistent mma-based encoder layer (layer = 0 or 1) ==========
// Block = 64 batch x 64 gate-cols (16 j x 4 gate types), K=512/step.
// W_hh hi/lo resident in SMEM all 512 steps; A (=h) streamed per step in
// 4 double-buffered k-chunks of 128. 8 warps = 4M x 2N (warp: 16 x 32).
#define ESM_W_H 0
#define ESM_W_L 66560
#define ESM_A   133120
#define ESM_AB  17408
#define ESM_C   202752
#define ENC_SMEM 220160

template<int LAYER>
__global__ __launch_bounds__(256, 1) void enc_mma_persist(
    const float* __restrict__ w_hh, const float* __restrict__ bias)
{
    extern __shared__ __align__(16) char esm[];
    __nv_bfloat16* Wh = reinterpret_cast<__nv_bfloat16*>(esm + ESM_W_H);
    __nv_bfloat16* Wl = reinterpret_cast<__nv_bfloat16*>(esm + ESM_W_L);
    float* Cb = reinterpret_cast<float*>(esm + ESM_C);

    const int tid = threadIdx.x, lane = tid & 31, wid = tid >> 5;
    const int warp_m = wid & 3, warp_n = wid >> 2;
    const int bid = blockIdx.x;
    const int dir = bid >> 6, rr = bid & 63;
    const int b0 = (rr >> 5) * 64, j0 = (rr & 31) * 16;

    // ---- one-time W_hh load + hi/lo split into resident smem ----
    const float* wsrc = w_hh + (long)dir * G_ * H_;
    for (int idx = tid; idx < 64 * 512; idx += 256) {
        int n = idx >> 9, k = idx & 511;
        int gc = (n >> 4) * 512 + j0 + (n & 15);
        float v = __ldg(wsrc + (long)gc * H_ + k);
        __nv_bfloat16 h = __float2bfloat16(v);
        Wh[n * 520 + k] = h;
        Wl[n * 520 + k] = __float2bfloat16(v - __bfloat162float(h));
    }

    // ---- per-thread pointwise cell mapping: (pb batch-local, jq j-quad) ----
    const int pb = tid >> 2, jq = tid & 3;
    const float* bp = bias + dir * G_ + j0 + jq * 4;
    float4 bI = __ldg((const float4*)(bp));
    float4 bF = __ldg((const float4*)(bp + 512));
    float4 bG = __ldg((const float4*)(bp + 1024));
    float4 bO = __ldg((const float4*)(bp + 1536));
    float cst[4] = {0.f, 0.f, 0.f, 0.f};

    // ---- ldmatrix lane offsets ----
    uint32_t WhB = smem_u32(Wh), WlB = smem_u32(Wl);
    const uint32_t aRow = (uint32_t)((warp_m * 16 + (lane & 15)) * 272
                                     + (lane >> 4) * 16);
    uint32_t bRow[4];
    #pragma unroll
    for (int ni = 0; ni < 4; ++ni)
        bRow[ni] = (uint32_t)((warp_n * 32 + ni * 8 + (lane & 7)) * 1040
                              + ((lane >> 3) & 1) * 16);

    const float* gatesrc = (LAYER == 0 ? &g_gates0[0][0][0][0]
                                       : &g_gates1[0][0][0][0])
                         + (long)dir * T_ * B_ * G_;
    __syncthreads();

    for (int s = 0; s < T_; ++s) {
        const int t = dir ? (T_ - 1 - s) : s;
        // prefetch gate-init (hidden behind the MMA work)
        const float* gp = gatesrc + ((long)t * B_ + b0 + pb) * G_ + j0 + jq * 4;
        float4 gI = __ldg((const float4*)(gp));
        float4 gF = __ldg((const float4*)(gp + 512));
        float4 gG = __ldg((const float4*)(gp + 1024));
        float4 gO = __ldg((const float4*)(gp + 1536));

        float acc[4][4] = {};
        if (s > 0) {
            const __nv_bfloat16 *pAh, *pAl;
            long apitch;
            if (LAYER == 0) {
                const int tp = dir ? t + 1 : t - 1;
                pAh = &g_Ah[tp * 128 + b0][dir * 512];
                pAl = &g_Al[tp * 128 + b0][dir * 512];
                apitch = 1024;
            } else {
                pAh = &g_h1h[s & 1][dir][b0][0];
                pAl = &g_h1l[s & 1][dir][b0][0];
                apitch = 512;
            }
            uint4 stg[8];
            auto stage = [&](int kc) {
                #pragma unroll
                for (int i = 0; i < 8; ++i) {
                    int idx = tid + i * 256;            // 0..2047
                    int term = idx >> 10, rem = idx & 1023;
                    int row = rem >> 4, c8 = rem & 15;
                    const __nv_bfloat16* src =
                        (term ? pAl : pAh) + (long)row * apitch + kc * 128 + c8 * 8;
                    stg[i] = __ldcg(reinterpret_cast<const uint4*>(src));
                }
            };
            auto commitA = [&](int buf) {
                #pragma unroll
                for (int i = 0; i < 8; ++i) {
                    int idx = tid + i * 256;
                    int term = idx >> 10, rem = idx & 1023;
                    int row = rem >> 4, c8 = rem & 15;
                    *reinterpret_cast<uint4*>(
                        esm + ESM_A + (buf * 2 + term) * ESM_AB + row * 272 + c8 * 16)
                        = stg[i];
                }
            };
            stage(0);
            commitA(0);
            __syncthreads();
            #pragma unroll 1
            for (int kc = 0; kc < 4; ++kc) {
                const int buf = kc & 1;
                if (kc < 3) stage(kc + 1);
                const uint32_t AhB = smem_u32(esm + ESM_A + (buf * 2) * ESM_AB);
                const uint32_t AlB = AhB + ESM_AB;
                #pragma unroll
                for (int ks = 0; ks < 8; ++ks) {
                    uint32_t ah[4], al[4], bh[4][2], bl[4][2];
                    ldsm4(AhB + aRow + ks * 32, ah[0], ah[1], ah[2], ah[3]);
                    ldsm4(AlB + aRow + ks * 32, al[0], al[1], al[2], al[3]);
                    #pragma unroll
                    for (int ni = 0; ni < 4; ++ni) {
                        ldsm2(WhB + bRow[ni] + kc * 256 + ks * 32, bh[ni][0], bh[ni][1]);
                        ldsm2(WlB + bRow[ni] + kc * 256 + ks * 32, bl[ni][0], bl[ni][1]);
                    }
                    #pragma unroll
                    for (int ni = 0; ni < 4; ++ni) {
                        mma_bf16(acc[ni], ah, bh[ni]);
                        mma_bf16(acc[ni], ah, bl[ni]);
                        mma_bf16(acc[ni], al, bh[ni]);
                    }
                }
                if (kc < 3) commitA(buf ^ 1);
                __syncthreads();
            }
        }
        // ---- epilogue: dump acc frags to Cbuf (64 x 64, pitch 68) ----
        {
            const int row = warp_m * 16 + (lane >> 2);
            #pragma unroll
            for (int ni = 0; ni < 4; ++ni) {
                const int col = warp_n * 32 + ni * 8 + (lane & 3) * 2;
                *reinterpret_cast<float2*>(&Cb[row * 68 + col]) =
                    make_float2(acc[ni][0], acc[ni][1]);
                *reinterpret_cast<float2*>(&Cb[(row + 8) * 68 + col]) =
                    make_float2(acc[ni][2], acc[ni][3]);
            }
        }
        __syncthreads();
        // ---- pointwise LSTM cell + h split/write ----
        {
            __align__(8) __nv_bfloat16 hh[4], hl[4];
            float hv[4];
            const float* gIv = (const float*)&gI;
            const float* gFv = (const float*)&gF;
            const float* gGv = (const float*)&gG;
            const float* gOv = (const float*)&gO;
            const float* bIv = (const float*)&bI;
            const float* bFv = (const float*)&bF;
            const float* bGv = (const float*)&bG;
            const float* bOv = (const float*)&bO;
            #pragma unroll
            for (int q = 0; q < 4; ++q) {
                const int jl = jq * 4 + q;
                float iv = Cb[pb * 68 + jl]      + gIv[q] + bIv[q];
                float fv = Cb[pb * 68 + 16 + jl] + gFv[q] + bFv[q];
                float gv = Cb[pb * 68 + 32 + jl] + gGv[q] + bGv[q];
                float ov = Cb[pb * 68 + 48 + jl] + gOv[q] + bOv[q];
                float i_ = sigm_(iv), f_ = sigm_(fv), g_ = tanh_(gv), o_ = sigm_(ov);
                float c = f_ * cst[q] + i_ * g_;
                cst[q] = c;
                float h = o_ * tanh_(c);
                hv[q] = h;
                hh[q] = __float2bfloat16(h);
                hl[q] = __float2bfloat16(h - __bfloat162float(hh[q]));
            }
            if (LAYER == 0) {
                *reinterpret_cast<uint2*>(&g_Ah[t * 128 + b0 + pb][dir * 512 + j0 + jq * 4])
                    = *reinterpret_cast<uint2*>(hh);
                *reinterpret_cast<uint2*>(&g_Al[t * 128 + b0 + pb][dir * 512 + j0 + jq * 4])
                    = *reinterpret_cast<uint2*>(hl);
                if (s == T_ - 1)
                    *reinterpret_cast<float4*>(&g_h0fin[dir][b0 + pb][j0 + jq * 4]) =
                        make_float4(hv[0], hv[1], hv[2], hv[3]);
            } else {
                *reinterpret_cast<uint2*>(&g_h1h[(s + 1) & 1][dir][b0 + pb][j0 + jq * 4])
                    = *reinterpret_cast<uint2*>(hh);
                *reinterpret_cast<uint2*>(&g_h1l[(s + 1) & 1][dir][b0 + pb][j0 + jq * 4])
                    = *reinterpret_cast<uint2*>(hl);
                if (s == T_ - 1)
                    *reinterpret_cast<float4*>(&g_h1fin[dir][b0 + pb][j0 + jq * 4]) =
                        make_float4(hv[0], hv[1], hv[2], hv[3]);
            }
        }
        grid_barrier();
    }
    #pragma unroll
    for (int q = 0; q < 4; ++q)
        g_c[LAYER][dir][b0 + pb][j0 + jq * 4 + q] = cst[q];
}

// ======== gates1 via mma.sync bf16: D[128,128] = A[128,1024] @ W^T =========
#define PITCH 40

__global__ __launch_bounds__(256) void gates1_mma()
{
    __shared__ __align__(16) __nv_bfloat16 smem4[4][128 * PITCH];
    const int tid = threadIdx.x;
    const int wid = tid >> 5, lane = tid & 31;
    const int n0 = blockIdx.x * 128, r0 = blockIdx.y * 128, dir = blockIdx.z;
    const int warp_m = wid & 1, warp_n = wid >> 1;

    const __nv_bfloat16* srcs[4] = {
        &g_Ah[r0][0], &g_Al[r0][0], &g_Bh[dir][n0][0], &g_Bl[dir][n0][0] };
    uint32_t sb[4] = { smem_u32(smem4[0]), smem_u32(smem4[1]),
                       smem_u32(smem4[2]), smem_u32(smem4[3]) };

    uint32_t aOff[4], bOff[4];
    #pragma unroll
    for (int mi = 0; mi < 4; ++mi)
        aOff[mi] = (uint32_t)((warp_m * 64 + mi * 16 + (lane & 15)) * (PITCH * 2)
                              + (lane >> 4) * 16);
    #pragma unroll
    for (int ni = 0; ni < 4; ++ni)
        bOff[ni] = (uint32_t)((warp_n * 32 + ni * 8 + (lane & 7)) * (PITCH * 2)
                              + ((lane >> 3) & 1) * 16);

    uint2 stg[16];
    auto stage = [&](int kbase) {
        #pragma unroll
        for (int i = 0; i < 16; ++i) {
            int idx = i * 256 + tid;
            int tI = idx >> 10, row = (idx >> 3) & 127, c = idx & 7;
            stg[i] = *reinterpret_cast<const uint2*>(
                srcs[tI] + (long)row * 1024 + kbase + c * 4);
        }
    };
    auto commit = [&]() {
        #pragma unroll
        for (int i = 0; i < 16; ++i) {
            int idx = i * 256 + tid;
            int tI = idx >> 10, row = (idx >> 3) & 127, c = idx & 7;
            *reinterpret_cast<uint2*>(&smem4[tI][row * PITCH + c * 4]) = stg[i];
        }
    };

    float acc[4][4][4];
    #pragma unroll
    for (int mi = 0; mi < 4; ++mi)
        #pragma unroll
        for (int ni = 0; ni < 4; ++ni)
            #pragma unroll
            for (int q = 0; q < 4; ++q) acc[mi][ni][q] = 0.f;

    stage(0);
    commit();
    __syncthreads();
    #pragma unroll 1
    for (int kc = 0; kc < 32; ++kc) {
        if (kc < 31) stage((kc + 1) * 32);
        #pragma unroll
        for (int ks = 0; ks < 2; ++ks) {
            const uint32_t kb = ks * 32;
            uint32_t ah[4][4], al[4][4], bh[4][2], bl[4][2];
            #pragma unroll
            for (int mi = 0; mi < 4; ++mi) {
                ldsm4(sb[0] + aOff[mi] + kb, ah[mi][0], ah[mi][1], ah[mi][2], ah[mi][3]);
                ldsm4(sb[1] + aOff[mi] + kb, al[mi][0], al[mi][1], al[mi][2], al[mi][3]);
            }
            #pragma unroll
            for (int ni = 0; ni < 4; ++ni) {
                ldsm2(sb[2] + bOff[ni] + kb, bh[ni][0], bh[ni][1]);
                ldsm2(sb[3] + bOff[ni] + kb, bl[ni][0], bl[ni][1]);
            }
            #pragma unroll
            for (int mi = 0; mi < 4; ++mi)
                #pragma unroll
                for (int ni = 0; ni < 4; ++ni) {
                    mma_bf16(acc[mi][ni], ah[mi], bh[ni]);
                    mma_bf16(acc[mi][ni], ah[mi], bl[ni]);
                    mma_bf16(acc[mi][ni], al[mi], bh[ni]);
                }
        }
        __syncthreads();
        if (kc < 31) { commit(); __syncthreads(); }
    }

    float* ob = &g_gates1[dir][0][0][0];
    const int group = lane >> 2, tig = lane & 3;
    #pragma unroll
    for (int mi = 0; mi < 4; ++mi) {
        const long row = r0 + warp_m * 64 + mi * 16 + group;
        #pragma unroll
        for (int ni = 0; ni < 4; ++ni) {
            const int col = n0 + warp_n * 32 + ni * 8 + tig * 2;
            *reinterpret_cast<float2*>(ob + row * G_ + col) =
                make_float2(acc[mi][ni][0], acc[mi][ni][1]);
            *reinterpret_cast<float2*>(ob + (row + 8) * G_ + col) =
                make_float2(acc[mi][ni][2], acc[mi][ni][3]);
        }
    }
}

// -------- SIMT segment accumulate (decoder only, BT=16) -------------------
template<int BT>
__device__ __forceinline__ void seg_accum(
    float (*a_s)[BT + 4], float (*w_s)[33],
    const float* __restrict__ xp, int xs, int use_ldcg,
    const float* __restrict__ wp, int ws, int K,
    int b0, int j0, u64 acc2[BT / 16][4])
{
    const int tid = threadIdx.x, tx = tid & 31, ty = tid >> 5;
    constexpr int P = BT / 16;
    for (int k0 = 0; k0 < K; k0 += 32) {
        __syncthreads();
        #pragma unroll
        for (int i = 0; i < (BT * 32) / 256; ++i) {
            int e = tid + i * 256;
            int r = e >> 5, kk = e & 31, kg = k0 + kk;
            float v = 0.f;
            if (kg < K) {
                const float* p = xp + (long)(b0 + r) * xs + kg;
                v = use_ldcg ? __ldcg(p) : __ldg(p);
            }
            a_s[kk][r] = v;
        }
        #pragma unroll
        for (int i = 0; i < 16; ++i) {
            int e = tid + i * 256;
            int c = e >> 5, kk = e & 31, kg = k0 + kk;
            float v = 0.f;
            if (kg < K) {
                int gc = j0 + (c >> 5) * 512 + (c & 31);
                v = __ldg(wp + (long)gc * ws + kg);
            }
            w_s[c][kk] = v;
        }
        __syncthreads();
        #pragma unroll
        for (int kk = 0; kk < 32; ++kk) {
            u64 av[P];
            #pragma unroll
            for (int p = 0; p < P; ++p)
                av[p] = *reinterpret_cast<const u64*>(&a_s[kk][ty * (2 * P) + 2 * p]);
            #pragma unroll
            for (int gi = 0; gi < 4; ++gi) {
                u64 wv2 = bcast2(w_s[gi * 32 + tx][kk]);
                #pragma unroll
                for (int p = 0; p < P; ++p)
                    ffma2(acc2[p][gi], av[p], wv2);
            }
        }
    }
}

// ---------------- bridge: elu(h/c_flat @ Wbᵀ + bb) -> decoder init ---------
__global__ __launch_bounds__(256) void bridge_kernel(
    const float* __restrict__ wb, const float* __restrict__ bb)
{
    __shared__ float in_s[32][33], w_s2[32][33];
    const int tid = threadIdx.x, tx = tid & 31, ty = tid >> 5;
    const int b0 = blockIdx.x * 32, m0 = blockIdx.y * 32, z = blockIdx.z;
    const float* srcs[4];
    if (z == 0) {
        srcs[0] = &g_h0fin[0][0][0]; srcs[1] = &g_h0fin[1][0][0];
        srcs[2] = &g_h1fin[0][0][0]; srcs[3] = &g_h1fin[1][0][0];
    } else {
        srcs[0] = &g_c[0][0][0][0]; srcs[1] = &g_c[0][1][0][0];
        srcs[2] = &g_c[1][0][0][0]; srcs[3] = &g_c[1][1][0][0];
    }
    float acc[4] = {0.f, 0.f, 0.f, 0.f};
    for (int k0 = 0; k0 < 2048; k0 += 32) {
        __syncthreads();
        const float* src = srcs[k0 >> 9];
        const int kl = k0 & 511;
        #pragma unroll
        for (int i = 0; i < 4; ++i) {
            int e = tid + i * 256;
            int r = e >> 5, kk = e & 31;
            in_s[r][kk] = src[(long)(b0 + r) * H_ + kl + kk];
            w_s2[r][kk] = wb[(long)(m0 + r) * 2048 + k0 + kk];
        }
        __syncthreads();
        #pragma unroll
        for (int kk = 0; kk < 32; ++kk) {
            float wv = w_s2[tx][kk];
            #pragma unroll
            for (int bi = 0; bi < 4; ++bi)
                acc[bi] = fmaf(in_s[ty * 4 + bi][kk], wv, acc[bi]);
        }
    }
    const int m = m0 + tx;
    #pragma unroll
    for (int bi = 0; bi < 4; ++bi) {
        int b = b0 + ty * 4 + bi;
        float v = acc[bi] + bb[m];
        v = (v > 0.f) ? v : expm1f(v);
        if (z == 0) {
            if (m < 512) g_dec_h0[0][b][m] = v; else g_dec_h1[0][b][m - 512] = v;
        } else {
            if (m < 512) g_dec_c0[b][m] = v;    else g_dec_c1[b][m - 512] = v;
        }
    }
}

// ---------------- decoder: persistent, 64 steps ----------------------------
__global__ __launch_bounds__(256, 1) void dec_persist(
    const float* __restrict__ X, const float* __restrict__ fut,
    const float* __restrict__ dwih0, const float* __restrict__ dwhh0,
    const float* __restrict__ db0,
    const float* __restrict__ dwih1, const float* __restrict__ dwhh1,
    const float* __restrict__ db1,
    const float* __restrict__ wo, const float* __restrict__ bo,
    float* __restrict__ out)
{
    __shared__ __align__(16) float a_s[32][20];
    __shared__ __align__(16) float w_s[128][33];
    __shared__ float red[8][MQ_];
    const int bid = blockIdx.x, tid = threadIdx.x;
    const int tx = tid & 31, ty = tid >> 5;
    const int b0 = (bid >> 4) * 16, j0 = (bid & 15) * 32;
    const int j = j0 + tx;

    if (tid < DIN_)
        g_decx[bid][tid] = (tid == 0)
            ? __ldg(X + (long)bid * T_ * DIN_ + (T_ - 1) * DIN_)
            : __ldg(fut + (long)bid * HOR_ * DFF_ + (tid - 1));

    const float b0I = __ldg(db0 + j),        b0F = __ldg(db0 + 512 + j),
                b0G = __ldg(db0 + 1024 + j), b0O = __ldg(db0 + 1536 + j);
    const float b1I = __ldg(db1 + j),        b1F = __ldg(db1 + 512 + j),
                b1G = __ldg(db1 + 1024 + j), b1O = __ldg(db1 + 1536 + j);
    float c0[2], c1[2];
    #pragma unroll
    for (int bi = 0; bi < 2; ++bi) {
        c0[bi] = g_dec_c0[b0 + ty * 2 + bi][j];
        c1[bi] = g_dec_c1[b0 + ty * 2 + bi][j];
    }
    grid_barrier();

    for (int s = 0; s < HOR_; ++s) {
        {
            u64 acc2[1][4] = {};
            seg_accum<16>(a_s, w_s, &g_decx[0][0], DIN_, 1, dwih0, DIN_, DIN_, b0, j0, acc2);
            seg_accum<16>(a_s, w_s, &g_dec_h0[s & 1][0][0], H_, 1, dwhh0, H_, H_, b0, j0, acc2);
            float acc[2][4];
            #pragma unroll
            for (int gi = 0; gi < 4; ++gi)
                unpack2(acc2[0][gi], acc[0][gi], acc[1][gi]);
            #pragma unroll
            for (int bi = 0; bi < 2; ++bi) {
                float i_ = sigm_(acc[bi][0] + b0I);
                float f_ = sigm_(acc[bi][1] + b0F);
                float g_ = tanh_(acc[bi][2] + b0G);
                float o_ = sigm_(acc[bi][3] + b0O);
                float c  = f_ * c0[bi] + i_ * g_;
                c0[bi] = c;
                g_dec_h0[(s + 1) & 1][b0 + ty * 2 + bi][j] = o_ * tanh_(c);
            }
        }
        grid_barrier();
        {
            u64 acc2[1][4] = {};
            seg_accum<16>(a_s, w_s, &g_dec_h0[(s + 1) & 1][0][0], H_, 1, dwih1, H_, H_, b0, j0, acc2);
            seg_accum<16>(a_s, w_s, &g_dec_h1[s & 1][0][0],       H_, 1, dwhh1, H_, H_, b0, j0, acc2);
            float acc[2][4];
            #pragma unroll
            for (int gi = 0; gi < 4; ++gi)
                unpack2(acc2[0][gi], acc[0][gi], acc[1][gi]);
            #pragma unroll
            for (int bi = 0; bi < 2; ++bi) {
                float i_ = sigm_(acc[bi][0] + b1I);
                float f_ = sigm_(acc[bi][1] + b1F);
                float g_ = tanh_(acc[bi][2] + b1G);
                float o_ = sigm_(acc[bi][3] + b1O);
                float c  = f_ * c1[bi] + i_ * g_;
                c1[bi] = c;
                g_dec_h1[(s + 1) & 1][b0 + ty * 2 + bi][j] = o_ * tanh_(c);
            }
        }
        grid_barrier();
        {
            const float* h1 = &g_dec_h1[(s + 1) & 1][bid][0];
            float part[MQ_] = {0.f, 0.f, 0.f, 0.f, 0.f};
            for (int k = tid; k < H_; k += 256) {
                float hv = __ldcg(h1 + k);
                #pragma unroll
                for (int q = 0; q < MQ_; ++q)
                    part[q] = fmaf(hv, __ldg(wo + q * H_ + k), part[q]);
            }
            #pragma unroll
            for (int o = 16; o; o >>= 1)
                #pragma unroll
                for (int q = 0; q < MQ_; ++q)
                    part[q] += __shfl_down_sync(0xffffffffu, part[q], o);
            if ((tid & 31) == 0)
                #pragma unroll
                for (int q = 0; q < MQ_; ++q) red[tid >> 5][q] = part[q];
            __syncthreads();
            if (tid < MQ_) {
                float v = __ldg(bo + tid);
                #pragma unroll
                for (int w2 = 0; w2 < 8; ++w2) v += red[w2][tid];
                out[(long)bid * HOR_ * MQ_ + s * MQ_ + tid] = v;
                if (tid == 0) g_decx[bid][0] = v;
            }
            if (s + 1 < HOR_ && tid >= 32 && tid < 32 + DFF_)
                g_decx[bid][tid - 31] =
                    __ldg(fut + (long)bid * HOR_ * DFF_ + (s + 1) * DFF_ + (tid - 32));
        }
        grid_barrier();
    }
}

// ---------------- launcher (7 graph nodes) ----------------
extern "C" void kernel_launch(void* const* d_in, const int* in_sizes, int n_in,
                              void* d_out, int out_size)
{
    int off = (n_in >= 4 && in_sizes[3] == 1) ? 0 : -1;
    const float* X     = (const float*)d_in[0];
    const float* fut   = (const float*)d_in[1];
    const float* ewih0 = (const float*)d_in[4 + off];
    const float* ewhh0 = (const float*)d_in[5 + off];
    const float* eb0   = (const float*)d_in[6 + off];
    const float* ewih1 = (const float*)d_in[7 + off];
    const float* ewhh1 = (const float*)d_in[8 + off];
    const float* eb1   = (const float*)d_in[9 + off];
    const float* dwih0 = (const float*)d_in[10 + off];
    const float* dwhh0 = (const float*)d_in[11 + off];
    const float* db0   = (const float*)d_in[12 + off];
    const float* dwih1 = (const float*)d_in[13 + off];
    const float* dwhh1 = (const float*)d_in[14 + off];
    const float* db1   = (const float*)d_in[15 + off];
    const float* wb    = (const float*)d_in[16 + off];
    const float* bb    = (const float*)d_in[17 + off];
    const float* wo    = (const float*)d_in[18 + off];
    const float* bo    = (const float*)d_in[19 + off];
    float* out = (float*)d_out;

    cudaFuncSetAttribute(enc_mma_persist<0>,
                         cudaFuncAttributeMaxDynamicSharedMemorySize, ENC_SMEM);
    cudaFuncSetAttribute(enc_mma_persist<1>,
                         cudaFuncAttributeMaxDynamicSharedMemorySize, ENC_SMEM);

    gates0_gemm<<<dim3(T_, 2), 256>>>(X, ewih0);
    convB_kernel<<<2048, 256>>>(ewih1);
    enc_mma_persist<0><<<NBLK, 256, ENC_SMEM>>>(ewhh0, eb0);
    gates1_mma<<<dim3(16, 512, 2), 256>>>();
    enc_mma_persist<1><<<NBLK, 256, ENC_SMEM>>>(ewhh1, eb1);
    bridge_kernel<<<dim3(4, 32, 2), 256>>>(wb, bb);
    dec_persist<<<NBLK, 256>>>(X, fut, dwih0, dwhh0, db0,
                               dwih1, dwhh1, db1, wo, bo, out);
}

// round 13
// speedup vs baseline: 1.5491x; 1.0344x over previous
#include <cuda_runtime.h>
#include <cuda_bf16.h>
#include <math.h>
#include <stdint.h>

#define B_   128
#define T_   512
#define H_   512
#define G_   2048
#define DIN_ 8
#define HOR_ 64
#define MQ_  5
#define DFF_ 7
#define NBLK 128

typedef unsigned long long u64;

// ---------------- scratch (device globals; no allocations) ----------------
__device__ float g_gates0[2][T_][B_][G_];    // precomputed layer-0 input gates
__device__ float g_gates1[2][T_][B_][G_];    // precomputed layer-1 input gates
__device__ float g_c[2][2][B_][H_];          // final cell states [layer][dir]
__device__ float g_h0fin[2][B_][H_];         // layer-0 final h per dir (fp32)
__device__ float g_h1fin[2][B_][H_];         // layer-1 final h per dir (fp32)
__device__ float g_dec_h0[2][B_][H_];
__device__ float g_dec_c0[B_][H_];
__device__ float g_dec_h1[2][B_][H_];
__device__ float g_dec_c1[B_][H_];
__device__ float g_decx[B_][DIN_];           // decoder input vector [y_fb, fut]
__device__ unsigned g_bar_cnt;
__device__ unsigned g_bar_gen;

// bf16 hi/lo split activations (enc-L0 h sequence; also gates1_mma's A input)
__device__ __nv_bfloat16 g_Ah[T_ * B_][1024];
__device__ __nv_bfloat16 g_Al[T_ * B_][1024];
// layer-1 h ping-pong, bf16 hi/lo
__device__ __nv_bfloat16 g_h1h[2][2][B_][H_];
__device__ __nv_bfloat16 g_h1l[2][2][B_][H_];
// gates1 weights, bf16 hi/lo
__device__ __nv_bfloat16 g_Bh[2][G_][1024];
__device__ __nv_bfloat16 g_Bl[2][G_][1024];

// ---------------- software grid barrier (R8 mechanism, verbatim) ----------
__device__ __forceinline__ void grid_barrier()
{
    __syncthreads();
    if (threadIdx.x == 0) {
        volatile unsigned* genp = &g_bar_gen;
        unsigned gen = *genp;
        __threadfence();
        if (atomicAdd(&g_bar_cnt, 1u) == NBLK - 1u) {
            g_bar_cnt = 0u;
            __threadfence();
            *genp = gen + 1u;
        } else {
            while (*genp == gen) { }
        }
        __threadfence();
    }
    __syncthreads();
}

// ---------------- packed fp32x2 helpers (decoder SIMT path) ----------------
__device__ __forceinline__ void ffma2(u64& d, u64 a, u64 b) {
    asm("fma.rn.f32x2 %0, %1, %2, %0;" : "+l"(d) : "l"(a), "l"(b));
}
__device__ __forceinline__ u64 bcast2(float v) {
    u64 r;
    asm("mov.b64 %0, {%1, %1};" : "=l"(r) : "f"(v));
    return r;
}
__device__ __forceinline__ void unpack2(u64 v, float& lo, float& hi) {
    asm("mov.b64 {%0, %1}, %2;" : "=f"(lo), "=f"(hi) : "l"(v));
}

// ---------------- fast transcendentals ----------------
__device__ __forceinline__ float sigm_(float x) {
    return __fdividef(1.f, 1.f + __expf(-x));
}
__device__ __forceinline__ float tanh_(float x) {
    return __fdividef(2.f, 1.f + __expf(-2.f * x)) - 1.f;
}

// ---------------- mma.sync / ldmatrix helpers ----------------
__device__ __forceinline__ uint32_t smem_u32(const void* p) {
    uint32_t a;
    asm("{ .reg .u64 t; cvta.to.shared.u64 t, %1; cvt.u32.u64 %0, t; }"
        : "=r"(a) : "l"(p));
    return a;
}
__device__ __forceinline__ void ldsm4(uint32_t a, uint32_t& r0, uint32_t& r1,
                                      uint32_t& r2, uint32_t& r3) {
    asm volatile("ldmatrix.sync.aligned.m8n8.x4.shared.b16 {%0,%1,%2,%3}, [%4];"
                 : "=r"(r0), "=r"(r1), "=r"(r2), "=r"(r3) : "r"(a));
}
__device__ __forceinline__ void ldsm2(uint32_t a, uint32_t& r0, uint32_t& r1) {
    asm volatile("ldmatrix.sync.aligned.m8n8.x2.shared.b16 {%0,%1}, [%2];"
                 : "=r"(r0), "=r"(r1) : "r"(a));
}
__device__ __forceinline__ void mma_bf16(float* c, const uint32_t* a, const uint32_t* b) {
    asm volatile(
        "mma.sync.aligned.m16n8k16.row.col.f32.bf16.bf16.f32 "
        "{%0,%1,%2,%3}, {%4,%5,%6,%7}, {%8,%9}, {%0,%1,%2,%3};"
        : "+f"(c[0]), "+f"(c[1]), "+f"(c[2]), "+f"(c[3])
        : "r"(a[0]), "r"(a[1]), "r"(a[2]), "r"(a[3]), "r"(b[0]), "r"(b[1]));
}

// ---------------- layer-0 input gates: one-shot tiny-K GEMM ----------------
__global__ __launch_bounds__(256) void gates0_gemm(
    const float* __restrict__ X, const float* __restrict__ w_ih)
{
    __shared__ float xs_[B_][DIN_];
    const int t = blockIdx.x, dir = blockIdx.y;
    const int tid = threadIdx.x;
    for (int e = tid; e < B_ * DIN_; e += 256) {
        int b = e >> 3, k = e & 7;
        xs_[b][k] = __ldg(X + ((long)b * T_ + t) * DIN_ + k);
    }
    __syncthreads();
    const float* w = w_ih + (long)dir * G_ * DIN_;
    for (int g = tid; g < G_; g += 256) {
        float4 w0 = *reinterpret_cast<const float4*>(w + g * DIN_);
        float4 w1 = *reinterpret_cast<const float4*>(w + g * DIN_ + 4);
        float* op = &g_gates0[dir][t][0][0];
        for (int b = 0; b < B_; ++b) {
            const float* xb = xs_[b];
            float acc = xb[0] * w0.x + xb[1] * w0.y + xb[2] * w0.z + xb[3] * w0.w
                      + xb[4] * w1.x + xb[5] * w1.y + xb[6] * w1.z + xb[7] * w1.w;
            op[(long)b * G_ + g] = acc;
        }
    }
}

// -------- fp32 -> bf16 hi/lo conversion for gates1 weights ----------------
__global__ __launch_bounds__(256) void convB_kernel(const float* __restrict__ w_ih1)
{
    const long npairs = (long)2 * G_ * 512;
    __nv_bfloat16* bh = &g_Bh[0][0][0];
    __nv_bfloat16* bl = &g_Bl[0][0][0];
    for (long p = (long)blockIdx.x * 256 + threadIdx.x; p < npairs;
         p += (long)gridDim.x * 256) {
        float2 v = *reinterpret_cast<const float2*>(w_ih1 + p * 2);
        __nv_bfloat16 h0 = __float2bfloat16(v.x);
        __nv_bfloat16 l0 = __float2bfloat16(v.x - __bfloat162float(h0));
        __nv_bfloat16 h1 = __float2bfloat16(v.y);
        __nv_bfloat16 l1 = __float2bfloat16(v.y - __bfloat162float(h1));
        *reinterpret_cast<__nv_bfloat162*>(bh + p * 2) = __nv_bfloat162(h0, h1);
        *reinterpret_cast<__nv_bfloat162*>(bl + p * 2) = __nv_bfloat162(l0, l1);
    }
}

// =========== persistent mma-based encoder layer (layer = 0 or 1) ==========
// Block = 64 batch x 64 gate-cols (16 j x 4 gate types), K=512/step.
// W_hh hi/lo resident in SMEM all 512 steps; A (=h) streamed per step in
// 8 double-buffered k-chunks of 64. 8 warps = 4M x 2N (warp: 16 x 32).
#define ESM_W_H 0
#define ESM_W_L 66560
#define ESM_A   133120
#define ESM_AB  9216
#define ESM_C   169984
#define ENC_SMEM 187392

template<int LAYER>
__global__ __launch_bounds__(256, 1) void enc_mma_persist(
    const float* __restrict__ w_hh, const float* __restrict__ bias)
{
    extern __shared__ __align__(16) char esm[];
    __nv_bfloat16* Wh = reinterpret_cast<__nv_bfloat16*>(esm + ESM_W_H);
    __nv_bfloat16* Wl = reinterpret_cast<__nv_bfloat16*>(esm + ESM_W_L);
    float* Cb = reinterpret_cast<float*>(esm + ESM_C);

    const int tid = threadIdx.x, lane = tid & 31, wid = tid >> 5;
    const int warp_m = wid & 3, warp_n = wid >> 2;
    const int bid = blockIdx.x;
    const int dir = bid >> 6, rr = bid & 63;
    const int b0 = (rr >> 5) * 64, j0 = (rr & 31) * 16;

    // ---- one-time W_hh load + hi/lo split into resident smem ----
    const float* wsrc = w_hh + (long)dir * G_ * H_;
    for (int idx = tid; idx < 64 * 512; idx += 256) {
        int n = idx >> 9, k = idx & 511;
        int gc = (n >> 4) * 512 + j0 + (n & 15);
        float v = __ldg(wsrc + (long)gc * H_ + k);
        __nv_bfloat16 h = __float2bfloat16(v);
        Wh[n * 520 + k] = h;
        Wl[n * 520 + k] = __float2bfloat16(v - __bfloat162float(h));
    }

    // ---- per-thread pointwise cell mapping: (pb batch-local, jq j-quad) ----
    const int pb = tid >> 2, jq = tid & 3;
    const float* bp = bias + dir * G_ + j0 + jq * 4;
    float4 bI = __ldg((const float4*)(bp));
    float4 bF = __ldg((const float4*)(bp + 512));
    float4 bG = __ldg((const float4*)(bp + 1024));
    float4 bO = __ldg((const float4*)(bp + 1536));
    float cst[4] = {0.f, 0.f, 0.f, 0.f};

    // ---- ldmatrix lane offsets ----
    uint32_t WhB = smem_u32(Wh), WlB = smem_u32(Wl);
    const uint32_t aRow = (uint32_t)((warp_m * 16 + (lane & 15)) * 144
                                     + (lane >> 4) * 16);
    uint32_t bRow[4];
    #pragma unroll
    for (int ni = 0; ni < 4; ++ni)
        bRow[ni] = (uint32_t)((warp_n * 32 + ni * 8 + (lane & 7)) * 1040
                              + ((lane >> 3) & 1) * 16);

    const float* gatesrc = (LAYER == 0 ? &g_gates0[0][0][0][0]
                                       : &g_gates1[0][0][0][0])
                         + (long)dir * T_ * B_ * G_;
    __syncthreads();

    for (int s = 0; s < T_; ++s) {
        const int t = dir ? (T_ - 1 - s) : s;
        // prefetch gate-init (hidden behind the MMA work)
        const float* gp = gatesrc + ((long)t * B_ + b0 + pb) * G_ + j0 + jq * 4;
        float4 gI = __ldg((const float4*)(gp));
        float4 gF = __ldg((const float4*)(gp + 512));
        float4 gG = __ldg((const float4*)(gp + 1024));
        float4 gO = __ldg((const float4*)(gp + 1536));

        float acc[4][4] = {};
        if (s > 0) {
            const __nv_bfloat16 *pAh, *pAl;
            long apitch;
            if (LAYER == 0) {
                const int tp = dir ? t + 1 : t - 1;
                pAh = &g_Ah[tp * 128 + b0][dir * 512];
                pAl = &g_Al[tp * 128 + b0][dir * 512];
                apitch = 1024;
            } else {
                pAh = &g_h1h[s & 1][dir][b0][0];
                pAl = &g_h1l[s & 1][dir][b0][0];
                apitch = 512;
            }
            uint4 stg[4];
            auto stage = [&](int kc) {
                #pragma unroll
                for (int i = 0; i < 4; ++i) {
                    int idx = tid + i * 256;
                    int term = idx >> 9, rem = idx & 511;
                    int row = rem >> 3, c8 = rem & 7;
                    const __nv_bfloat16* src =
                        (term ? pAl : pAh) + (long)row * apitch + kc * 64 + c8 * 8;
                    stg[i] = __ldcg(reinterpret_cast<const uint4*>(src));
                }
            };
            auto commitA = [&](int buf) {
                #pragma unroll
                for (int i = 0; i < 4; ++i) {
                    int idx = tid + i * 256;
                    int term = idx >> 9, rem = idx & 511;
                    int row = rem >> 3, c8 = rem & 7;
                    *reinterpret_cast<uint4*>(
                        esm + ESM_A + (buf * 2 + term) * ESM_AB + row * 144 + c8 * 16)
                        = stg[i];
                }
            };
            stage(0);
            commitA(0);
            __syncthreads();
            #pragma unroll 1
            for (int kc = 0; kc < 8; ++kc) {
                const int buf = kc & 1;
                if (kc < 7) stage(kc + 1);
                const uint32_t AhB = smem_u32(esm + ESM_A + (buf * 2) * ESM_AB);
                const uint32_t AlB = AhB + ESM_AB;
                #pragma unroll
                for (int ks = 0; ks < 4; ++ks) {
                    uint32_t ah[4], al[4], bh[4][2], bl[4][2];
                    ldsm4(AhB + aRow + ks * 32, ah[0], ah[1], ah[2], ah[3]);
                    ldsm4(AlB + aRow + ks * 32, al[0], al[1], al[2], al[3]);
                    #pragma unroll
                    for (int ni = 0; ni < 4; ++ni) {
                        ldsm2(WhB + bRow[ni] + kc * 128 + ks * 32, bh[ni][0], bh[ni][1]);
                        ldsm2(WlB + bRow[ni] + kc * 128 + ks * 32, bl[ni][0], bl[ni][1]);
                    }
                    #pragma unroll
                    for (int ni = 0; ni < 4; ++ni) {
                        mma_bf16(acc[ni], ah, bh[ni]);
                        mma_bf16(acc[ni], ah, bl[ni]);
                        mma_bf16(acc[ni], al, bh[ni]);
                    }
                }
                if (kc < 7) commitA(buf ^ 1);
                __syncthreads();
            }
        }
        // ---- epilogue: dump acc frags to Cbuf (64 x 64, pitch 68) ----
        {
            const int row = warp_m * 16 + (lane >> 2);
            #pragma unroll
            for (int ni = 0; ni < 4; ++ni) {
                const int col = warp_n * 32 + ni * 8 + (lane & 3) * 2;
                *reinterpret_cast<float2*>(&Cb[row * 68 + col]) =
                    make_float2(acc[ni][0], acc[ni][1]);
                *reinterpret_cast<float2*>(&Cb[(row + 8) * 68 + col]) =
                    make_float2(acc[ni][2], acc[ni][3]);
            }
        }
        __syncthreads();
        // ---- pointwise LSTM cell + h split/write ----
        {
            __align__(8) __nv_bfloat16 hh[4], hl[4];
            float hv[4];
            const float* gIv = (const float*)&gI;
            const float* gFv = (const float*)&gF;
            const float* gGv = (const float*)&gG;
            const float* gOv = (const float*)&gO;
            const float* bIv = (const float*)&bI;
            const float* bFv = (const float*)&bF;
            const float* bGv = (const float*)&bG;
            const float* bOv = (const float*)&bO;
            #pragma unroll
            for (int q = 0; q < 4; ++q) {
                const int jl = jq * 4 + q;
                float iv = Cb[pb * 68 + jl]      + gIv[q] + bIv[q];
                float fv = Cb[pb * 68 + 16 + jl] + gFv[q] + bFv[q];
                float gv = Cb[pb * 68 + 32 + jl] + gGv[q] + bGv[q];
                float ov = Cb[pb * 68 + 48 + jl] + gOv[q] + bOv[q];
                float i_ = sigm_(iv), f_ = sigm_(fv), g_ = tanh_(gv), o_ = sigm_(ov);
                float c = f_ * cst[q] + i_ * g_;
                cst[q] = c;
                float h = o_ * tanh_(c);
                hv[q] = h;
                hh[q] = __float2bfloat16(h);
                hl[q] = __float2bfloat16(h - __bfloat162float(hh[q]));
            }
            if (LAYER == 0) {
                *reinterpret_cast<uint2*>(&g_Ah[t * 128 + b0 + pb][dir * 512 + j0 + jq * 4])
                    = *reinterpret_cast<uint2*>(hh);
                *reinterpret_cast<uint2*>(&g_Al[t * 128 + b0 + pb][dir * 512 + j0 + jq * 4])
                    = *reinterpret_cast<uint2*>(hl);
                if (s == T_ - 1)
                    *reinterpret_cast<float4*>(&g_h0fin[dir][b0 + pb][j0 + jq * 4]) =
                        make_float4(hv[0], hv[1], hv[2], hv[3]);
            } else {
                *reinterpret_cast<uint2*>(&g_h1h[(s + 1) & 1][dir][b0 + pb][j0 + jq * 4])
                    = *reinterpret_cast<uint2*>(hh);
                *reinterpret_cast<uint2*>(&g_h1l[(s + 1) & 1][dir][b0 + pb][j0 + jq * 4])
                    = *reinterpret_cast<uint2*>(hl);
                if (s == T_ - 1)
                    *reinterpret_cast<float4*>(&g_h1fin[dir][b0 + pb][j0 + jq * 4]) =
                        make_float4(hv[0], hv[1], hv[2], hv[3]);
            }
        }
        grid_barrier();
    }
    #pragma unroll
    for (int q = 0; q < 4; ++q)
        g_c[LAYER][dir][b0 + pb][j0 + jq * 4 + q] = cst[q];
}

// ======== gates1 via mma.sync bf16: D[128,128] = A[128,1024] @ W^T =========
#define PITCH 40

__global__ __launch_bounds__(256) void gates1_mma()
{
    __shared__ __align__(16) __nv_bfloat16 smem4[4][128 * PITCH];
    const int tid = threadIdx.x;
    const int wid = tid >> 5, lane = tid & 31;
    const int n0 = blockIdx.x * 128, r0 = blockIdx.y * 128, dir = blockIdx.z;
    const int warp_m = wid & 1, warp_n = wid >> 1;

    const __nv_bfloat16* srcs[4] = {
        &g_Ah[r0][0], &g_Al[r0][0], &g_Bh[dir][n0][0], &g_Bl[dir][n0][0] };
    uint32_t sb[4] = { smem_u32(smem4[0]), smem_u32(smem4[1]),
                       smem_u32(smem4[2]), smem_u32(smem4[3]) };

    uint32_t aOff[4], bOff[4];
    #pragma unroll
    for (int mi = 0; mi < 4; ++mi)
        aOff[mi] = (uint32_t)((warp_m * 64 + mi * 16 + (lane & 15)) * (PITCH * 2)
                              + (lane >> 4) * 16);
    #pragma unroll
    for (int ni = 0; ni < 4; ++ni)
        bOff[ni] = (uint32_t)((warp_n * 32 + ni * 8 + (lane & 7)) * (PITCH * 2)
                              + ((lane >> 3) & 1) * 16);

    uint2 stg[16];
    auto stage = [&](int kbase) {
        #pragma unroll
        for (int i = 0; i < 16; ++i) {
            int idx = i * 256 + tid;
            int tI = idx >> 10, row = (idx >> 3) & 127, c = idx & 7;
            stg[i] = *reinterpret_cast<const uint2*>(
                srcs[tI] + (long)row * 1024 + kbase + c * 4);
        }
    };
    auto commit = [&]() {
        #pragma unroll
        for (int i = 0; i < 16; ++i) {
            int idx = i * 256 + tid;
            int tI = idx >> 10, row = (idx >> 3) & 127, c = idx & 7;
            *reinterpret_cast<uint2*>(&smem4[tI][row * PITCH + c * 4]) = stg[i];
        }
    };

    float acc[4][4][4];
    #pragma unroll
    for (int mi = 0; mi < 4; ++mi)
        #pragma unroll
        for (int ni = 0; ni < 4; ++ni)
            #pragma unroll
            for (int q = 0; q < 4; ++q) acc[mi][ni][q] = 0.f;

    stage(0);
    commit();
    __syncthreads();
    #pragma unroll 1
    for (int kc = 0; kc < 32; ++kc) {
        if (kc < 31) stage((kc + 1) * 32);
        #pragma unroll
        for (int ks = 0; ks < 2; ++ks) {
            const uint32_t kb = ks * 32;
            uint32_t ah[4][4], al[4][4], bh[4][2], bl[4][2];
            #pragma unroll
            for (int mi = 0; mi < 4; ++mi) {
                ldsm4(sb[0] + aOff[mi] + kb, ah[mi][0], ah[mi][1], ah[mi][2], ah[mi][3]);
                ldsm4(sb[1] + aOff[mi] + kb, al[mi][0], al[mi][1], al[mi][2], al[mi][3]);
            }
            #pragma unroll
            for (int ni = 0; ni < 4; ++ni) {
                ldsm2(sb[2] + bOff[ni] + kb, bh[ni][0], bh[ni][1]);
                ldsm2(sb[3] + bOff[ni] + kb, bl[ni][0], bl[ni][1]);
            }
            #pragma unroll
            for (int mi = 0; mi < 4; ++mi)
                #pragma unroll
                for (int ni = 0; ni < 4; ++ni) {
                    mma_bf16(acc[mi][ni], ah[mi], bh[ni]);
                    mma_bf16(acc[mi][ni], ah[mi], bl[ni]);
                    mma_bf16(acc[mi][ni], al[mi], bh[ni]);
                }
        }
        __syncthreads();
        if (kc < 31) { commit(); __syncthreads(); }
    }

    float* ob = &g_gates1[dir][0][0][0];
    const int group = lane >> 2, tig = lane & 3;
    #pragma unroll
    for (int mi = 0; mi < 4; ++mi) {
        const long row = r0 + warp_m * 64 + mi * 16 + group;
        #pragma unroll
        for (int ni = 0; ni < 4; ++ni) {
            const int col = n0 + warp_n * 32 + ni * 8 + tig * 2;
            *reinterpret_cast<float2*>(ob + row * G_ + col) =
                make_float2(acc[mi][ni][0], acc[mi][ni][1]);
            *reinterpret_cast<float2*>(ob + (row + 8) * G_ + col) =
                make_float2(acc[mi][ni][2], acc[mi][ni][3]);
        }
    }
}

// -------- SIMT segment accumulate, unpipelined (decoder K=8 seg only) -----
template<int BT>
__device__ __forceinline__ void seg_accum(
    float (*a_s)[BT + 4], float (*w_s)[33],
    const float* __restrict__ xp, int xs, int use_ldcg,
    const float* __restrict__ wp, int ws, int K,
    int b0, int j0, u64 acc2[BT / 16][4])
{
    const int tid = threadIdx.x, tx = tid & 31, ty = tid >> 5;
    constexpr int P = BT / 16;
    for (int k0 = 0; k0 < K; k0 += 32) {
        __syncthreads();
        #pragma unroll
        for (int i = 0; i < (BT * 32) / 256; ++i) {
            int e = tid + i * 256;
            int r = e >> 5, kk = e & 31, kg = k0 + kk;
            float v = 0.f;
            if (kg < K) {
                const float* p = xp + (long)(b0 + r) * xs + kg;
                v = use_ldcg ? __ldcg(p) : __ldg(p);
            }
            a_s[kk][r] = v;
        }
        #pragma unroll
        for (int i = 0; i < 16; ++i) {
            int e = tid + i * 256;
            int c = e >> 5, kk = e & 31, kg = k0 + kk;
            float v = 0.f;
            if (kg < K) {
                int gc = j0 + (c >> 5) * 512 + (c & 31);
                v = __ldg(wp + (long)gc * ws + kg);
            }
            w_s[c][kk] = v;
        }
        __syncthreads();
        #pragma unroll
        for (int kk = 0; kk < 32; ++kk) {
            u64 av[P];
            #pragma unroll
            for (int p = 0; p < P; ++p)
                av[p] = *reinterpret_cast<const u64*>(&a_s[kk][ty * (2 * P) + 2 * p]);
            #pragma unroll
            for (int gi = 0; gi < 4; ++gi) {
                u64 wv2 = bcast2(w_s[gi * 32 + tx][kk]);
                #pragma unroll
                for (int p = 0; p < P; ++p)
                    ffma2(acc2[p][gi], av[p], wv2);
            }
        }
    }
}

// -------- pipelined K=512 segment (decoder, BT=16) ------------------------
// Double-buffered register-staged: stage(kt+1) issued before compute(kt).
// Thread (tx,ty) owns batches {2ty, 2ty+1}, gate cols {j0 + gi*512 + tx}.
__device__ __forceinline__ void seg16_pipe(
    float (*a_s)[32][20], float (*w_s)[128][33],
    const float* __restrict__ xp, int xs,
    const float* __restrict__ wp, int ws,
    int b0, int j0, u64 acc2[1][4])
{
    const int tid = threadIdx.x, tx = tid & 31, ty = tid >> 5;
    int aofs[2], gcofs[16];
    #pragma unroll
    for (int i = 0; i < 2; ++i) {
        int e = tid + i * 256;
        aofs[i] = (b0 + (e >> 5)) * xs + (e & 31);
    }
    #pragma unroll
    for (int i = 0; i < 16; ++i) {
        int c = ty + 8 * i;
        gcofs[i] = (j0 + (c >> 5) * 512 + (c & 31)) * ws + tx;
    }
    float ar[2], wr[16];
    auto stage = [&](int kt) {
        const int ko = kt * 32;
        ar[0] = __ldcg(xp + aofs[0] + ko);
        ar[1] = __ldcg(xp + aofs[1] + ko);
        #pragma unroll
        for (int i = 0; i < 16; ++i)
            wr[i] = __ldg(wp + gcofs[i] + ko);
    };
    auto commit = [&](int buf) {
        #pragma unroll
        for (int i = 0; i < 2; ++i) {
            int e = tid + i * 256;
            a_s[buf][e & 31][e >> 5] = ar[i];
        }
        #pragma unroll
        for (int i = 0; i < 16; ++i)
            w_s[buf][ty + 8 * i][tx] = wr[i];
    };
    __syncthreads();              // protect buffers still being read by caller
    stage(0);
    commit(0);
    __syncthreads();
    #pragma unroll 1
    for (int kt = 0; kt < 16; ++kt) {
        const int buf = kt & 1;
        if (kt < 15) stage(kt + 1);
        #pragma unroll
        for (int kk = 0; kk < 32; ++kk) {
            u64 av = *reinterpret_cast<const u64*>(&a_s[buf][kk][2 * ty]);
            #pragma unroll
            for (int gi = 0; gi < 4; ++gi) {
                u64 w2 = bcast2(w_s[buf][gi * 32 + tx][kk]);
                ffma2(acc2[0][gi], av, w2);
            }
        }
        if (kt < 15) commit(buf ^ 1);
        __syncthreads();
    }
}

// ---------------- bridge: elu(h/c_flat @ Wbᵀ + bb) -> decoder init ---------
__global__ __launch_bounds__(256) void bridge_kernel(
    const float* __restrict__ wb, const float* __restrict__ bb)
{
    __shared__ float in_s[32][33], w_s2[32][33];
    const int tid = threadIdx.x, tx = tid & 31, ty = tid >> 5;
    const int b0 = blockIdx.x * 32, m0 = blockIdx.y * 32, z = blockIdx.z;
    const float* srcs[4];
    if (z == 0) {
        srcs[0] = &g_h0fin[0][0][0]; srcs[1] = &g_h0fin[1][0][0];
        srcs[2] = &g_h1fin[0][0][0]; srcs[3] = &g_h1fin[1][0][0];
    } else {
        srcs[0] = &g_c[0][0][0][0]; srcs[1] = &g_c[0][1][0][0];
        srcs[2] = &g_c[1][0][0][0]; srcs[3] = &g_c[1][1][0][0];
    }
    float acc[4] = {0.f, 0.f, 0.f, 0.f};
    for (int k0 = 0; k0 < 2048; k0 += 32) {
        __syncthreads();
        const float* src = srcs[k0 >> 9];
        const int kl = k0 & 511;
        #pragma unroll
        for (int i = 0; i < 4; ++i) {
            int e = tid + i * 256;
            int r = e >> 5, kk = e & 31;
            in_s[r][kk] = src[(long)(b0 + r) * H_ + kl + kk];
            w_s2[r][kk] = wb[(long)(m0 + r) * 2048 + k0 + kk];
        }
        __syncthreads();
        #pragma unroll
        for (int kk = 0; kk < 32; ++kk) {
            float wv = w_s2[tx][kk];
            #pragma unroll
            for (int bi = 0; bi < 4; ++bi)
                acc[bi] = fmaf(in_s[ty * 4 + bi][kk], wv, acc[bi]);
        }
    }
    const int m = m0 + tx;
    #pragma unroll
    for (int bi = 0; bi < 4; ++bi) {
        int b = b0 + ty * 4 + bi;
        float v = acc[bi] + bb[m];
        v = (v > 0.f) ? v : expm1f(v);
        if (z == 0) {
            if (m < 512) g_dec_h0[0][b][m] = v; else g_dec_h1[0][b][m - 512] = v;
        } else {
            if (m < 512) g_dec_c0[b][m] = v;    else g_dec_c1[b][m - 512] = v;
        }
    }
}

// ---------------- decoder: persistent, 64 steps ----------------------------
__global__ __launch_bounds__(256, 1) void dec_persist(
    const float* __restrict__ X, const float* __restrict__ fut,
    const float* __restrict__ dwih0, const float* __restrict__ dwhh0,
    const float* __restrict__ db0,
    const float* __restrict__ dwih1, const float* __restrict__ dwhh1,
    const float* __restrict__ db1,
    const float* __restrict__ wo, const float* __restrict__ bo,
    float* __restrict__ out)
{
    __shared__ __align__(16) float a_s2[2][32][20];
    __shared__ __align__(16) float w_s2[2][128][33];
    __shared__ float red[8][MQ_];
    const int bid = blockIdx.x, tid = threadIdx.x;
    const int tx = tid & 31, ty = tid >> 5;
    const int b0 = (bid >> 4) * 16, j0 = (bid & 15) * 32;
    const int j = j0 + tx;

    if (tid < DIN_)
        g_decx[bid][tid] = (tid == 0)
            ? __ldg(X + (long)bid * T_ * DIN_ + (T_ - 1) * DIN_)
            : __ldg(fut + (long)bid * HOR_ * DFF_ + (tid - 1));

    const float b0I = __ldg(db0 + j),        b0F = __ldg(db0 + 512 + j),
                b0G = __ldg(db0 + 1024 + j), b0O = __ldg(db0 + 1536 + j);
    const float b1I = __ldg(db1 + j),        b1F = __ldg(db1 + 512 + j),
                b1G = __ldg(db1 + 1024 + j), b1O = __ldg(db1 + 1536 + j);
    float c0[2], c1[2];
    #pragma unroll
    for (int bi = 0; bi < 2; ++bi) {
        c0[bi] = g_dec_c0[b0 + ty * 2 + bi][j];
        c1[bi] = g_dec_c1[b0 + ty * 2 + bi][j];
    }
    grid_barrier();

    for (int s = 0; s < HOR_; ++s) {
        {
            u64 acc2[1][4] = {};
            seg_accum<16>(a_s2[0], w_s2[0], &g_decx[0][0], DIN_, 1,
                          dwih0, DIN_, DIN_, b0, j0, acc2);
            seg16_pipe(a_s2, w_s2, &g_dec_h0[s & 1][0][0], H_,
                       dwhh0, H_, b0, j0, acc2);
            float acc[2][4];
            #pragma unroll
            for (int gi = 0; gi < 4; ++gi)
                unpack2(acc2[0][gi], acc[0][gi], acc[1][gi]);
            #pragma unroll
            for (int bi = 0; bi < 2; ++bi) {
                float i_ = sigm_(acc[bi][0] + b0I);
                float f_ = sigm_(acc[bi][1] + b0F);
                float g_ = tanh_(acc[bi][2] + b0G);
                float o_ = sigm_(acc[bi][3] + b0O);
                float c  = f_ * c0[bi] + i_ * g_;
                c0[bi] = c;
                g_dec_h0[(s + 1) & 1][b0 + ty * 2 + bi][j] = o_ * tanh_(c);
            }
        }
        grid_barrier();
        {
            u64 acc2[1][4] = {};
            seg16_pipe(a_s2, w_s2, &g_dec_h0[(s + 1) & 1][0][0], H_,
                       dwih1, H_, b0, j0, acc2);
            seg16_pipe(a_s2, w_s2, &g_dec_h1[s & 1][0][0], H_,
                       dwhh1, H_, b0, j0, acc2);
            float acc[2][4];
            #pragma unroll
            for (int gi = 0; gi < 4; ++gi)
                unpack2(acc2[0][gi], acc[0][gi], acc[1][gi]);
            #pragma unroll
            for (int bi = 0; bi < 2; ++bi) {
                float i_ = sigm_(acc[bi][0] + b1I);
                float f_ = sigm_(acc[bi][1] + b1F);
                float g_ = tanh_(acc[bi][2] + b1G);
                float o_ = sigm_(acc[bi][3] + b1O);
                float c  = f_ * c1[bi] + i_ * g_;
                c1[bi] = c;
                g_dec_h1[(s + 1) & 1][b0 + ty * 2 + bi][j] = o_ * tanh_(c);
            }
        }
        grid_barrier();
        {
            const float* h1 = &g_dec_h1[(s + 1) & 1][bid][0];
            float part[MQ_] = {0.f, 0.f, 0.f, 0.f, 0.f};
            for (int k = tid; k < H_; k += 256) {
                float hv = __ldcg(h1 + k);
                #pragma unroll
                for (int q = 0; q < MQ_; ++q)
                    part[q] = fmaf(hv, __ldg(wo + q * H_ + k), part[q]);
            }
            #pragma unroll
            for (int o = 16; o; o >>= 1)
                #pragma unroll
                for (int q = 0; q < MQ_; ++q)
                    part[q] += __shfl_down_sync(0xffffffffu, part[q], o);
            if ((tid & 31) == 0)
                #pragma unroll
                for (int q = 0; q < MQ_; ++q) red[tid >> 5][q] = part[q];
            __syncthreads();
            if (tid < MQ_) {
                float v = __ldg(bo + tid);
                #pragma unroll
                for (int w2 = 0; w2 < 8; ++w2) v += red[w2][tid];
                out[(long)bid * HOR_ * MQ_ + s * MQ_ + tid] = v;
                if (tid == 0) g_decx[bid][0] = v;
            }
            if (s + 1 < HOR_ && tid >= 32 && tid < 32 + DFF_)
                g_decx[bid][tid - 31] =
                    __ldg(fut + (long)bid * HOR_ * DFF_ + (s + 1) * DFF_ + (tid - 32));
        }
        grid_barrier();
    }
}

// ---------------- launcher (7 graph nodes) ----------------
extern "C" void kernel_launch(void* const* d_in, const int* in_sizes, int n_in,
                              void* d_out, int out_size)
{
    int off = (n_in >= 4 && in_sizes[3] == 1) ? 0 : -1;
    const float* X     = (const float*)d_in[0];
    const float* fut   = (const float*)d_in[1];
    const float* ewih0 = (const float*)d_in[4 + off];
    const float* ewhh0 = (const float*)d_in[5 + off];
    const float* eb0   = (const float*)d_in[6 + off];
    const float* ewih1 = (const float*)d_in[7 + off];
    const float* ewhh1 = (const float*)d_in[8 + off];
    const float* eb1   = (const float*)d_in[9 + off];
    const float* dwih0 = (const float*)d_in[10 + off];
    const float* dwhh0 = (const float*)d_in[11 + off];
    const float* db0   = (const float*)d_in[12 + off];
    const float* dwih1 = (const float*)d_in[13 + off];
    const float* dwhh1 = (const float*)d_in[14 + off];
    const float* db1   = (const float*)d_in[15 + off];
    const float* wb    = (const float*)d_in[16 + off];
    const float* bb    = (const float*)d_in[17 + off];
    const float* wo    = (const float*)d_in[18 + off];
    const float* bo    = (const float*)d_in[19 + off];
    float* out = (float*)d_out;

    cudaFuncSetAttribute(enc_mma_persist<0>,
                         cudaFuncAttributeMaxDynamicSharedMemorySize, ENC_SMEM);
    cudaFuncSetAttribute(enc_mma_persist<1>,
                         cudaFuncAttributeMaxDynamicSharedMemorySize, ENC_SMEM);

    gates0_gemm<<<dim3(T_, 2), 256>>>(X, ewih0);
    convB_kernel<<<2048, 256>>>(ewih1);
    enc_mma_persist<0><<<NBLK, 256, ENC_SMEM>>>(ewhh0, eb0);
    gates1_mma<<<dim3(16, 512, 2), 256>>>();
    enc_mma_persist<1><<<NBLK, 256, ENC_SMEM>>>(ewhh1, eb1);
    bridge_kernel<<<dim3(4, 32, 2), 256>>>(wb, bb);
    dec_persist<<<NBLK, 256>>>(X, fut, dwih0, dwhh0, db0,
                               dwih1, dwhh1, db1, wo, bo, out);
}

// round 14
// speedup vs baseline: 1.5570x; 1.0051x over previous
#include <cuda_runtime.h>
#include <cuda_bf16.h>
#include <math.h>
#include <stdint.h>

#define B_   128
#define T_   512
#define H_   512
#define G_   2048
#define DIN_ 8
#define HOR_ 64
#define MQ_  5
#define DFF_ 7
#define NBLK 128

typedef unsigned long long u64;

// ---------------- scratch (device globals; no allocations) ----------------
__device__ float g_gates0[2][T_][B_][G_];    // precomputed layer-0 input gates
__device__ float g_gates1[2][T_][B_][G_];    // precomputed layer-1 input gates
__device__ float g_c[2][2][B_][H_];          // final cell states [layer][dir]
__device__ float g_h0fin[2][B_][H_];         // layer-0 final h per dir (fp32)
__device__ float g_h1fin[2][B_][H_];         // layer-1 final h per dir (fp32)
__device__ float g_dec_h0[2][B_][H_];
__device__ float g_dec_c0[B_][H_];
__device__ float g_dec_h1[2][B_][H_];
__device__ float g_dec_c1[B_][H_];
__device__ float g_decx[B_][DIN_];           // decoder input vector [y_fb, fut]
__device__ unsigned g_bar_cnt;
__device__ unsigned g_bar_gen;

// bf16 hi/lo split activations (enc-L0 h sequence; also gates1_mma's A input)
__device__ __nv_bfloat16 g_Ah[T_ * B_][1024];
__device__ __nv_bfloat16 g_Al[T_ * B_][1024];
// layer-1 h ping-pong, bf16 hi/lo
__device__ __nv_bfloat16 g_h1h[2][2][B_][H_];
__device__ __nv_bfloat16 g_h1l[2][2][B_][H_];
// gates1 weights, bf16 hi/lo
__device__ __nv_bfloat16 g_Bh[2][G_][1024];
__device__ __nv_bfloat16 g_Bl[2][G_][1024];

// ---------------- software grid barrier (R8 mechanism, verbatim) ----------
__device__ __forceinline__ void grid_barrier()
{
    __syncthreads();
    if (threadIdx.x == 0) {
        volatile unsigned* genp = &g_bar_gen;
        unsigned gen = *genp;
        __threadfence();
        if (atomicAdd(&g_bar_cnt, 1u) == NBLK - 1u) {
            g_bar_cnt = 0u;
            __threadfence();
            *genp = gen + 1u;
        } else {
            while (*genp == gen) { }
        }
        __threadfence();
    }
    __syncthreads();
}

// ---------------- packed fp32x2 helpers (decoder SIMT path) ----------------
__device__ __forceinline__ void ffma2(u64& d, u64 a, u64 b) {
    asm("fma.rn.f32x2 %0, %1, %2, %0;" : "+l"(d) : "l"(a), "l"(b));
}
__device__ __forceinline__ u64 bcast2(float v) {
    u64 r;
    asm("mov.b64 %0, {%1, %1};" : "=l"(r) : "f"(v));
    return r;
}
__device__ __forceinline__ void unpack2(u64 v, float& lo, float& hi) {
    asm("mov.b64 {%0, %1}, %2;" : "=f"(lo), "=f"(hi) : "l"(v));
}

// ---------------- fast transcendentals ----------------
__device__ __forceinline__ float sigm_(float x) {
    return __fdividef(1.f, 1.f + __expf(-x));
}
__device__ __forceinline__ float tanh_(float x) {
    return __fdividef(2.f, 1.f + __expf(-2.f * x)) - 1.f;
}

// ---------------- mma.sync / ldmatrix helpers ----------------
__device__ __forceinline__ uint32_t smem_u32(const void* p) {
    uint32_t a;
    asm("{ .reg .u64 t; cvta.to.shared.u64 t, %1; cvt.u32.u64 %0, t; }"
        : "=r"(a) : "l"(p));
    return a;
}
__device__ __forceinline__ void ldsm4(uint32_t a, uint32_t& r0, uint32_t& r1,
                                      uint32_t& r2, uint32_t& r3) {
    asm volatile("ldmatrix.sync.aligned.m8n8.x4.shared.b16 {%0,%1,%2,%3}, [%4];"
                 : "=r"(r0), "=r"(r1), "=r"(r2), "=r"(r3) : "r"(a));
}
__device__ __forceinline__ void ldsm2(uint32_t a, uint32_t& r0, uint32_t& r1) {
    asm volatile("ldmatrix.sync.aligned.m8n8.x2.shared.b16 {%0,%1}, [%2];"
                 : "=r"(r0), "=r"(r1) : "r"(a));
}
__device__ __forceinline__ void mma_bf16(float* c, const uint32_t* a, const uint32_t* b) {
    asm volatile(
        "mma.sync.aligned.m16n8k16.row.col.f32.bf16.bf16.f32 "
        "{%0,%1,%2,%3}, {%4,%5,%6,%7}, {%8,%9}, {%0,%1,%2,%3};"
        : "+f"(c[0]), "+f"(c[1]), "+f"(c[2]), "+f"(c[3])
        : "r"(a[0]), "r"(a[1]), "r"(a[2]), "r"(a[3]), "r"(b[0]), "r"(b[1]));
}

// ---------------- layer-0 input gates: one-shot tiny-K GEMM ----------------
__global__ __launch_bounds__(256) void gates0_gemm(
    const float* __restrict__ X, const float* __restrict__ w_ih)
{
    __shared__ float xs_[B_][DIN_];
    const int t = blockIdx.x, dir = blockIdx.y;
    const int tid = threadIdx.x;
    for (int e = tid; e < B_ * DIN_; e += 256) {
        int b = e >> 3, k = e & 7;
        xs_[b][k] = __ldg(X + ((long)b * T_ + t) * DIN_ + k);
    }
    __syncthreads();
    const float* w = w_ih + (long)dir * G_ * DIN_;
    for (int g = tid; g < G_; g += 256) {
        float4 w0 = *reinterpret_cast<const float4*>(w + g * DIN_);
        float4 w1 = *reinterpret_cast<const float4*>(w + g * DIN_ + 4);
        float* op = &g_gates0[dir][t][0][0];
        for (int b = 0; b < B_; ++b) {
            const float* xb = xs_[b];
            float acc = xb[0] * w0.x + xb[1] * w0.y + xb[2] * w0.z + xb[3] * w0.w
                      + xb[4] * w1.x + xb[5] * w1.y + xb[6] * w1.z + xb[7] * w1.w;
            op[(long)b * G_ + g] = acc;
        }
    }
}

// -------- fp32 -> bf16 hi/lo conversion for gates1 weights ----------------
__global__ __launch_bounds__(256) void convB_kernel(const float* __restrict__ w_ih1)
{
    const long npairs = (long)2 * G_ * 512;
    __nv_bfloat16* bh = &g_Bh[0][0][0];
    __nv_bfloat16* bl = &g_Bl[0][0][0];
    for (long p = (long)blockIdx.x * 256 + threadIdx.x; p < npairs;
         p += (long)gridDim.x * 256) {
        float2 v = *reinterpret_cast<const float2*>(w_ih1 + p * 2);
        __nv_bfloat16 h0 = __float2bfloat16(v.x);
        __nv_bfloat16 l0 = __float2bfloat16(v.x - __bfloat162float(h0));
        __nv_bfloat16 h1 = __float2bfloat16(v.y);
        __nv_bfloat16 l1 = __float2bfloat16(v.y - __bfloat162float(h1));
        *reinterpret_cast<__nv_bfloat162*>(bh + p * 2) = __nv_bfloat162(h0, h1);
        *reinterpret_cast<__nv_bfloat162*>(bl + p * 2) = __nv_bfloat162(l0, l1);
    }
}

// =========== persistent mma-based encoder layer (layer = 0 or 1) ==========
// Block = 64 batch x 64 gate-cols (16 j x 4 gate types), K=512/step.
// W_hh hi/lo resident in SMEM all 512 steps; A (=h) streamed per step in
// 8 double-buffered k-chunks of 64. 8 warps = 4M x 2N (warp: 16 x 32).
#define ESM_W_H 0
#define ESM_W_L 66560
#define ESM_A   133120
#define ESM_AB  9216
#define ESM_C   169984
#define ENC_SMEM 187392

template<int LAYER>
__global__ __launch_bounds__(256, 1) void enc_mma_persist(
    const float* __restrict__ w_hh, const float* __restrict__ bias)
{
    extern __shared__ __align__(16) char esm[];
    __nv_bfloat16* Wh = reinterpret_cast<__nv_bfloat16*>(esm + ESM_W_H);
    __nv_bfloat16* Wl = reinterpret_cast<__nv_bfloat16*>(esm + ESM_W_L);
    float* Cb = reinterpret_cast<float*>(esm + ESM_C);

    const int tid = threadIdx.x, lane = tid & 31, wid = tid >> 5;
    const int warp_m = wid & 3, warp_n = wid >> 2;
    const int bid = blockIdx.x;
    const int dir = bid >> 6, rr = bid & 63;
    const int b0 = (rr >> 5) * 64, j0 = (rr & 31) * 16;

    // ---- one-time W_hh load + hi/lo split into resident smem ----
    const float* wsrc = w_hh + (long)dir * G_ * H_;
    for (int idx = tid; idx < 64 * 512; idx += 256) {
        int n = idx >> 9, k = idx & 511;
        int gc = (n >> 4) * 512 + j0 + (n & 15);
        float v = __ldg(wsrc + (long)gc * H_ + k);
        __nv_bfloat16 h = __float2bfloat16(v);
        Wh[n * 520 + k] = h;
        Wl[n * 520 + k] = __float2bfloat16(v - __bfloat162float(h));
    }

    // ---- per-thread pointwise cell mapping: (pb batch-local, jq j-quad) ----
    const int pb = tid >> 2, jq = tid & 3;
    const float* bp = bias + dir * G_ + j0 + jq * 4;
    float4 bI = __ldg((const float4*)(bp));
    float4 bF = __ldg((const float4*)(bp + 512));
    float4 bG = __ldg((const float4*)(bp + 1024));
    float4 bO = __ldg((const float4*)(bp + 1536));
    float cst[4] = {0.f, 0.f, 0.f, 0.f};

    // ---- ldmatrix lane offsets ----
    uint32_t WhB = smem_u32(Wh), WlB = smem_u32(Wl);
    const uint32_t aRow = (uint32_t)((warp_m * 16 + (lane & 15)) * 144
                                     + (lane >> 4) * 16);
    // ldsm4 B offsets: pair p covers ni={2p,2p+1}; lane groups 0-7/8-15/16-23/24-31
    // map to tiles (ni=2p,k0),(ni=2p,k8),(ni=2p+1,k0),(ni=2p+1,k8).
    uint32_t bOff4[2];
    #pragma unroll
    for (int p = 0; p < 2; ++p)
        bOff4[p] = (uint32_t)((warp_n * 32 + (2 * p + ((lane >> 4) & 1)) * 8
                               + (lane & 7)) * 1040
                              + ((lane >> 3) & 1) * 16);

    const float* gatesrc = (LAYER == 0 ? &g_gates0[0][0][0][0]
                                       : &g_gates1[0][0][0][0])
                         + (long)dir * T_ * B_ * G_;
    __syncthreads();

    for (int s = 0; s < T_; ++s) {
        const int t = dir ? (T_ - 1 - s) : s;
        // prefetch gate-init (hidden behind the MMA work)
        const float* gp = gatesrc + ((long)t * B_ + b0 + pb) * G_ + j0 + jq * 4;
        float4 gI = __ldg((const float4*)(gp));
        float4 gF = __ldg((const float4*)(gp + 512));
        float4 gG = __ldg((const float4*)(gp + 1024));
        float4 gO = __ldg((const float4*)(gp + 1536));

        float acc[4][4] = {};
        if (s > 0) {
            const __nv_bfloat16 *pAh, *pAl;
            long apitch;
            if (LAYER == 0) {
                const int tp = dir ? t + 1 : t - 1;
                pAh = &g_Ah[tp * 128 + b0][dir * 512];
                pAl = &g_Al[tp * 128 + b0][dir * 512];
                apitch = 1024;
            } else {
                pAh = &g_h1h[s & 1][dir][b0][0];
                pAl = &g_h1l[s & 1][dir][b0][0];
                apitch = 512;
            }
            uint4 stg[4];
            auto stage = [&](int kc) {
                #pragma unroll
                for (int i = 0; i < 4; ++i) {
                    int idx = tid + i * 256;
                    int term = idx >> 9, rem = idx & 511;
                    int row = rem >> 3, c8 = rem & 7;
                    const __nv_bfloat16* src =
                        (term ? pAl : pAh) + (long)row * apitch + kc * 64 + c8 * 8;
                    stg[i] = __ldcg(reinterpret_cast<const uint4*>(src));
                }
            };
            auto commitA = [&](int buf) {
                #pragma unroll
                for (int i = 0; i < 4; ++i) {
                    int idx = tid + i * 256;
                    int term = idx >> 9, rem = idx & 511;
                    int row = rem >> 3, c8 = rem & 7;
                    *reinterpret_cast<uint4*>(
                        esm + ESM_A + (buf * 2 + term) * ESM_AB + row * 144 + c8 * 16)
                        = stg[i];
                }
            };
            stage(0);
            commitA(0);
            __syncthreads();
            #pragma unroll 1
            for (int kc = 0; kc < 8; ++kc) {
                const int buf = kc & 1;
                if (kc < 7) stage(kc + 1);
                const uint32_t AhB = smem_u32(esm + ESM_A + (buf * 2) * ESM_AB);
                const uint32_t AlB = AhB + ESM_AB;
                #pragma unroll
                for (int ks = 0; ks < 4; ++ks) {
                    const uint32_t wko = kc * 128 + ks * 32;
                    uint32_t ah[4], al[4], bh[4][2], bl[4][2];
                    ldsm4(AhB + aRow + ks * 32, ah[0], ah[1], ah[2], ah[3]);
                    ldsm4(AlB + aRow + ks * 32, al[0], al[1], al[2], al[3]);
                    ldsm4(WhB + bOff4[0] + wko, bh[0][0], bh[0][1], bh[1][0], bh[1][1]);
                    ldsm4(WhB + bOff4[1] + wko, bh[2][0], bh[2][1], bh[3][0], bh[3][1]);
                    ldsm4(WlB + bOff4[0] + wko, bl[0][0], bl[0][1], bl[1][0], bl[1][1]);
                    ldsm4(WlB + bOff4[1] + wko, bl[2][0], bl[2][1], bl[3][0], bl[3][1]);
                    #pragma unroll
                    for (int ni = 0; ni < 4; ++ni) {
                        mma_bf16(acc[ni], ah, bh[ni]);
                        mma_bf16(acc[ni], ah, bl[ni]);
                        mma_bf16(acc[ni], al, bh[ni]);
                    }
                }
                if (kc < 7) commitA(buf ^ 1);
                __syncthreads();
            }
        }
        // ---- epilogue: dump acc frags to Cbuf (64 x 64, pitch 68) ----
        {
            const int row = warp_m * 16 + (lane >> 2);
            #pragma unroll
            for (int ni = 0; ni < 4; ++ni) {
                const int col = warp_n * 32 + ni * 8 + (lane & 3) * 2;
                *reinterpret_cast<float2*>(&Cb[row * 68 + col]) =
                    make_float2(acc[ni][0], acc[ni][1]);
                *reinterpret_cast<float2*>(&Cb[(row + 8) * 68 + col]) =
                    make_float2(acc[ni][2], acc[ni][3]);
            }
        }
        __syncthreads();
        // ---- pointwise LSTM cell + h split/write ----
        {
            __align__(8) __nv_bfloat16 hh[4], hl[4];
            float hv[4];
            const float* gIv = (const float*)&gI;
            const float* gFv = (const float*)&gF;
            const float* gGv = (const float*)&gG;
            const float* gOv = (const float*)&gO;
            const float* bIv = (const float*)&bI;
            const float* bFv = (const float*)&bF;
            const float* bGv = (const float*)&bG;
            const float* bOv = (const float*)&bO;
            #pragma unroll
            for (int q = 0; q < 4; ++q) {
                const int jl = jq * 4 + q;
                float iv = Cb[pb * 68 + jl]      + gIv[q] + bIv[q];
                float fv = Cb[pb * 68 + 16 + jl] + gFv[q] + bFv[q];
                float gv = Cb[pb * 68 + 32 + jl] + gGv[q] + bGv[q];
                float ov = Cb[pb * 68 + 48 + jl] + gOv[q] + bOv[q];
                float i_ = sigm_(iv), f_ = sigm_(fv), g_ = tanh_(gv), o_ = sigm_(ov);
                float c = f_ * cst[q] + i_ * g_;
                cst[q] = c;
                float h = o_ * tanh_(c);
                hv[q] = h;
                hh[q] = __float2bfloat16(h);
                hl[q] = __float2bfloat16(h - __bfloat162float(hh[q]));
            }
            if (LAYER == 0) {
                *reinterpret_cast<uint2*>(&g_Ah[t * 128 + b0 + pb][dir * 512 + j0 + jq * 4])
                    = *reinterpret_cast<uint2*>(hh);
                *reinterpret_cast<uint2*>(&g_Al[t * 128 + b0 + pb][dir * 512 + j0 + jq * 4])
                    = *reinterpret_cast<uint2*>(hl);
                if (s == T_ - 1)
                    *reinterpret_cast<float4*>(&g_h0fin[dir][b0 + pb][j0 + jq * 4]) =
                        make_float4(hv[0], hv[1], hv[2], hv[3]);
            } else {
                *reinterpret_cast<uint2*>(&g_h1h[(s + 1) & 1][dir][b0 + pb][j0 + jq * 4])
                    = *reinterpret_cast<uint2*>(hh);
                *reinterpret_cast<uint2*>(&g_h1l[(s + 1) & 1][dir][b0 + pb][j0 + jq * 4])
                    = *reinterpret_cast<uint2*>(hl);
                if (s == T_ - 1)
                    *reinterpret_cast<float4*>(&g_h1fin[dir][b0 + pb][j0 + jq * 4]) =
                        make_float4(hv[0], hv[1], hv[2], hv[3]);
            }
        }
        grid_barrier();
    }
    #pragma unroll
    for (int q = 0; q < 4; ++q)
        g_c[LAYER][dir][b0 + pb][j0 + jq * 4 + q] = cst[q];
}

// ======== gates1 via mma.sync bf16: D[128,128] = A[128,1024] @ W^T =========
#define PITCH 40

__global__ __launch_bounds__(256) void gates1_mma()
{
    __shared__ __align__(16) __nv_bfloat16 smem4[4][128 * PITCH];
    const int tid = threadIdx.x;
    const int wid = tid >> 5, lane = tid & 31;
    const int n0 = blockIdx.x * 128, r0 = blockIdx.y * 128, dir = blockIdx.z;
    const int warp_m = wid & 1, warp_n = wid >> 1;

    const __nv_bfloat16* srcs[4] = {
        &g_Ah[r0][0], &g_Al[r0][0], &g_Bh[dir][n0][0], &g_Bl[dir][n0][0] };
    uint32_t sb[4] = { smem_u32(smem4[0]), smem_u32(smem4[1]),
                       smem_u32(smem4[2]), smem_u32(smem4[3]) };

    uint32_t aOff[4], bOff4[2];
    #pragma unroll
    for (int mi = 0; mi < 4; ++mi)
        aOff[mi] = (uint32_t)((warp_m * 64 + mi * 16 + (lane & 15)) * (PITCH * 2)
                              + (lane >> 4) * 16);
    #pragma unroll
    for (int p = 0; p < 2; ++p)
        bOff4[p] = (uint32_t)((warp_n * 32 + (2 * p + ((lane >> 4) & 1)) * 8
                               + (lane & 7)) * (PITCH * 2)
                              + ((lane >> 3) & 1) * 16);

    uint2 stg[16];
    auto stage = [&](int kbase) {
        #pragma unroll
        for (int i = 0; i < 16; ++i) {
            int idx = i * 256 + tid;
            int tI = idx >> 10, row = (idx >> 3) & 127, c = idx & 7;
            stg[i] = *reinterpret_cast<const uint2*>(
                srcs[tI] + (long)row * 1024 + kbase + c * 4);
        }
    };
    auto commit = [&]() {
        #pragma unroll
        for (int i = 0; i < 16; ++i) {
            int idx = i * 256 + tid;
            int tI = idx >> 10, row = (idx >> 3) & 127, c = idx & 7;
            *reinterpret_cast<uint2*>(&smem4[tI][row * PITCH + c * 4]) = stg[i];
        }
    };

    float acc[4][4][4];
    #pragma unroll
    for (int mi = 0; mi < 4; ++mi)
        #pragma unroll
        for (int ni = 0; ni < 4; ++ni)
            #pragma unroll
            for (int q = 0; q < 4; ++q) acc[mi][ni][q] = 0.f;

    stage(0);
    commit();
    __syncthreads();
    #pragma unroll 1
    for (int kc = 0; kc < 32; ++kc) {
        if (kc < 31) stage((kc + 1) * 32);
        #pragma unroll
        for (int ks = 0; ks < 2; ++ks) {
            const uint32_t kb = ks * 32;
            uint32_t ah[4][4], al[4][4], bh[4][2], bl[4][2];
            #pragma unroll
            for (int mi = 0; mi < 4; ++mi) {
                ldsm4(sb[0] + aOff[mi] + kb, ah[mi][0], ah[mi][1], ah[mi][2], ah[mi][3]);
                ldsm4(sb[1] + aOff[mi] + kb, al[mi][0], al[mi][1], al[mi][2], al[mi][3]);
            }
            ldsm4(sb[2] + bOff4[0] + kb, bh[0][0], bh[0][1], bh[1][0], bh[1][1]);
            ldsm4(sb[2] + bOff4[1] + kb, bh[2][0], bh[2][1], bh[3][0], bh[3][1]);
            ldsm4(sb[3] + bOff4[0] + kb, bl[0][0], bl[0][1], bl[1][0], bl[1][1]);
            ldsm4(sb[3] + bOff4[1] + kb, bl[2][0], bl[2][1], bl[3][0], bl[3][1]);
            #pragma unroll
            for (int mi = 0; mi < 4; ++mi)
                #pragma unroll
                for (int ni = 0; ni < 4; ++ni) {
                    mma_bf16(acc[mi][ni], ah[mi], bh[ni]);
                    mma_bf16(acc[mi][ni], ah[mi], bl[ni]);
                    mma_bf16(acc[mi][ni], al[mi], bh[ni]);
                }
        }
        __syncthreads();
        if (kc < 31) { commit(); __syncthreads(); }
    }

    float* ob = &g_gates1[dir][0][0][0];
    const int group = lane >> 2, tig = lane & 3;
    #pragma unroll
    for (int mi = 0; mi < 4; ++mi) {
        const long row = r0 + warp_m * 64 + mi * 16 + group;
        #pragma unroll
        for (int ni = 0; ni < 4; ++ni) {
            const int col = n0 + warp_n * 32 + ni * 8 + tig * 2;
            *reinterpret_cast<float2*>(ob + row * G_ + col) =
                make_float2(acc[mi][ni][0], acc[mi][ni][1]);
            *reinterpret_cast<float2*>(ob + (row + 8) * G_ + col) =
                make_float2(acc[mi][ni][2], acc[mi][ni][3]);
        }
    }
}

// -------- SIMT segment accumulate, unpipelined (decoder K=8 seg only) -----
template<int BT>
__device__ __forceinline__ void seg_accum(
    float (*a_s)[BT + 4], float (*w_s)[33],
    const float* __restrict__ xp, int xs, int use_ldcg,
    const float* __restrict__ wp, int ws, int K,
    int b0, int j0, u64 acc2[BT / 16][4])
{
    const int tid = threadIdx.x, tx = tid & 31, ty = tid >> 5;
    constexpr int P = BT / 16;
    for (int k0 = 0; k0 < K; k0 += 32) {
        __syncthreads();
        #pragma unroll
        for (int i = 0; i < (BT * 32) / 256; ++i) {
            int e = tid + i * 256;
            int r = e >> 5, kk = e & 31, kg = k0 + kk;
            float v = 0.f;
            if (kg < K) {
                const float* p = xp + (long)(b0 + r) * xs + kg;
                v = use_ldcg ? __ldcg(p) : __ldg(p);
            }
            a_s[kk][r] = v;
        }
        #pragma unroll
        for (int i = 0; i < 16; ++i) {
            int e = tid + i * 256;
            int c = e >> 5, kk = e & 31, kg = k0 + kk;
            float v = 0.f;
            if (kg < K) {
                int gc = j0 + (c >> 5) * 512 + (c & 31);
                v = __ldg(wp + (long)gc * ws + kg);
            }
            w_s[c][kk] = v;
        }
        __syncthreads();
        #pragma unroll
        for (int kk = 0; kk < 32; ++kk) {
            u64 av[P];
            #pragma unroll
            for (int p = 0; p < P; ++p)
                av[p] = *reinterpret_cast<const u64*>(&a_s[kk][ty * (2 * P) + 2 * p]);
            #pragma unroll
            for (int gi = 0; gi < 4; ++gi) {
                u64 wv2 = bcast2(w_s[gi * 32 + tx][kk]);
                #pragma unroll
                for (int p = 0; p < P; ++p)
                    ffma2(acc2[p][gi], av[p], wv2);
            }
        }
    }
}

// -------- pipelined K=512 segment (decoder, BT=16) ------------------------
__device__ __forceinline__ void seg16_pipe(
    float (*a_s)[32][20], float (*w_s)[128][33],
    const float* __restrict__ xp, int xs,
    const float* __restrict__ wp, int ws,
    int b0, int j0, u64 acc2[1][4])
{
    const int tid = threadIdx.x, tx = tid & 31, ty = tid >> 5;
    int aofs[2], gcofs[16];
    #pragma unroll
    for (int i = 0; i < 2; ++i) {
        int e = tid + i * 256;
        aofs[i] = (b0 + (e >> 5)) * xs + (e & 31);
    }
    #pragma unroll
    for (int i = 0; i < 16; ++i) {
        int c = ty + 8 * i;
        gcofs[i] = (j0 + (c >> 5) * 512 + (c & 31)) * ws + tx;
    }
    float ar[2], wr[16];
    auto stage = [&](int kt) {
        const int ko = kt * 32;
        ar[0] = __ldcg(xp + aofs[0] + ko);
        ar[1] = __ldcg(xp + aofs[1] + ko);
        #pragma unroll
        for (int i = 0; i < 16; ++i)
            wr[i] = __ldg(wp + gcofs[i] + ko);
    };
    auto commit = [&](int buf) {
        #pragma unroll
        for (int i = 0; i < 2; ++i) {
            int e = tid + i * 256;
            a_s[buf][e & 31][e >> 5] = ar[i];
        }
        #pragma unroll
        for (int i = 0; i < 16; ++i)
            w_s[buf][ty + 8 * i][tx] = wr[i];
    };
    __syncthreads();
    stage(0);
    commit(0);
    __syncthreads();
    #pragma unroll 1
    for (int kt = 0; kt < 16; ++kt) {
        const int buf = kt & 1;
        if (kt < 15) stage(kt + 1);
        #pragma unroll
        for (int kk = 0; kk < 32; ++kk) {
            u64 av = *reinterpret_cast<const u64*>(&a_s[buf][kk][2 * ty]);
            #pragma unroll
            for (int gi = 0; gi < 4; ++gi) {
                u64 w2 = bcast2(w_s[buf][gi * 32 + tx][kk]);
                ffma2(acc2[0][gi], av, w2);
            }
        }
        if (kt < 15) commit(buf ^ 1);
        __syncthreads();
    }
}

// ---------------- bridge: elu(h/c_flat @ Wbᵀ + bb) -> decoder init ---------
__global__ __launch_bounds__(256) void bridge_kernel(
    const float* __restrict__ wb, const float* __restrict__ bb)
{
    __shared__ float in_s[32][33], w_s2[32][33];
    const int tid = threadIdx.x, tx = tid & 31, ty = tid >> 5;
    const int b0 = blockIdx.x * 32, m0 = blockIdx.y * 32, z = blockIdx.z;
    const float* srcs[4];
    if (z == 0) {
        srcs[0] = &g_h0fin[0][0][0]; srcs[1] = &g_h0fin[1][0][0];
        srcs[2] = &g_h1fin[0][0][0]; srcs[3] = &g_h1fin[1][0][0];
    } else {
        srcs[0] = &g_c[0][0][0][0]; srcs[1] = &g_c[0][1][0][0];
        srcs[2] = &g_c[1][0][0][0]; srcs[3] = &g_c[1][1][0][0];
    }
    float acc[4] = {0.f, 0.f, 0.f, 0.f};
    for (int k0 = 0; k0 < 2048; k0 += 32) {
        __syncthreads();
        const float* src = srcs[k0 >> 9];
        const int kl = k0 & 511;
        #pragma unroll
        for (int i = 0; i < 4; ++i) {
            int e = tid + i * 256;
            int r = e >> 5, kk = e & 31;
            in_s[r][kk] = src[(long)(b0 + r) * H_ + kl + kk];
            w_s2[r][kk] = wb[(long)(m0 + r) * 2048 + k0 + kk];
        }
        __syncthreads();
        #pragma unroll
        for (int kk = 0; kk < 32; ++kk) {
            float wv = w_s2[tx][kk];
            #pragma unroll
            for (int bi = 0; bi < 4; ++bi)
                acc[bi] = fmaf(in_s[ty * 4 + bi][kk], wv, acc[bi]);
        }
    }
    const int m = m0 + tx;
    #pragma unroll
    for (int bi = 0; bi < 4; ++bi) {
        int b = b0 + ty * 4 + bi;
        float v = acc[bi] + bb[m];
        v = (v > 0.f) ? v : expm1f(v);
        if (z == 0) {
            if (m < 512) g_dec_h0[0][b][m] = v; else g_dec_h1[0][b][m - 512] = v;
        } else {
            if (m < 512) g_dec_c0[b][m] = v;    else g_dec_c1[b][m - 512] = v;
        }
    }
}

// ---------------- decoder: persistent, 64 steps ----------------------------
__global__ __launch_bounds__(256, 1) void dec_persist(
    const float* __restrict__ X, const float* __restrict__ fut,
    const float* __restrict__ dwih0, const float* __restrict__ dwhh0,
    const float* __restrict__ db0,
    const float* __restrict__ dwih1, const float* __restrict__ dwhh1,
    const float* __restrict__ db1,
    const float* __restrict__ wo, const float* __restrict__ bo,
    float* __restrict__ out)
{
    __shared__ __align__(16) float a_s2[2][32][20];
    __shared__ __align__(16) float w_s2[2][128][33];
    __shared__ float red[8][MQ_];
    const int bid = blockIdx.x, tid = threadIdx.x;
    const int tx = tid & 31, ty = tid >> 5;
    const int b0 = (bid >> 4) * 16, j0 = (bid & 15) * 32;
    const int j = j0 + tx;

    if (tid < DIN_)
        g_decx[bid][tid] = (tid == 0)
            ? __ldg(X + (long)bid * T_ * DIN_ + (T_ - 1) * DIN_)
            : __ldg(fut + (long)bid * HOR_ * DFF_ + (tid - 1));

    const float b0I = __ldg(db0 + j),        b0F = __ldg(db0 + 512 + j),
                b0G = __ldg(db0 + 1024 + j), b0O = __ldg(db0 + 1536 + j);
    const float b1I = __ldg(db1 + j),        b1F = __ldg(db1 + 512 + j),
                b1G = __ldg(db1 + 1024 + j), b1O = __ldg(db1 + 1536 + j);
    float c0[2], c1[2];
    #pragma unroll
    for (int bi = 0; bi < 2; ++bi) {
        c0[bi] = g_dec_c0[b0 + ty * 2 + bi][j];
        c1[bi] = g_dec_c1[b0 + ty * 2 + bi][j];
    }
    grid_barrier();

    for (int s = 0; s < HOR_; ++s) {
        {
            u64 acc2[1][4] = {};
            seg_accum<16>(a_s2[0], w_s2[0], &g_decx[0][0], DIN_, 1,
                          dwih0, DIN_, DIN_, b0, j0, acc2);
            seg16_pipe(a_s2, w_s2, &g_dec_h0[s & 1][0][0], H_,
                       dwhh0, H_, b0, j0, acc2);
            float acc[2][4];
            #pragma unroll
            for (int gi = 0; gi < 4; ++gi)
                unpack2(acc2[0][gi], acc[0][gi], acc[1][gi]);
            #pragma unroll
            for (int bi = 0; bi < 2; ++bi) {
                float i_ = sigm_(acc[bi][0] + b0I);
                float f_ = sigm_(acc[bi][1] + b0F);
                float g_ = tanh_(acc[bi][2] + b0G);
                float o_ = sigm_(acc[bi][3] + b0O);
                float c  = f_ * c0[bi] + i_ * g_;
                c0[bi] = c;
                g_dec_h0[(s + 1) & 1][b0 + ty * 2 + bi][j] = o_ * tanh_(c);
            }
        }
        grid_barrier();
        {
            u64 acc2[1][4] = {};
            seg16_pipe(a_s2, w_s2, &g_dec_h0[(s + 1) & 1][0][0], H_,
                       dwih1, H_, b0, j0, acc2);
            seg16_pipe(a_s2, w_s2, &g_dec_h1[s & 1][0][0], H_,
                       dwhh1, H_, b0, j0, acc2);
            float acc[2][4];
            #pragma unroll
            for (int gi = 0; gi < 4; ++gi)
                unpack2(acc2[0][gi], acc[0][gi], acc[1][gi]);
            #pragma unroll
            for (int bi = 0; bi < 2; ++bi) {
                float i_ = sigm_(acc[bi][0] + b1I);
                float f_ = sigm_(acc[bi][1] + b1F);
                float g_ = tanh_(acc[bi][2] + b1G);
                float o_ = sigm_(acc[bi][3] + b1O);
                float c  = f_ * c1[bi] + i_ * g_;
                c1[bi] = c;
                g_dec_h1[(s + 1) & 1][b0 + ty * 2 + bi][j] = o_ * tanh_(c);
            }
        }
        grid_barrier();
        {
            const float* h1 = &g_dec_h1[(s + 1) & 1][bid][0];
            float part[MQ_] = {0.f, 0.f, 0.f, 0.f, 0.f};
            for (int k = tid; k < H_; k += 256) {
                float hv = __ldcg(h1 + k);
                #pragma unroll
                for (int q = 0; q < MQ_; ++q)
                    part[q] = fmaf(hv, __ldg(wo + q * H_ + k), part[q]);
            }
            #pragma unroll
            for (int o = 16; o; o >>= 1)
                #pragma unroll
                for (int q = 0; q < MQ_; ++q)
                    part[q] += __shfl_down_sync(0xffffffffu, part[q], o);
            if ((tid & 31) == 0)
                #pragma unroll
                for (int q = 0; q < MQ_; ++q) red[tid >> 5][q] = part[q];
            __syncthreads();
            if (tid < MQ_) {
                float v = __ldg(bo + tid);
                #pragma unroll
                for (int w2 = 0; w2 < 8; ++w2) v += red[w2][tid];
                out[(long)bid * HOR_ * MQ_ + s * MQ_ + tid] = v;
                if (tid == 0) g_decx[bid][0] = v;
            }
            if (s + 1 < HOR_ && tid >= 32 && tid < 32 + DFF_)
                g_decx[bid][tid - 31] =
                    __ldg(fut + (long)bid * HOR_ * DFF_ + (s + 1) * DFF_ + (tid - 32));
        }
        grid_barrier();
    }
}

// ---------------- launcher (7 graph nodes) ----------------
extern "C" void kernel_launch(void* const* d_in, const int* in_sizes, int n_in,
                              void* d_out, int out_size)
{
    int off = (n_in >= 4 && in_sizes[3] == 1) ? 0 : -1;
    const float* X     = (const float*)d_in[0];
    const float* fut   = (const float*)d_in[1];
    const float* ewih0 = (const float*)d_in[4 + off];
    const float* ewhh0 = (const float*)d_in[5 + off];
    const float* eb0   = (const float*)d_in[6 + off];
    const float* ewih1 = (const float*)d_in[7 + off];
    const float* ewhh1 = (const float*)d_in[8 + off];
    const float* eb1   = (const float*)d_in[9 + off];
    const float* dwih0 = (const float*)d_in[10 + off];
    const float* dwhh0 = (const float*)d_in[11 + off];
    const float* db0   = (const float*)d_in[12 + off];
    const float* dwih1 = (const float*)d_in[13 + off];
    const float* dwhh1 = (const float*)d_in[14 + off];
    const float* db1   = (const float*)d_in[15 + off];
    const float* wb    = (const float*)d_in[16 + off];
    const float* bb    = (const float*)d_in[17 + off];
    const float* wo    = (const float*)d_in[18 + off];
    const float* bo    = (const float*)d_in[19 + off];
    float* out = (float*)d_out;

    cudaFuncSetAttribute(enc_mma_persist<0>,
                         cudaFuncAttributeMaxDynamicSharedMemorySize, ENC_SMEM);
    cudaFuncSetAttribute(enc_mma_persist<1>,
                         cudaFuncAttributeMaxDynamicSharedMemorySize, ENC_SMEM);

    gates0_gemm<<<dim3(T_, 2), 256>>>(X, ewih0);
    convB_kernel<<<2048, 256>>>(ewih1);
    enc_mma_persist<0><<<NBLK, 256, ENC_SMEM>>>(ewhh0, eb0);
    gates1_mma<<<dim3(16, 512, 2), 256>>>();
    enc_mma_persist<1><<<NBLK, 256, ENC_SMEM>>>(ewhh1, eb1);
    bridge_kernel<<<dim3(4, 32, 2), 256>>>(wb, bb);
    dec_persist<<<NBLK, 256>>>(X, fut, dwih0, dwhh0, db0,
                               dwih1, dwhh1, db1, wo, bo, out);
}